// round 5
// baseline (speedup 1.0000x reference)
#include <cuda_runtime.h>
#include <math.h>

#define NR     8192
#define DM     768
#define DP     512
#define NCLS   128
#define JC     256          // gPsi col-tile

// ---------------- scratch (NO huge buffers this round) ----------------
__device__ float g_Psin[NR * DP];     // 16 MB (validated path)
__device__ float g_Finv[NR];          // 1/||FF_row||
__device__ float g_Drs[NR];
__device__ float g_gPsi[NR * DP];     // 16 MB
__device__ float g_Ct[DP * NCLS];
__device__ float g_csq[NCLS];
__device__ int   g_assign[NR];
__device__ float g_R4[4][DP * DP];    // 4 MB

__device__ __forceinline__ float warpSum(float v) {
#pragma unroll
    for (int o = 16; o > 0; o >>= 1) v += __shfl_down_sync(0xffffffffu, v, o);
    return v;
}

// ---------------- row L2-normalize (warp-per-row) -> g_Psin (validated) -------
template <int D>
__global__ void norm_rows_kernel(const float* __restrict__ in,
                                 float* __restrict__ out) {
    int row  = blockIdx.x * 8 + (threadIdx.x >> 5);
    int lane = threadIdx.x & 31;
    const float* x = in + (size_t)row * D;
    float s = 0.f;
    for (int k = lane; k < D; k += 32) { float v = x[k]; s += v * v; }
    s = warpSum(s);
    s = __shfl_sync(0xffffffffu, s, 0);
    float scale = 1.f / fmaxf(sqrtf(s), 1e-12f);
    for (int k = lane; k < D; k += 32)
        out[(size_t)row * D + k] = x[k] * scale;
}

// ---------------- FF row inverse norms ----------------
__global__ void finv_kernel(const float* __restrict__ FF) {
    int row  = blockIdx.x * 8 + (threadIdx.x >> 5);
    int lane = threadIdx.x & 31;
    const float* x = FF + (size_t)row * DM;
    float s = 0.f;
    for (int k = lane; k < DM; k += 32) { float v = x[k]; s += v * v; }
    s = warpSum(s);
    if (lane == 0) g_Finv[row] = 1.f / fmaxf(sqrtf(s), 1e-12f);
}

// ---------------- centers: transpose + squared norms (validated) --------------
__global__ void prep_centers_kernel(const float* __restrict__ C) {
    int j = blockIdx.x;
    int k = threadIdx.x;
    float v = C[j * DP + k];
    g_Ct[k * NCLS + j] = v;
    float s = v * v;
    __shared__ float sh[16];
    int lane = k & 31, wid = k >> 5;
    s = warpSum(s);
    if (lane == 0) sh[wid] = s;
    __syncthreads();
    if (k == 0) {
        float t = 0.f;
        for (int w = 0; w < 16; w++) t += sh[w];
        g_csq[j] = t;
    }
}

// ---------------- logits + argmax (validated — byte identical) ----------------
__global__ void logits_kernel(const float* __restrict__ Psi,
                              float* __restrict__ out_logits) {
    __shared__ float sp[4][DP];
    __shared__ float srawsq[4];
    __shared__ float spsq[4];
    __shared__ float bv[128];
    __shared__ int   bidx[128];

    int tid  = threadIdx.x;
    int w    = tid >> 5;
    int lane = tid & 31;
    int row0 = blockIdx.x * 4;

    const float* src = Psi + (size_t)(row0 + w) * DP;
    float ss = 0.f;
    for (int k = lane; k < DP; k += 32) {
        float v = src[k];
        sp[w][k] = v;
        ss += v * v;
    }
    ss = warpSum(ss);
    if (lane == 0) srawsq[w] = ss;
    __syncthreads();
    {
        float tot = srawsq[w];
        float scl = 1.f / fmaxf(sqrtf(tot), 1e-12f);
        for (int k = lane; k < DP; k += 32) sp[w][k] *= scl;
        if (lane == 0) spsq[w] = tot * scl * scl;
    }
    __syncthreads();

    float acc0 = 0.f, acc1 = 0.f, acc2 = 0.f, acc3 = 0.f;
    for (int k = 0; k < DP; k++) {
        float c = g_Ct[k * NCLS + tid];
        acc0 = fmaf(sp[0][k], c, acc0);
        acc1 = fmaf(sp[1][k], c, acc1);
        acc2 = fmaf(sp[2][k], c, acc2);
        acc3 = fmaf(sp[3][k], c, acc3);
    }
    float accs[4] = {acc0, acc1, acc2, acc3};
    float cs = g_csq[tid];

    for (int r = 0; r < 4; r++) {
        float logit = -(spsq[r] + cs - 2.f * accs[r]);
        out_logits[(size_t)(row0 + r) * NCLS + tid] = logit;
        bv[tid] = logit;
        bidx[tid] = tid;
        __syncthreads();
        for (int off = 64; off > 0; off >>= 1) {
            if (tid < off) {
                float ov = bv[tid + off];
                int   oi = bidx[tid + off];
                if (ov > bv[tid] || (ov == bv[tid] && oi < bidx[tid])) {
                    bv[tid] = ov; bidx[tid] = oi;
                }
            }
            __syncthreads();
        }
        if (tid == 0) g_assign[row0 + r] = bidx[0];
        __syncthreads();
    }
}

// ---------------- EMA centroid update (validated — unchanged) -----------------
__global__ void cluster_update_kernel(const float* __restrict__ centers,
                                      float* __restrict__ out_centers) {
    int j = blockIdx.x;
    int tid = threadIdx.x;     // 512
    __shared__ int sa[1024];
    float acc = 0.f;
    int cnt = 0;
    for (int base = 0; base < NR; base += 1024) {
        __syncthreads();
        for (int t = tid; t < 1024; t += 512) sa[t] = g_assign[base + t];
        __syncthreads();
        for (int u = 0; u < 1024; u++) {
            if (sa[u] == j) { acc += g_Psin[(size_t)(base + u) * DP + tid]; cnt++; }
        }
    }
    float denom = fmaxf((float)cnt, 1.f);
    out_centers[j * DP + tid] = centers[j * DP + tid] * 0.9f + (acc / denom) * 0.1f;
}

// ---------------- Phase 1: D row-sums WITHOUT materializing A -----------------
// Block bi owns rows [i0, i0+64). Loops over all 128 column tiles; A-tile lives
// only in registers. Deterministic fixed-order reduction.
__global__ void __launch_bounds__(256) computeD_kernel(const float* __restrict__ FF) {
    int i0 = blockIdx.x * 64;

    __shared__ float sFi[16][68];
    __shared__ float sFj[16][68];
    __shared__ float srow[64][17];

    int tid = threadIdx.x;
    int tx = tid & 15, ty = tid >> 4;
    int ra = tid >> 2, ca = (tid & 3) * 4;

    float fia = g_Finv[i0 + ra];
    float rowacc[4] = {0.f, 0.f, 0.f, 0.f};

    for (int j0 = 0; j0 < NR; j0 += 64) {
        float fja = g_Finv[j0 + ra];
        float acc[4][4];
#pragma unroll
        for (int u = 0; u < 4; u++)
#pragma unroll
            for (int v = 0; v < 4; v++) acc[u][v] = 0.f;

        for (int k0 = 0; k0 < DM; k0 += 16) {
            float4 av = *(const float4*)(FF + (size_t)(i0 + ra) * DM + k0 + ca);
            float4 bv = *(const float4*)(FF + (size_t)(j0 + ra) * DM + k0 + ca);
            av.x *= fia; av.y *= fia; av.z *= fia; av.w *= fia;
            bv.x *= fja; bv.y *= fja; bv.z *= fja; bv.w *= fja;
            __syncthreads();
            sFi[ca + 0][ra] = av.x; sFi[ca + 1][ra] = av.y;
            sFi[ca + 2][ra] = av.z; sFi[ca + 3][ra] = av.w;
            sFj[ca + 0][ra] = bv.x; sFj[ca + 1][ra] = bv.y;
            sFj[ca + 2][ra] = bv.z; sFj[ca + 3][ra] = bv.w;
            __syncthreads();
#pragma unroll
            for (int kk = 0; kk < 16; kk++) {
                float fa[4], fb[4];
#pragma unroll
                for (int u = 0; u < 4; u++) fa[u] = sFi[kk][ty * 4 + u];
#pragma unroll
                for (int v = 0; v < 4; v++) fb[v] = sFj[kk][tx * 4 + v];
#pragma unroll
                for (int u = 0; u < 4; u++)
#pragma unroll
                    for (int v = 0; v < 4; v++) acc[u][v] = fmaf(fa[u], fb[v], acc[u][v]);
            }
        }
#pragma unroll
        for (int u = 0; u < 4; u++) {
            int gi = i0 + ty * 4 + u;
#pragma unroll
            for (int v = 0; v < 4; v++) {
                int gj = j0 + tx * 4 + v;
                float val = fmaxf(acc[u][v], 0.f);
                if (gi == gj) val = 0.f;
                rowacc[u] += val;
            }
        }
    }

#pragma unroll
    for (int u = 0; u < 4; u++) srow[ty * 4 + u][tx] = rowacc[u];
    __syncthreads();
    if (tid < 64) {
        float s = 0.f;
        for (int t = 0; t < 16; t++) s += srow[tid][t];
        float D = s / (float)(NR - 1);
        g_Drs[i0 + tid] = rsqrtf(fmaxf(D, 1e-30f));
    }
}

// ---------------- Phase 2: gPsi = Dr ∘ (A @ (Dr∘PsiL)), A recomputed ----------
// Block: rows [i0,i0+64) x cols [c0,c0+256). Per k-tile: build S(64x64) in smem,
// then multiply by W rows staged 16 at a time.
__global__ void __launch_bounds__(256) gpsi_kernel(const float* __restrict__ FF,
                                                   const float* __restrict__ Psi) {
    const float SCALE = 10.f / 8192.f;
    int i0 = blockIdx.x * 64;
    int c0 = blockIdx.y * JC;

    __shared__ float sS[64][68];
    __shared__ float sFi[16][68];
    __shared__ float sFj[16][68];
    __shared__ float sW[16][JC + 4];

    int tid = threadIdx.x;
    int tx = tid & 15, ty = tid >> 4;
    int ra = tid >> 2, ca = (tid & 3) * 4;

    float fia = g_Finv[i0 + ra];

    float acc[4][16];
#pragma unroll
    for (int u = 0; u < 4; u++)
#pragma unroll
        for (int v = 0; v < 16; v++) acc[u][v] = 0.f;

    for (int kt = 0; kt < NR; kt += 64) {
        // ---- build S = clamp(Fn_i . Fn_k^T, 0), diag zeroed ----
        float fja = g_Finv[kt + ra];
        float s2[4][4];
#pragma unroll
        for (int u = 0; u < 4; u++)
#pragma unroll
            for (int v = 0; v < 4; v++) s2[u][v] = 0.f;

        for (int k0 = 0; k0 < DM; k0 += 16) {
            float4 av = *(const float4*)(FF + (size_t)(i0 + ra) * DM + k0 + ca);
            float4 bv = *(const float4*)(FF + (size_t)(kt + ra) * DM + k0 + ca);
            av.x *= fia; av.y *= fia; av.z *= fia; av.w *= fia;
            bv.x *= fja; bv.y *= fja; bv.z *= fja; bv.w *= fja;
            __syncthreads();
            sFi[ca + 0][ra] = av.x; sFi[ca + 1][ra] = av.y;
            sFi[ca + 2][ra] = av.z; sFi[ca + 3][ra] = av.w;
            sFj[ca + 0][ra] = bv.x; sFj[ca + 1][ra] = bv.y;
            sFj[ca + 2][ra] = bv.z; sFj[ca + 3][ra] = bv.w;
            __syncthreads();
#pragma unroll
            for (int kk = 0; kk < 16; kk++) {
                float fa[4], fb[4];
#pragma unroll
                for (int u = 0; u < 4; u++) fa[u] = sFi[kk][ty * 4 + u];
#pragma unroll
                for (int v = 0; v < 4; v++) fb[v] = sFj[kk][tx * 4 + v];
#pragma unroll
                for (int u = 0; u < 4; u++)
#pragma unroll
                    for (int v = 0; v < 4; v++) s2[u][v] = fmaf(fa[u], fb[v], s2[u][v]);
            }
        }
        __syncthreads();     // previous sW/sS consumers done (also covered above)
#pragma unroll
        for (int u = 0; u < 4; u++) {
            int gi = i0 + ty * 4 + u;
#pragma unroll
            for (int v = 0; v < 4; v++) {
                int gk = kt + tx * 4 + v;
                float val = fmaxf(s2[u][v], 0.f);
                if (gi == gk) val = 0.f;
                sS[ty * 4 + u][tx * 4 + v] = val;
            }
        }
        __syncthreads();

        // ---- multiply: acc += S @ W,  W[k][c] = Psi[k][c]*Drs[k]*SCALE ----
        int wr = tid >> 4;            // 0..15
        int wc = (tid & 15) * 16;     // 0..240
        for (int cch = 0; cch < 4; cch++) {
            int kb = kt + cch * 16;
            float wsc = g_Drs[kb + wr] * SCALE;
            float4 w0 = *(const float4*)(Psi + (size_t)(kb + wr) * DP + c0 + wc);
            float4 w1 = *(const float4*)(Psi + (size_t)(kb + wr) * DP + c0 + wc + 4);
            float4 w2 = *(const float4*)(Psi + (size_t)(kb + wr) * DP + c0 + wc + 8);
            float4 w3 = *(const float4*)(Psi + (size_t)(kb + wr) * DP + c0 + wc + 12);
            __syncthreads();
            w0.x *= wsc; w0.y *= wsc; w0.z *= wsc; w0.w *= wsc;
            w1.x *= wsc; w1.y *= wsc; w1.z *= wsc; w1.w *= wsc;
            w2.x *= wsc; w2.y *= wsc; w2.z *= wsc; w2.w *= wsc;
            w3.x *= wsc; w3.y *= wsc; w3.z *= wsc; w3.w *= wsc;
            *(float4*)&sW[wr][wc + 0]  = w0;
            *(float4*)&sW[wr][wc + 4]  = w1;
            *(float4*)&sW[wr][wc + 8]  = w2;
            *(float4*)&sW[wr][wc + 12] = w3;
            __syncthreads();
#pragma unroll
            for (int jj = 0; jj < 16; jj++) {
                float fs[4];
#pragma unroll
                for (int u = 0; u < 4; u++) fs[u] = sS[ty * 4 + u][cch * 16 + jj];
#pragma unroll
                for (int v = 0; v < 16; v++) {
                    float fw = sW[jj][tx * 16 + v];
#pragma unroll
                    for (int u = 0; u < 4; u++) acc[u][v] = fmaf(fs[u], fw, acc[u][v]);
                }
            }
        }
        __syncthreads();   // done with sS before next kt overwrites
    }

#pragma unroll
    for (int u = 0; u < 4; u++) {
        int gi = i0 + ty * 4 + u;
        float di = g_Drs[gi];
#pragma unroll
        for (int q = 0; q < 4; q++) {
            float4 ov = make_float4(di * acc[u][q * 4 + 0], di * acc[u][q * 4 + 1],
                                    di * acc[u][q * 4 + 2], di * acc[u][q * 4 + 3]);
            *(float4*)(g_gPsi + (size_t)gi * DP + c0 + tx * 16 + q * 4) = ov;
        }
    }
}

// ---------------- R partials (4-way split-K) ----------------
__global__ void __launch_bounds__(256) gemm3_kernel(const float* __restrict__ Psi) {
    const float SCALE = 10.f / 8192.f;
    int b0 = blockIdx.x * 64;
    int a0 = blockIdx.y * 64;
    int z  = blockIdx.z;

    __shared__ float Xs[16][68];
    __shared__ float Ys[16][68];

    int tid = threadIdx.x;
    int tx = tid & 15, ty = tid >> 4;
    int r = tid >> 4, c = (tid & 15) * 4;

    float acc[4][4];
#pragma unroll
    for (int u = 0; u < 4; u++)
#pragma unroll
        for (int v = 0; v < 4; v++) acc[u][v] = 0.f;

    int kbeg = z * (NR / 4);
    for (int k0 = kbeg; k0 < kbeg + NR / 4; k0 += 16) {
        float4 xv = *(const float4*)(Psi + (size_t)(k0 + r) * DP + a0 + c);
        float4 yv = *(const float4*)(g_gPsi + (size_t)(k0 + r) * DP + b0 + c);
        xv.x *= SCALE; xv.y *= SCALE; xv.z *= SCALE; xv.w *= SCALE;
        __syncthreads();
        *(float4*)&Xs[r][c] = xv;
        *(float4*)&Ys[r][c] = yv;
        __syncthreads();
#pragma unroll
        for (int kk = 0; kk < 16; kk++) {
            float fx[4], fy[4];
#pragma unroll
            for (int u = 0; u < 4; u++) fx[u] = Xs[kk][ty * 4 + u];
#pragma unroll
            for (int v = 0; v < 4; v++) fy[v] = Ys[kk][tx * 4 + v];
#pragma unroll
            for (int u = 0; u < 4; u++)
#pragma unroll
                for (int v = 0; v < 4; v++) acc[u][v] = fmaf(fx[u], fy[v], acc[u][v]);
        }
    }
#pragma unroll
    for (int u = 0; u < 4; u++)
        *(float4*)(&g_R4[z][(a0 + ty * 4 + u) * DP + b0 + tx * 4]) =
            make_float4(acc[u][0], acc[u][1], acc[u][2], acc[u][3]);
}

// ---------------- final: trace + triu reg ----------------
__global__ void final_kernel(float* __restrict__ out2) {
    int b = threadIdx.x;   // 512
    float tr = 0.f, rg = 0.f;
    for (int a = 0; a < DP; a++) {
        float s = g_R4[0][a * DP + b] + g_R4[1][a * DP + b]
                + g_R4[2][a * DP + b] + g_R4[3][a * DP + b];
        if (b == a) tr += s;
        else if (b > a) rg += s * s;
    }
    __shared__ float st[DP], sr[DP];
    st[b] = tr; sr[b] = rg;
    __syncthreads();
    if (b == 0) {
        double T = 0.0, R = 0.0;
        for (int i = 0; i < DP; i++) { T += (double)st[i]; R += (double)sr[i]; }
        out2[0] = (float)(-T);
        out2[1] = (float)(R * 0.02);
    }
}

// ---------------- launcher ----------------
extern "C" void kernel_launch(void* const* d_in, const int* in_sizes, int n_in,
                              void* d_out, int out_size) {
    const float* FF  = (const float*)d_in[0];
    const float* Psi = (const float*)d_in[1];
    const float* C   = (const float*)d_in[2];
    float* out = (float*)d_out;

    float* out_logits  = out;
    float* out_centers = out + (size_t)NR * NCLS;
    float* out_scal    = out + (size_t)NR * NCLS + NCLS * DP;

    // clustering branch (validated)
    norm_rows_kernel<DP><<<NR / 8, 256>>>(Psi, g_Psin);
    prep_centers_kernel<<<NCLS, DP>>>(C);
    logits_kernel<<<NR / 4, 128>>>(Psi, out_logits);
    cluster_update_kernel<<<NCLS, DP>>>(C, out_centers);

    // neuralef branch — NO materialized A
    finv_kernel<<<NR / 8, 256>>>(FF);
    computeD_kernel<<<NR / 64, 256>>>(FF);
    gpsi_kernel<<<dim3(NR / 64, DP / JC), 256>>>(FF, Psi);
    gemm3_kernel<<<dim3(DP / 64, DP / 64, 4), 256>>>(Psi);
    final_kernel<<<1, DP>>>(out_scal);
}

// round 6
// speedup vs baseline: 2.4551x; 2.4551x over previous
#include <cuda_runtime.h>
#include <math.h>
#include <stdint.h>

#define NR     8192
#define DM     768
#define DP     512
#define NCLS   128
#define SCALE  (10.f / 8192.f)

// ---------------- scratch (all buffers modest; 256MB globals are poison) -------
__device__ float g_Psin[NR * DP];          // 16 MB
__device__ float g_Finv[NR];
__device__ float g_Drs[NR];
__device__ float g_gPsi[NR * DP];          // 16 MB
__device__ float g_Ct[DP * NCLS];
__device__ float g_csq[NCLS];
__device__ int   g_assign[NR];
__device__ float g_R4[4][DP * DP];         // 4 MB
__device__ float g_cpart[16][NCLS][DP];    // 16 MB
__device__ int   g_ccnt[16][NCLS];

__device__ __forceinline__ float warpSum(float v) {
#pragma unroll
    for (int o = 16; o > 0; o >>= 1) v += __shfl_down_sync(0xffffffffu, v, o);
    return v;
}

__device__ __forceinline__ uint32_t f2tf32(float x) {
    uint32_t y;
    asm("cvt.rna.tf32.f32 %0, %1;" : "=r"(y) : "f"(x));
    return y;
}

__device__ __forceinline__ void mma8(float* c,
                                     uint32_t a0, uint32_t a1, uint32_t a2, uint32_t a3,
                                     uint32_t b0, uint32_t b1) {
    asm volatile(
        "mma.sync.aligned.m16n8k8.row.col.f32.tf32.tf32.f32 "
        "{%0,%1,%2,%3}, {%4,%5,%6,%7}, {%8,%9}, {%0,%1,%2,%3};\n"
        : "+f"(c[0]), "+f"(c[1]), "+f"(c[2]), "+f"(c[3])
        : "r"(a0), "r"(a1), "r"(a2), "r"(a3), "r"(b0), "r"(b1));
}

// ---------------- row L2-normalize (warp-per-row) ----------------
template <int D>
__global__ void norm_rows_kernel(const float* __restrict__ in,
                                 float* __restrict__ out) {
    int row  = blockIdx.x * 8 + (threadIdx.x >> 5);
    int lane = threadIdx.x & 31;
    const float* x = in + (size_t)row * D;
    float s = 0.f;
    for (int k = lane; k < D; k += 32) { float v = x[k]; s += v * v; }
    s = warpSum(s);
    s = __shfl_sync(0xffffffffu, s, 0);
    float scale = 1.f / fmaxf(sqrtf(s), 1e-12f);
    for (int k = lane; k < D; k += 32)
        out[(size_t)row * D + k] = x[k] * scale;
}

// ---------------- FF row inverse norms ----------------
__global__ void finv_kernel(const float* __restrict__ FF) {
    int row  = blockIdx.x * 8 + (threadIdx.x >> 5);
    int lane = threadIdx.x & 31;
    const float* x = FF + (size_t)row * DM;
    float s = 0.f;
    for (int k = lane; k < DM; k += 32) { float v = x[k]; s += v * v; }
    s = warpSum(s);
    if (lane == 0) g_Finv[row] = 1.f / fmaxf(sqrtf(s), 1e-12f);
}

// ---------------- centers: transpose + squared norms (validated) --------------
__global__ void prep_centers_kernel(const float* __restrict__ C) {
    int j = blockIdx.x;
    int k = threadIdx.x;
    float v = C[j * DP + k];
    g_Ct[k * NCLS + j] = v;
    float s = v * v;
    __shared__ float sh[16];
    int lane = k & 31, wid = k >> 5;
    s = warpSum(s);
    if (lane == 0) sh[wid] = s;
    __syncthreads();
    if (k == 0) {
        float t = 0.f;
        for (int w = 0; w < 16; w++) t += sh[w];
        g_csq[j] = t;
    }
}

// ---------------- logits + argmax (validated — byte identical) ----------------
__global__ void logits_kernel(const float* __restrict__ Psi,
                              float* __restrict__ out_logits) {
    __shared__ float sp[4][DP];
    __shared__ float srawsq[4];
    __shared__ float spsq[4];
    __shared__ float bv[128];
    __shared__ int   bidx[128];

    int tid  = threadIdx.x;
    int w    = tid >> 5;
    int lane = tid & 31;
    int row0 = blockIdx.x * 4;

    const float* src = Psi + (size_t)(row0 + w) * DP;
    float ss = 0.f;
    for (int k = lane; k < DP; k += 32) {
        float v = src[k];
        sp[w][k] = v;
        ss += v * v;
    }
    ss = warpSum(ss);
    if (lane == 0) srawsq[w] = ss;
    __syncthreads();
    {
        float tot = srawsq[w];
        float scl = 1.f / fmaxf(sqrtf(tot), 1e-12f);
        for (int k = lane; k < DP; k += 32) sp[w][k] *= scl;
        if (lane == 0) spsq[w] = tot * scl * scl;
    }
    __syncthreads();

    float acc0 = 0.f, acc1 = 0.f, acc2 = 0.f, acc3 = 0.f;
    for (int k = 0; k < DP; k++) {
        float c = g_Ct[k * NCLS + tid];
        acc0 = fmaf(sp[0][k], c, acc0);
        acc1 = fmaf(sp[1][k], c, acc1);
        acc2 = fmaf(sp[2][k], c, acc2);
        acc3 = fmaf(sp[3][k], c, acc3);
    }
    float accs[4] = {acc0, acc1, acc2, acc3};
    float cs = g_csq[tid];

    for (int r = 0; r < 4; r++) {
        float logit = -(spsq[r] + cs - 2.f * accs[r]);
        out_logits[(size_t)(row0 + r) * NCLS + tid] = logit;
        bv[tid] = logit;
        bidx[tid] = tid;
        __syncthreads();
        for (int off = 64; off > 0; off >>= 1) {
            if (tid < off) {
                float ov = bv[tid + off];
                int   oi = bidx[tid + off];
                if (ov > bv[tid] || (ov == bv[tid] && oi < bidx[tid])) {
                    bv[tid] = ov; bidx[tid] = oi;
                }
            }
            __syncthreads();
        }
        if (tid == 0) g_assign[row0 + r] = bidx[0];
        __syncthreads();
    }
}

// ---------------- cluster update: 16-way chunked partials (deterministic) -----
__global__ void clusterA_kernel() {
    int z = blockIdx.x;      // 16 chunks
    int j = blockIdx.y;      // 128 clusters
    int tid = threadIdx.x;   // 512
    __shared__ int sa[512];
    sa[tid] = g_assign[z * 512 + tid];
    __syncthreads();
    float acc = 0.f;
    int cnt = 0;
    for (int u = 0; u < 512; u++) {
        if (sa[u] == j) { acc += g_Psin[(size_t)(z * 512 + u) * DP + tid]; cnt++; }
    }
    g_cpart[z][j][tid] = acc;
    if (tid == 0) g_ccnt[z][j] = cnt;
}

__global__ void clusterB_kernel(const float* __restrict__ centers,
                                float* __restrict__ out_centers) {
    int j = blockIdx.x;
    int tid = threadIdx.x;   // 512
    float acc = 0.f;
    int cnt = 0;
    for (int z = 0; z < 16; z++) { acc += g_cpart[z][j][tid]; cnt += g_ccnt[z][j]; }
    float denom = fmaxf((float)cnt, 1.f);
    out_centers[j * DP + tid] = centers[j * DP + tid] * 0.9f + (acc / denom) * 0.1f;
}

// ---------------- computeD: tf32 mma S-tiles (64x64), rowsum -> Drs -----------
__global__ void __launch_bounds__(256) computeD_tc(const float* __restrict__ FF) {
    __shared__ uint32_t sFi[64][36];
    __shared__ uint32_t sFj[64][36];
    __shared__ float srow[64][2];

    int tid = threadIdx.x, wid = tid >> 5, lane = tid & 31;
    int g = lane >> 2, t = lane & 3;
    int wm = wid & 3, wn = wid >> 2;
    int i0 = blockIdx.x * 64;

    int lr = tid >> 2, lc8 = (tid & 3) * 8;
    float fia = g_Finv[i0 + lr];

    float r0 = 0.f, r1 = 0.f;

    for (int j0 = 0; j0 < NR; j0 += 64) {
        float fja = g_Finv[j0 + lr];
        float sc[4][4];
#pragma unroll
        for (int n8 = 0; n8 < 4; n8++)
#pragma unroll
            for (int q = 0; q < 4; q++) sc[n8][q] = 0.f;

        for (int kc = 0; kc < DM; kc += 32) {
            __syncthreads();
            const float* pi = FF + (size_t)(i0 + lr) * DM + kc + lc8;
            const float* pj = FF + (size_t)(j0 + lr) * DM + kc + lc8;
            float4 x0 = *(const float4*)(pi);
            float4 x1 = *(const float4*)(pi + 4);
            float4 y0 = *(const float4*)(pj);
            float4 y1 = *(const float4*)(pj + 4);
            sFi[lr][lc8 + 0] = f2tf32(x0.x * fia); sFi[lr][lc8 + 1] = f2tf32(x0.y * fia);
            sFi[lr][lc8 + 2] = f2tf32(x0.z * fia); sFi[lr][lc8 + 3] = f2tf32(x0.w * fia);
            sFi[lr][lc8 + 4] = f2tf32(x1.x * fia); sFi[lr][lc8 + 5] = f2tf32(x1.y * fia);
            sFi[lr][lc8 + 6] = f2tf32(x1.z * fia); sFi[lr][lc8 + 7] = f2tf32(x1.w * fia);
            sFj[lr][lc8 + 0] = f2tf32(y0.x * fja); sFj[lr][lc8 + 1] = f2tf32(y0.y * fja);
            sFj[lr][lc8 + 2] = f2tf32(y0.z * fja); sFj[lr][lc8 + 3] = f2tf32(y0.w * fja);
            sFj[lr][lc8 + 4] = f2tf32(y1.x * fja); sFj[lr][lc8 + 5] = f2tf32(y1.y * fja);
            sFj[lr][lc8 + 6] = f2tf32(y1.z * fja); sFj[lr][lc8 + 7] = f2tf32(y1.w * fja);
            __syncthreads();
#pragma unroll
            for (int kk = 0; kk < 4; kk++) {
                uint32_t a0 = sFi[wm * 16 + g][kk * 8 + t];
                uint32_t a1 = sFi[wm * 16 + g + 8][kk * 8 + t];
                uint32_t a2 = sFi[wm * 16 + g][kk * 8 + t + 4];
                uint32_t a3 = sFi[wm * 16 + g + 8][kk * 8 + t + 4];
#pragma unroll
                for (int n8 = 0; n8 < 4; n8++) {
                    uint32_t b0 = sFj[wn * 32 + n8 * 8 + g][kk * 8 + t];
                    uint32_t b1 = sFj[wn * 32 + n8 * 8 + g][kk * 8 + t + 4];
                    mma8(sc[n8], a0, a1, a2, a3, b0, b1);
                }
            }
        }
        // clamp + diag, accumulate row sums
#pragma unroll
        for (int n8 = 0; n8 < 4; n8++) {
            int colb = j0 + wn * 32 + n8 * 8 + 2 * t;
            int rg0 = i0 + wm * 16 + g;
            float v0 = fmaxf(sc[n8][0], 0.f); if (rg0 == colb)      v0 = 0.f;
            float v1 = fmaxf(sc[n8][1], 0.f); if (rg0 == colb + 1)  v1 = 0.f;
            float v2 = fmaxf(sc[n8][2], 0.f); if (rg0 + 8 == colb)     v2 = 0.f;
            float v3 = fmaxf(sc[n8][3], 0.f); if (rg0 + 8 == colb + 1) v3 = 0.f;
            r0 += v0 + v1;
            r1 += v2 + v3;
        }
    }
    r0 += __shfl_xor_sync(0xffffffffu, r0, 1);
    r0 += __shfl_xor_sync(0xffffffffu, r0, 2);
    r1 += __shfl_xor_sync(0xffffffffu, r1, 1);
    r1 += __shfl_xor_sync(0xffffffffu, r1, 2);
    if (t == 0) {
        srow[wm * 16 + g][wn]     = r0;
        srow[wm * 16 + g + 8][wn] = r1;
    }
    __syncthreads();
    if (tid < 64) {
        float D = (srow[tid][0] + srow[tid][1]) / (float)(NR - 1);
        g_Drs[i0 + tid] = rsqrtf(fmaxf(D, 1e-30f));
    }
}

// ---------------- gPsi: per 64-row x 256-col block; S recomputed via mma ------
__global__ void __launch_bounds__(256) gpsi_tc(const float* __restrict__ FF,
                                               const float* __restrict__ Psi) {
    __shared__ uint32_t sS[64][68];
    __shared__ uint32_t sBuf[64 * 36 * 2];
    uint32_t (*sFi)[36] = (uint32_t(*)[36])sBuf;
    uint32_t (*sFj)[36] = (uint32_t(*)[36])(sBuf + 64 * 36);
    uint32_t (*sW)[68]  = (uint32_t(*)[68])sBuf;

    int tid = threadIdx.x, wid = tid >> 5, lane = tid & 31;
    int g = lane >> 2, t = lane & 3;
    int wm = wid & 3, wn = wid >> 2;
    int i0 = blockIdx.x * 64, c0 = blockIdx.y * 256;

    int lr = tid >> 2, lc8 = (tid & 3) * 8, lc16 = (tid & 3) * 16;
    float fia = g_Finv[i0 + lr];

    float gacc[16][4];
#pragma unroll
    for (int f = 0; f < 16; f++)
#pragma unroll
        for (int q = 0; q < 4; q++) gacc[f][q] = 0.f;

    for (int kt = 0; kt < NR; kt += 64) {
        float fja = g_Finv[kt + lr];
        float sc[4][4];
#pragma unroll
        for (int n8 = 0; n8 < 4; n8++)
#pragma unroll
            for (int q = 0; q < 4; q++) sc[n8][q] = 0.f;

        // ---- S-build: S = clamp(Fn_i . Fn_kt^T, 0), diag zeroed ----
        for (int kc = 0; kc < DM; kc += 32) {
            __syncthreads();
            const float* pi = FF + (size_t)(i0 + lr) * DM + kc + lc8;
            const float* pj = FF + (size_t)(kt + lr) * DM + kc + lc8;
            float4 x0 = *(const float4*)(pi);
            float4 x1 = *(const float4*)(pi + 4);
            float4 y0 = *(const float4*)(pj);
            float4 y1 = *(const float4*)(pj + 4);
            sFi[lr][lc8 + 0] = f2tf32(x0.x * fia); sFi[lr][lc8 + 1] = f2tf32(x0.y * fia);
            sFi[lr][lc8 + 2] = f2tf32(x0.z * fia); sFi[lr][lc8 + 3] = f2tf32(x0.w * fia);
            sFi[lr][lc8 + 4] = f2tf32(x1.x * fia); sFi[lr][lc8 + 5] = f2tf32(x1.y * fia);
            sFi[lr][lc8 + 6] = f2tf32(x1.z * fia); sFi[lr][lc8 + 7] = f2tf32(x1.w * fia);
            sFj[lr][lc8 + 0] = f2tf32(y0.x * fja); sFj[lr][lc8 + 1] = f2tf32(y0.y * fja);
            sFj[lr][lc8 + 2] = f2tf32(y0.z * fja); sFj[lr][lc8 + 3] = f2tf32(y0.w * fja);
            sFj[lr][lc8 + 4] = f2tf32(y1.x * fja); sFj[lr][lc8 + 5] = f2tf32(y1.y * fja);
            sFj[lr][lc8 + 6] = f2tf32(y1.z * fja); sFj[lr][lc8 + 7] = f2tf32(y1.w * fja);
            __syncthreads();
#pragma unroll
            for (int kk = 0; kk < 4; kk++) {
                uint32_t a0 = sFi[wm * 16 + g][kk * 8 + t];
                uint32_t a1 = sFi[wm * 16 + g + 8][kk * 8 + t];
                uint32_t a2 = sFi[wm * 16 + g][kk * 8 + t + 4];
                uint32_t a3 = sFi[wm * 16 + g + 8][kk * 8 + t + 4];
#pragma unroll
                for (int n8 = 0; n8 < 4; n8++) {
                    uint32_t b0 = sFj[wn * 32 + n8 * 8 + g][kk * 8 + t];
                    uint32_t b1 = sFj[wn * 32 + n8 * 8 + g][kk * 8 + t + 4];
                    mma8(sc[n8], a0, a1, a2, a3, b0, b1);
                }
            }
        }
        __syncthreads();   // all S-build smem reads done before sW overwrites sFi/sFj
        // clamp + diag -> sS (tf32)
#pragma unroll
        for (int n8 = 0; n8 < 4; n8++) {
            int row_l0 = wm * 16 + g;
            int col_l  = wn * 32 + n8 * 8 + 2 * t;
            float v0 = fmaxf(sc[n8][0], 0.f); if (i0 + row_l0 == kt + col_l)     v0 = 0.f;
            float v1 = fmaxf(sc[n8][1], 0.f); if (i0 + row_l0 == kt + col_l + 1) v1 = 0.f;
            float v2 = fmaxf(sc[n8][2], 0.f); if (i0 + row_l0 + 8 == kt + col_l)     v2 = 0.f;
            float v3 = fmaxf(sc[n8][3], 0.f); if (i0 + row_l0 + 8 == kt + col_l + 1) v3 = 0.f;
            sS[row_l0][col_l]         = f2tf32(v0);
            sS[row_l0][col_l + 1]     = f2tf32(v1);
            sS[row_l0 + 8][col_l]     = f2tf32(v2);
            sS[row_l0 + 8][col_l + 1] = f2tf32(v3);
        }
        __syncthreads();

        // ---- multiply: gacc += S @ W (W = Drs_k*SCALE*Psi) ----
        float wsc = g_Drs[kt + lr] * SCALE;
#pragma unroll
        for (int ch = 0; ch < 4; ch++) {
            const float* pw = Psi + (size_t)(kt + lr) * DP + c0 + ch * 64 + lc16;
#pragma unroll
            for (int q4 = 0; q4 < 4; q4++) {
                float4 w = *(const float4*)(pw + q4 * 4);
                sW[lr][lc16 + q4 * 4 + 0] = f2tf32(w.x * wsc);
                sW[lr][lc16 + q4 * 4 + 1] = f2tf32(w.y * wsc);
                sW[lr][lc16 + q4 * 4 + 2] = f2tf32(w.z * wsc);
                sW[lr][lc16 + q4 * 4 + 3] = f2tf32(w.w * wsc);
            }
            __syncthreads();
#pragma unroll
            for (int kk = 0; kk < 8; kk++) {
                uint32_t a0 = sS[wm * 16 + g][kk * 8 + t];
                uint32_t a1 = sS[wm * 16 + g + 8][kk * 8 + t];
                uint32_t a2 = sS[wm * 16 + g][kk * 8 + t + 4];
                uint32_t a3 = sS[wm * 16 + g + 8][kk * 8 + t + 4];
#pragma unroll
                for (int n8 = 0; n8 < 4; n8++) {
                    uint32_t b0 = sW[kk * 8 + t][wn * 32 + n8 * 8 + g];
                    uint32_t b1 = sW[kk * 8 + t + 4][wn * 32 + n8 * 8 + g];
                    mma8(gacc[ch * 4 + n8], a0, a1, a2, a3, b0, b1);
                }
            }
            __syncthreads();
        }
    }

    // epilogue: scale by Drs_i, write gPsi
    int row = i0 + wm * 16 + g;
    float d0 = g_Drs[row], d1 = g_Drs[row + 8];
#pragma unroll
    for (int ch = 0; ch < 4; ch++) {
#pragma unroll
        for (int n8 = 0; n8 < 4; n8++) {
            int col = c0 + ch * 64 + wn * 32 + n8 * 8 + 2 * t;
            float* p0 = g_gPsi + (size_t)row * DP + col;
            float* p1 = g_gPsi + (size_t)(row + 8) * DP + col;
            p0[0] = d0 * gacc[ch * 4 + n8][0];
            p0[1] = d0 * gacc[ch * 4 + n8][1];
            p1[0] = d1 * gacc[ch * 4 + n8][2];
            p1[1] = d1 * gacc[ch * 4 + n8][3];
        }
    }
}

// ---------------- gemm3: R partials = PsiL^T @ gPsi, 4-way split-K, tf32 ------
__global__ void __launch_bounds__(256) gemm3_tc(const float* __restrict__ Psi) {
    __shared__ uint32_t Xs[64][33];
    __shared__ uint32_t Ys[32][68];

    int tid = threadIdx.x, wid = tid >> 5, lane = tid & 31;
    int g = lane >> 2, t = lane & 3;
    int wm = wid & 3, wn = wid >> 2;
    int b0 = blockIdx.x * 64, a0 = blockIdx.y * 64, z = blockIdx.z;

    int lk = tid >> 3, la8 = (tid & 7) * 8;

    float sc[4][4];
#pragma unroll
    for (int n8 = 0; n8 < 4; n8++)
#pragma unroll
        for (int q = 0; q < 4; q++) sc[n8][q] = 0.f;

    int kbeg = z * (NR / 4);
    for (int k0 = kbeg; k0 < kbeg + NR / 4; k0 += 32) {
        __syncthreads();
        const float* px = Psi + (size_t)(k0 + lk) * DP + a0 + la8;
        const float* py = g_gPsi + (size_t)(k0 + lk) * DP + b0 + la8;
        float4 x0 = *(const float4*)(px);
        float4 x1 = *(const float4*)(px + 4);
        float4 y0 = *(const float4*)(py);
        float4 y1 = *(const float4*)(py + 4);
        Xs[la8 + 0][lk] = f2tf32(x0.x * SCALE); Xs[la8 + 1][lk] = f2tf32(x0.y * SCALE);
        Xs[la8 + 2][lk] = f2tf32(x0.z * SCALE); Xs[la8 + 3][lk] = f2tf32(x0.w * SCALE);
        Xs[la8 + 4][lk] = f2tf32(x1.x * SCALE); Xs[la8 + 5][lk] = f2tf32(x1.y * SCALE);
        Xs[la8 + 6][lk] = f2tf32(x1.z * SCALE); Xs[la8 + 7][lk] = f2tf32(x1.w * SCALE);
        Ys[lk][la8 + 0] = f2tf32(y0.x); Ys[lk][la8 + 1] = f2tf32(y0.y);
        Ys[lk][la8 + 2] = f2tf32(y0.z); Ys[lk][la8 + 3] = f2tf32(y0.w);
        Ys[lk][la8 + 4] = f2tf32(y1.x); Ys[lk][la8 + 5] = f2tf32(y1.y);
        Ys[lk][la8 + 6] = f2tf32(y1.z); Ys[lk][la8 + 7] = f2tf32(y1.w);
        __syncthreads();
#pragma unroll
        for (int kk = 0; kk < 4; kk++) {
            uint32_t fa0 = Xs[wm * 16 + g][kk * 8 + t];
            uint32_t fa1 = Xs[wm * 16 + g + 8][kk * 8 + t];
            uint32_t fa2 = Xs[wm * 16 + g][kk * 8 + t + 4];
            uint32_t fa3 = Xs[wm * 16 + g + 8][kk * 8 + t + 4];
#pragma unroll
            for (int n8 = 0; n8 < 4; n8++) {
                uint32_t fb0 = Ys[kk * 8 + t][wn * 32 + n8 * 8 + g];
                uint32_t fb1 = Ys[kk * 8 + t + 4][wn * 32 + n8 * 8 + g];
                mma8(sc[n8], fa0, fa1, fa2, fa3, fb0, fb1);
            }
        }
    }
    int a = a0 + wm * 16 + g;
#pragma unroll
    for (int n8 = 0; n8 < 4; n8++) {
        int b = b0 + wn * 32 + n8 * 8 + 2 * t;
        g_R4[z][a * DP + b]           = sc[n8][0];
        g_R4[z][a * DP + b + 1]       = sc[n8][1];
        g_R4[z][(a + 8) * DP + b]     = sc[n8][2];
        g_R4[z][(a + 8) * DP + b + 1] = sc[n8][3];
    }
}

// ---------------- final: trace + triu reg ----------------
__global__ void final_kernel(float* __restrict__ out2) {
    int b = threadIdx.x;   // 512
    float tr = 0.f, rg = 0.f;
    for (int a = 0; a < DP; a++) {
        float s = g_R4[0][a * DP + b] + g_R4[1][a * DP + b]
                + g_R4[2][a * DP + b] + g_R4[3][a * DP + b];
        if (b == a) tr += s;
        else if (b > a) rg += s * s;
    }
    __shared__ float st[DP], sr[DP];
    st[b] = tr; sr[b] = rg;
    __syncthreads();
    if (b == 0) {
        double T = 0.0, R = 0.0;
        for (int i = 0; i < DP; i++) { T += (double)st[i]; R += (double)sr[i]; }
        out2[0] = (float)(-T);
        out2[1] = (float)(R * 0.02);
    }
}

// ---------------- launcher ----------------
extern "C" void kernel_launch(void* const* d_in, const int* in_sizes, int n_in,
                              void* d_out, int out_size) {
    const float* FF  = (const float*)d_in[0];
    const float* Psi = (const float*)d_in[1];
    const float* C   = (const float*)d_in[2];
    float* out = (float*)d_out;

    float* out_logits  = out;
    float* out_centers = out + (size_t)NR * NCLS;
    float* out_scal    = out + (size_t)NR * NCLS + NCLS * DP;

    // clustering branch
    norm_rows_kernel<DP><<<NR / 8, 256>>>(Psi, g_Psin);
    prep_centers_kernel<<<NCLS, DP>>>(C);
    logits_kernel<<<NR / 4, 128>>>(Psi, out_logits);
    clusterA_kernel<<<dim3(16, NCLS), 512>>>();
    clusterB_kernel<<<NCLS, DP>>>(C, out_centers);

    // neuralef branch — tensor-core tf32
    finv_kernel<<<NR / 8, 256>>>(FF);
    computeD_tc<<<NR / 64, 256>>>(FF);
    gpsi_tc<<<dim3(NR / 64, DP / 256), 256>>>(FF, Psi);
    gemm3_tc<<<dim3(DP / 64, DP / 64, 4), 256>>>(Psi);
    final_kernel<<<1, DP>>>(out_scal);
}

// round 7
// speedup vs baseline: 3.4878x; 1.4206x over previous
#include <cuda_runtime.h>
#include <math.h>
#include <stdint.h>

#define NR     8192
#define DM     768
#define DP     512
#define NCLS   128
#define SCALE  (10.f / 8192.f)
#define JW     128

// ---------------- scratch ----------------
__device__ float g_Psin[NR * DP];
__device__ float g_Finv[NR];
__device__ float g_Drs[NR];
__device__ float g_gPsi[NR * DP];
__device__ float g_Ct[DP * NCLS];
__device__ float g_csq[NCLS];
__device__ int   g_assign[NR];
__device__ float g_R4[4][DP * DP];
__device__ float g_cpart[16][NCLS][DP];
__device__ int   g_ccnt[16][NCLS];

__device__ __forceinline__ float warpSum(float v) {
#pragma unroll
    for (int o = 16; o > 0; o >>= 1) v += __shfl_down_sync(0xffffffffu, v, o);
    return v;
}

__device__ __forceinline__ uint32_t f2tf32(float x) {
    uint32_t y;
    asm("cvt.rna.tf32.f32 %0, %1;" : "=r"(y) : "f"(x));
    return y;
}
__device__ __forceinline__ uint4 cvt4(float4 v, float s) {
    uint4 u;
    u.x = f2tf32(v.x * s); u.y = f2tf32(v.y * s);
    u.z = f2tf32(v.z * s); u.w = f2tf32(v.w * s);
    return u;
}

__device__ __forceinline__ void mma8(float* c,
                                     uint32_t a0, uint32_t a1, uint32_t a2, uint32_t a3,
                                     uint32_t b0, uint32_t b1) {
    asm volatile(
        "mma.sync.aligned.m16n8k8.row.col.f32.tf32.tf32.f32 "
        "{%0,%1,%2,%3}, {%4,%5,%6,%7}, {%8,%9}, {%0,%1,%2,%3};\n"
        : "+f"(c[0]), "+f"(c[1]), "+f"(c[2]), "+f"(c[3])
        : "r"(a0), "r"(a1), "r"(a2), "r"(a3), "r"(b0), "r"(b1));
}

// ---------------- row L2-normalize (warp-per-row) ----------------
template <int D>
__global__ void norm_rows_kernel(const float* __restrict__ in,
                                 float* __restrict__ out) {
    int row  = blockIdx.x * 8 + (threadIdx.x >> 5);
    int lane = threadIdx.x & 31;
    const float* x = in + (size_t)row * D;
    float s = 0.f;
    for (int k = lane; k < D; k += 32) { float v = x[k]; s += v * v; }
    s = warpSum(s);
    s = __shfl_sync(0xffffffffu, s, 0);
    float scale = 1.f / fmaxf(sqrtf(s), 1e-12f);
    for (int k = lane; k < D; k += 32)
        out[(size_t)row * D + k] = x[k] * scale;
}

// ---------------- FF row inverse norms ----------------
__global__ void finv_kernel(const float* __restrict__ FF) {
    int row  = blockIdx.x * 8 + (threadIdx.x >> 5);
    int lane = threadIdx.x & 31;
    const float* x = FF + (size_t)row * DM;
    float s = 0.f;
    for (int k = lane; k < DM; k += 32) { float v = x[k]; s += v * v; }
    s = warpSum(s);
    if (lane == 0) g_Finv[row] = 1.f / fmaxf(sqrtf(s), 1e-12f);
}

// ---------------- centers prep (validated) ----------------
__global__ void prep_centers_kernel(const float* __restrict__ C) {
    int j = blockIdx.x;
    int k = threadIdx.x;
    float v = C[j * DP + k];
    g_Ct[k * NCLS + j] = v;
    float s = v * v;
    __shared__ float sh[16];
    int lane = k & 31, wid = k >> 5;
    s = warpSum(s);
    if (lane == 0) sh[wid] = s;
    __syncthreads();
    if (k == 0) {
        float t = 0.f;
        for (int w = 0; w < 16; w++) t += sh[w];
        g_csq[j] = t;
    }
}

// ---------------- logits + argmax (validated — byte identical) ----------------
__global__ void logits_kernel(const float* __restrict__ Psi,
                              float* __restrict__ out_logits) {
    __shared__ float sp[4][DP];
    __shared__ float srawsq[4];
    __shared__ float spsq[4];
    __shared__ float bv[128];
    __shared__ int   bidx[128];

    int tid  = threadIdx.x;
    int w    = tid >> 5;
    int lane = tid & 31;
    int row0 = blockIdx.x * 4;

    const float* src = Psi + (size_t)(row0 + w) * DP;
    float ss = 0.f;
    for (int k = lane; k < DP; k += 32) {
        float v = src[k];
        sp[w][k] = v;
        ss += v * v;
    }
    ss = warpSum(ss);
    if (lane == 0) srawsq[w] = ss;
    __syncthreads();
    {
        float tot = srawsq[w];
        float scl = 1.f / fmaxf(sqrtf(tot), 1e-12f);
        for (int k = lane; k < DP; k += 32) sp[w][k] *= scl;
        if (lane == 0) spsq[w] = tot * scl * scl;
    }
    __syncthreads();

    float acc0 = 0.f, acc1 = 0.f, acc2 = 0.f, acc3 = 0.f;
    for (int k = 0; k < DP; k++) {
        float c = g_Ct[k * NCLS + tid];
        acc0 = fmaf(sp[0][k], c, acc0);
        acc1 = fmaf(sp[1][k], c, acc1);
        acc2 = fmaf(sp[2][k], c, acc2);
        acc3 = fmaf(sp[3][k], c, acc3);
    }
    float accs[4] = {acc0, acc1, acc2, acc3};
    float cs = g_csq[tid];

    for (int r = 0; r < 4; r++) {
        float logit = -(spsq[r] + cs - 2.f * accs[r]);
        out_logits[(size_t)(row0 + r) * NCLS + tid] = logit;
        bv[tid] = logit;
        bidx[tid] = tid;
        __syncthreads();
        for (int off = 64; off > 0; off >>= 1) {
            if (tid < off) {
                float ov = bv[tid + off];
                int   oi = bidx[tid + off];
                if (ov > bv[tid] || (ov == bv[tid] && oi < bidx[tid])) {
                    bv[tid] = ov; bidx[tid] = oi;
                }
            }
            __syncthreads();
        }
        if (tid == 0) g_assign[row0 + r] = bidx[0];
        __syncthreads();
    }
}

// ---------------- cluster update: chunked partials (validated) ----------------
__global__ void clusterA_kernel() {
    int z = blockIdx.x;
    int j = blockIdx.y;
    int tid = threadIdx.x;
    __shared__ int sa[512];
    sa[tid] = g_assign[z * 512 + tid];
    __syncthreads();
    float acc = 0.f;
    int cnt = 0;
    for (int u = 0; u < 512; u++) {
        if (sa[u] == j) { acc += g_Psin[(size_t)(z * 512 + u) * DP + tid]; cnt++; }
    }
    g_cpart[z][j][tid] = acc;
    if (tid == 0) g_ccnt[z][j] = cnt;
}

__global__ void clusterB_kernel(const float* __restrict__ centers,
                                float* __restrict__ out_centers) {
    int j = blockIdx.x;
    int tid = threadIdx.x;
    float acc = 0.f;
    int cnt = 0;
    for (int z = 0; z < 16; z++) { acc += g_cpart[z][j][tid]; cnt += g_ccnt[z][j]; }
    float denom = fmaxf((float)cnt, 1.f);
    out_centers[j * DP + tid] = centers[j * DP + tid] * 0.9f + (acc / denom) * 0.1f;
}

// ---------------- computeD: pipelined tf32 mma, 64x128 tiles ----------------
__global__ void __launch_bounds__(256) computeD_tc(const float* __restrict__ FF) {
    __shared__ uint32_t sFi[64][36];
    __shared__ uint32_t sFj[JW][36];
    __shared__ float srow[64][2];

    int tid = threadIdx.x, wid = tid >> 5, lane = tid & 31;
    int g = lane >> 2, t = lane & 3;
    int wm = wid & 3, wn = wid >> 2;      // 4 x 2 warps; warp = m16 x n64
    int i0 = blockIdx.x * 64;

    int ir = tid >> 2, ic = (tid & 3) * 8;    // i-tile: 2 uint4
    int jr = tid >> 1, jc = (tid & 1) * 16;   // j-tile: 4 uint4

    float fia = g_Finv[i0 + ir];
    float r0 = 0.f, r1 = 0.f;

    const float* pi = FF + (size_t)(i0 + ir) * DM + ic;

    for (int j0 = 0; j0 < NR; j0 += JW) {
        float fja = g_Finv[j0 + jr];
        const float* pj = FF + (size_t)(j0 + jr) * DM + jc;

        float sc[8][4];
#pragma unroll
        for (int n8 = 0; n8 < 8; n8++)
#pragma unroll
            for (int q = 0; q < 4; q++) sc[n8][q] = 0.f;

        // prefetch chunk 0
        float4 Ra0 = *(const float4*)(pi);
        float4 Ra1 = *(const float4*)(pi + 4);
        float4 Rb0 = *(const float4*)(pj);
        float4 Rb1 = *(const float4*)(pj + 4);
        float4 Rb2 = *(const float4*)(pj + 8);
        float4 Rb3 = *(const float4*)(pj + 12);

        for (int kc = 0; kc < DM; kc += 32) {
            __syncthreads();
            *(uint4*)&sFi[ir][ic]     = cvt4(Ra0, fia);
            *(uint4*)&sFi[ir][ic + 4] = cvt4(Ra1, fia);
            *(uint4*)&sFj[jr][jc]      = cvt4(Rb0, fja);
            *(uint4*)&sFj[jr][jc + 4]  = cvt4(Rb1, fja);
            *(uint4*)&sFj[jr][jc + 8]  = cvt4(Rb2, fja);
            *(uint4*)&sFj[jr][jc + 12] = cvt4(Rb3, fja);
            if (kc + 32 < DM) {
                Ra0 = *(const float4*)(pi + kc + 32);
                Ra1 = *(const float4*)(pi + kc + 36);
                Rb0 = *(const float4*)(pj + kc + 32);
                Rb1 = *(const float4*)(pj + kc + 36);
                Rb2 = *(const float4*)(pj + kc + 40);
                Rb3 = *(const float4*)(pj + kc + 44);
            }
            __syncthreads();
#pragma unroll
            for (int kk = 0; kk < 4; kk++) {
                uint32_t a0 = sFi[wm * 16 + g][kk * 8 + t];
                uint32_t a1 = sFi[wm * 16 + g + 8][kk * 8 + t];
                uint32_t a2 = sFi[wm * 16 + g][kk * 8 + t + 4];
                uint32_t a3 = sFi[wm * 16 + g + 8][kk * 8 + t + 4];
#pragma unroll
                for (int n8 = 0; n8 < 8; n8++) {
                    uint32_t b0 = sFj[wn * 64 + n8 * 8 + g][kk * 8 + t];
                    uint32_t b1 = sFj[wn * 64 + n8 * 8 + g][kk * 8 + t + 4];
                    mma8(sc[n8], a0, a1, a2, a3, b0, b1);
                }
            }
        }
#pragma unroll
        for (int n8 = 0; n8 < 8; n8++) {
            int colb = j0 + wn * 64 + n8 * 8 + 2 * t;
            int rg0 = i0 + wm * 16 + g;
            float v0 = fmaxf(sc[n8][0], 0.f); if (rg0 == colb)         v0 = 0.f;
            float v1 = fmaxf(sc[n8][1], 0.f); if (rg0 == colb + 1)     v1 = 0.f;
            float v2 = fmaxf(sc[n8][2], 0.f); if (rg0 + 8 == colb)     v2 = 0.f;
            float v3 = fmaxf(sc[n8][3], 0.f); if (rg0 + 8 == colb + 1) v3 = 0.f;
            r0 += v0 + v1;
            r1 += v2 + v3;
        }
    }
    r0 += __shfl_xor_sync(0xffffffffu, r0, 1);
    r0 += __shfl_xor_sync(0xffffffffu, r0, 2);
    r1 += __shfl_xor_sync(0xffffffffu, r1, 1);
    r1 += __shfl_xor_sync(0xffffffffu, r1, 2);
    if (t == 0) {
        srow[wm * 16 + g][wn]     = r0;
        srow[wm * 16 + g + 8][wn] = r1;
    }
    __syncthreads();
    if (tid < 64) {
        float D = (srow[tid][0] + srow[tid][1]) / (float)(NR - 1);
        g_Drs[i0 + tid] = rsqrtf(fmaxf(D, 1e-30f));
    }
}

// ---------------- gpsi: 512 threads, full 512-col tile, pipelined -------------
__global__ void __launch_bounds__(512, 1) gpsi_tc(const float* __restrict__ FF,
                                                  const float* __restrict__ Psi) {
    extern __shared__ uint32_t dyn[];
    uint32_t (*sS)[68]  = (uint32_t(*)[68])dyn;                 // 64x68
    uint32_t* stage     = dyn + 64 * 68;
    uint32_t (*sFi)[36] = (uint32_t(*)[36])stage;               // 64x36
    uint32_t (*sFj)[36] = (uint32_t(*)[36])(stage + 64 * 36);   // 64x36
    uint32_t (*sW)[520] = (uint32_t(*)[520])stage;              // 16x520

    int tid = threadIdx.x, wid = tid >> 5, lane = tid & 31;
    int g = lane >> 2, t = lane & 3;
    int wm = wid & 3, wn = wid >> 2;      // 4 x 4 warps
    int i0 = blockIdx.x * 64;

    int ir = tid >> 3, ic = (tid & 7) * 4;     // S-build staging: 1 uint4 each
    int wr = tid >> 5, wc = (tid & 31) * 16;   // W staging: 4 uint4

    float fia = g_Finv[i0 + ir];
    const float* pi = FF + (size_t)(i0 + ir) * DM + ic;

    float gacc[16][4];
#pragma unroll
    for (int f = 0; f < 16; f++)
#pragma unroll
        for (int q = 0; q < 4; q++) gacc[f][q] = 0.f;

    for (int kt = 0; kt < NR; kt += 64) {
        float fja = g_Finv[kt + ir];
        const float* pj = FF + (size_t)(kt + ir) * DM + ic;

        float sc[2][4];
#pragma unroll
        for (int n8 = 0; n8 < 2; n8++)
#pragma unroll
            for (int q = 0; q < 4; q++) sc[n8][q] = 0.f;

        // ---- S-build (pipelined) ----
        float4 Ri = *(const float4*)(pi);
        float4 Rj = *(const float4*)(pj);
        for (int kc = 0; kc < DM; kc += 32) {
            __syncthreads();
            *(uint4*)&sFi[ir][ic] = cvt4(Ri, fia);
            *(uint4*)&sFj[ir][ic] = cvt4(Rj, fja);
            if (kc + 32 < DM) {
                Ri = *(const float4*)(pi + kc + 32);
                Rj = *(const float4*)(pj + kc + 32);
            }
            __syncthreads();
#pragma unroll
            for (int kk = 0; kk < 4; kk++) {
                uint32_t a0 = sFi[wm * 16 + g][kk * 8 + t];
                uint32_t a1 = sFi[wm * 16 + g + 8][kk * 8 + t];
                uint32_t a2 = sFi[wm * 16 + g][kk * 8 + t + 4];
                uint32_t a3 = sFi[wm * 16 + g + 8][kk * 8 + t + 4];
#pragma unroll
                for (int n8 = 0; n8 < 2; n8++) {
                    uint32_t b0 = sFj[wn * 16 + n8 * 8 + g][kk * 8 + t];
                    uint32_t b1 = sFj[wn * 16 + n8 * 8 + g][kk * 8 + t + 4];
                    mma8(sc[n8], a0, a1, a2, a3, b0, b1);
                }
            }
        }
        __syncthreads();
        // clamp + diag -> sS
#pragma unroll
        for (int n8 = 0; n8 < 2; n8++) {
            int row_l0 = wm * 16 + g;
            int col_l  = wn * 16 + n8 * 8 + 2 * t;
            float v0 = fmaxf(sc[n8][0], 0.f); if (i0 + row_l0 == kt + col_l)         v0 = 0.f;
            float v1 = fmaxf(sc[n8][1], 0.f); if (i0 + row_l0 == kt + col_l + 1)     v1 = 0.f;
            float v2 = fmaxf(sc[n8][2], 0.f); if (i0 + row_l0 + 8 == kt + col_l)     v2 = 0.f;
            float v3 = fmaxf(sc[n8][3], 0.f); if (i0 + row_l0 + 8 == kt + col_l + 1) v3 = 0.f;
            sS[row_l0][col_l]         = f2tf32(v0);
            sS[row_l0][col_l + 1]     = f2tf32(v1);
            sS[row_l0 + 8][col_l]     = f2tf32(v2);
            sS[row_l0 + 8][col_l + 1] = f2tf32(v3);
        }
        __syncthreads();

        // ---- S @ W (pipelined over ch) ----
        const float* pw = Psi + (size_t)(kt + wr) * DP + wc;
        float4 W0 = *(const float4*)(pw);
        float4 W1 = *(const float4*)(pw + 4);
        float4 W2 = *(const float4*)(pw + 8);
        float4 W3 = *(const float4*)(pw + 12);
#pragma unroll
        for (int ch = 0; ch < 4; ch++) {
            float wsc = g_Drs[kt + ch * 16 + wr] * SCALE;
            __syncthreads();
            *(uint4*)&sW[wr][wc]      = cvt4(W0, wsc);
            *(uint4*)&sW[wr][wc + 4]  = cvt4(W1, wsc);
            *(uint4*)&sW[wr][wc + 8]  = cvt4(W2, wsc);
            *(uint4*)&sW[wr][wc + 12] = cvt4(W3, wsc);
            if (ch < 3) {
                const float* pn = pw + (size_t)(ch + 1) * 16 * DP;
                W0 = *(const float4*)(pn);
                W1 = *(const float4*)(pn + 4);
                W2 = *(const float4*)(pn + 8);
                W3 = *(const float4*)(pn + 12);
            }
            __syncthreads();
#pragma unroll
            for (int kk = 0; kk < 2; kk++) {
                uint32_t a0 = sS[wm * 16 + g][ch * 16 + kk * 8 + t];
                uint32_t a1 = sS[wm * 16 + g + 8][ch * 16 + kk * 8 + t];
                uint32_t a2 = sS[wm * 16 + g][ch * 16 + kk * 8 + t + 4];
                uint32_t a3 = sS[wm * 16 + g + 8][ch * 16 + kk * 8 + t + 4];
#pragma unroll
                for (int n8 = 0; n8 < 16; n8++) {
                    uint32_t b0 = sW[kk * 8 + t][wn * 128 + n8 * 8 + g];
                    uint32_t b1 = sW[kk * 8 + t + 4][wn * 128 + n8 * 8 + g];
                    mma8(gacc[n8], a0, a1, a2, a3, b0, b1);
                }
            }
        }
        __syncthreads();   // sW region reused as sFi/sFj next kt
    }

    // epilogue
    int row = i0 + wm * 16 + g;
    float d0 = g_Drs[row], d1 = g_Drs[row + 8];
#pragma unroll
    for (int n8 = 0; n8 < 16; n8++) {
        int col = wn * 128 + n8 * 8 + 2 * t;
        float* p0 = g_gPsi + (size_t)row * DP + col;
        float* p1 = g_gPsi + (size_t)(row + 8) * DP + col;
        p0[0] = d0 * gacc[n8][0];
        p0[1] = d0 * gacc[n8][1];
        p1[0] = d1 * gacc[n8][2];
        p1[1] = d1 * gacc[n8][3];
    }
}

// ---------------- gemm3: R partials, pipelined ----------------
__global__ void __launch_bounds__(256) gemm3_tc(const float* __restrict__ Psi) {
    __shared__ uint32_t Xs[64][33];
    __shared__ uint32_t Ys[32][68];

    int tid = threadIdx.x, wid = tid >> 5, lane = tid & 31;
    int g = lane >> 2, t = lane & 3;
    int wm = wid & 3, wn = wid >> 2;
    int b0 = blockIdx.x * 64, a0 = blockIdx.y * 64, z = blockIdx.z;

    int lk = tid >> 3, la8 = (tid & 7) * 8;

    float sc[4][4];
#pragma unroll
    for (int n8 = 0; n8 < 4; n8++)
#pragma unroll
        for (int q = 0; q < 4; q++) sc[n8][q] = 0.f;

    int kbeg = z * (NR / 4);
    const float* px = Psi + (size_t)(kbeg + lk) * DP + a0 + la8;
    const float* py = g_gPsi + (size_t)(kbeg + lk) * DP + b0 + la8;

    float4 X0 = *(const float4*)(px);
    float4 X1 = *(const float4*)(px + 4);
    float4 Y0 = *(const float4*)(py);
    float4 Y1 = *(const float4*)(py + 4);

    for (int k0 = 0; k0 < NR / 4; k0 += 32) {
        __syncthreads();
        Xs[la8 + 0][lk] = f2tf32(X0.x * SCALE); Xs[la8 + 1][lk] = f2tf32(X0.y * SCALE);
        Xs[la8 + 2][lk] = f2tf32(X0.z * SCALE); Xs[la8 + 3][lk] = f2tf32(X0.w * SCALE);
        Xs[la8 + 4][lk] = f2tf32(X1.x * SCALE); Xs[la8 + 5][lk] = f2tf32(X1.y * SCALE);
        Xs[la8 + 6][lk] = f2tf32(X1.z * SCALE); Xs[la8 + 7][lk] = f2tf32(X1.w * SCALE);
        *(uint4*)&Ys[lk][la8]     = cvt4(Y0, 1.f);
        *(uint4*)&Ys[lk][la8 + 4] = cvt4(Y1, 1.f);
        if (k0 + 32 < NR / 4) {
            const float* nx = px + (size_t)(k0 + 32) * DP;
            const float* ny = py + (size_t)(k0 + 32) * DP;
            X0 = *(const float4*)(nx);
            X1 = *(const float4*)(nx + 4);
            Y0 = *(const float4*)(ny);
            Y1 = *(const float4*)(ny + 4);
        }
        __syncthreads();
#pragma unroll
        for (int kk = 0; kk < 4; kk++) {
            uint32_t fa0 = Xs[wm * 16 + g][kk * 8 + t];
            uint32_t fa1 = Xs[wm * 16 + g + 8][kk * 8 + t];
            uint32_t fa2 = Xs[wm * 16 + g][kk * 8 + t + 4];
            uint32_t fa3 = Xs[wm * 16 + g + 8][kk * 8 + t + 4];
#pragma unroll
            for (int n8 = 0; n8 < 4; n8++) {
                uint32_t fb0 = Ys[kk * 8 + t][wn * 32 + n8 * 8 + g];
                uint32_t fb1 = Ys[kk * 8 + t + 4][wn * 32 + n8 * 8 + g];
                mma8(sc[n8], fa0, fa1, fa2, fa3, fb0, fb1);
            }
        }
    }
    int a = a0 + wm * 16 + g;
#pragma unroll
    for (int n8 = 0; n8 < 4; n8++) {
        int b = b0 + wn * 32 + n8 * 8 + 2 * t;
        g_R4[z][a * DP + b]           = sc[n8][0];
        g_R4[z][a * DP + b + 1]       = sc[n8][1];
        g_R4[z][(a + 8) * DP + b]     = sc[n8][2];
        g_R4[z][(a + 8) * DP + b + 1] = sc[n8][3];
    }
}

// ---------------- final: trace + triu reg ----------------
__global__ void final_kernel(float* __restrict__ out2) {
    int b = threadIdx.x;
    float tr = 0.f, rg = 0.f;
    for (int a = 0; a < DP; a++) {
        float s = g_R4[0][a * DP + b] + g_R4[1][a * DP + b]
                + g_R4[2][a * DP + b] + g_R4[3][a * DP + b];
        if (b == a) tr += s;
        else if (b > a) rg += s * s;
    }
    __shared__ float st[DP], sr[DP];
    st[b] = tr; sr[b] = rg;
    __syncthreads();
    if (b == 0) {
        double T = 0.0, R = 0.0;
        for (int i = 0; i < DP; i++) { T += (double)st[i]; R += (double)sr[i]; }
        out2[0] = (float)(-T);
        out2[1] = (float)(R * 0.02);
    }
}

// ---------------- launcher ----------------
extern "C" void kernel_launch(void* const* d_in, const int* in_sizes, int n_in,
                              void* d_out, int out_size) {
    const float* FF  = (const float*)d_in[0];
    const float* Psi = (const float*)d_in[1];
    const float* C   = (const float*)d_in[2];
    float* out = (float*)d_out;

    float* out_logits  = out;
    float* out_centers = out + (size_t)NR * NCLS;
    float* out_scal    = out + (size_t)NR * NCLS + NCLS * DP;

    static int smem_set = 0;
    if (!smem_set) {
        cudaFuncSetAttribute(gpsi_tc, cudaFuncAttributeMaxDynamicSharedMemorySize, 50688);
        smem_set = 1;
    }

    // clustering branch
    norm_rows_kernel<DP><<<NR / 8, 256>>>(Psi, g_Psin);
    prep_centers_kernel<<<NCLS, DP>>>(C);
    logits_kernel<<<NR / 4, 128>>>(Psi, out_logits);
    clusterA_kernel<<<dim3(16, NCLS), 512>>>();
    clusterB_kernel<<<NCLS, DP>>>(C, out_centers);

    // neuralef branch
    finv_kernel<<<NR / 8, 256>>>(FF);
    computeD_tc<<<NR / 64, 256>>>(FF);
    gpsi_tc<<<NR / 64, 512, 50688>>>(FF, Psi);
    gemm3_tc<<<dim3(DP / 64, DP / 64, 4), 256>>>(Psi);
    final_kernel<<<1, DP>>>(out_scal);
}

// round 9
// speedup vs baseline: 4.4772x; 1.2837x over previous
#include <cuda_runtime.h>
#include <math.h>
#include <stdint.h>

#define NR     8192
#define DM     768
#define DP     512
#define NCLS   128
#define SCALE  (10.f / 8192.f)

// ---------------- scratch ----------------
__device__ float g_Pinv[NR];
__device__ float g_Finv[NR];
__device__ float g_Drs[NR];
__device__ float g_pD[128][NR];        // partial D sums: [colblock][row]
__device__ float g_gPsi[NR * DP];
__device__ float g_Ct[DP * NCLS];
__device__ float g_csq[NCLS];
__device__ int   g_assign[NR];
__device__ float g_R4[4][DP * DP];
__device__ float g_cpart[16][NCLS][DP];
__device__ int   g_ccnt[16][NCLS];

__device__ __forceinline__ float warpSum(float v) {
#pragma unroll
    for (int o = 16; o > 0; o >>= 1) v += __shfl_down_sync(0xffffffffu, v, o);
    return v;
}

__device__ __forceinline__ uint32_t f2tf32(float x) {
    uint32_t y;
    asm("cvt.rna.tf32.f32 %0, %1;" : "=r"(y) : "f"(x));
    return y;
}
__device__ __forceinline__ uint4 cvt4(float4 v, float s) {
    uint4 u;
    u.x = f2tf32(v.x * s); u.y = f2tf32(v.y * s);
    u.z = f2tf32(v.z * s); u.w = f2tf32(v.w * s);
    return u;
}

__device__ __forceinline__ void mma8(float* c,
                                     uint32_t a0, uint32_t a1, uint32_t a2, uint32_t a3,
                                     uint32_t b0, uint32_t b1) {
    asm volatile(
        "mma.sync.aligned.m16n8k8.row.col.f32.tf32.tf32.f32 "
        "{%0,%1,%2,%3}, {%4,%5,%6,%7}, {%8,%9}, {%0,%1,%2,%3};\n"
        : "+f"(c[0]), "+f"(c[1]), "+f"(c[2]), "+f"(c[3])
        : "r"(a0), "r"(a1), "r"(a2), "r"(a3), "r"(b0), "r"(b1));
}

// ---------------- FF row inverse norms ----------------
__global__ void finv_kernel(const float* __restrict__ FF) {
    int row  = blockIdx.x * 8 + (threadIdx.x >> 5);
    int lane = threadIdx.x & 31;
    const float* x = FF + (size_t)row * DM;
    float s = 0.f;
    for (int k = lane; k < DM; k += 32) { float v = x[k]; s += v * v; }
    s = warpSum(s);
    if (lane == 0) g_Finv[row] = 1.f / fmaxf(sqrtf(s), 1e-12f);
}

// ---------------- centers prep (validated) ----------------
__global__ void prep_centers_kernel(const float* __restrict__ C) {
    int j = blockIdx.x;
    int k = threadIdx.x;
    float v = C[j * DP + k];
    g_Ct[k * NCLS + j] = v;
    float s = v * v;
    __shared__ float sh[16];
    int lane = k & 31, wid = k >> 5;
    s = warpSum(s);
    if (lane == 0) sh[wid] = s;
    __syncthreads();
    if (k == 0) {
        float t = 0.f;
        for (int w = 0; w < 16; w++) t += sh[w];
        g_csq[j] = t;
    }
}

// ---------------- logits + argmax (validated; stores g_Pinv) ------------------
__global__ void logits_kernel(const float* __restrict__ Psi,
                              float* __restrict__ out_logits) {
    __shared__ float sp[4][DP];
    __shared__ float srawsq[4];
    __shared__ float spsq[4];
    __shared__ float bv[128];
    __shared__ int   bidx[128];

    int tid  = threadIdx.x;
    int w    = tid >> 5;
    int lane = tid & 31;
    int row0 = blockIdx.x * 4;

    const float* src = Psi + (size_t)(row0 + w) * DP;
    float ss = 0.f;
    for (int k = lane; k < DP; k += 32) {
        float v = src[k];
        sp[w][k] = v;
        ss += v * v;
    }
    ss = warpSum(ss);
    if (lane == 0) srawsq[w] = ss;
    __syncthreads();
    {
        float tot = srawsq[w];
        float scl = 1.f / fmaxf(sqrtf(tot), 1e-12f);
        for (int k = lane; k < DP; k += 32) sp[w][k] *= scl;
        if (lane == 0) { spsq[w] = tot * scl * scl; g_Pinv[row0 + w] = scl; }
    }
    __syncthreads();

    float acc0 = 0.f, acc1 = 0.f, acc2 = 0.f, acc3 = 0.f;
    for (int k = 0; k < DP; k++) {
        float c = g_Ct[k * NCLS + tid];
        acc0 = fmaf(sp[0][k], c, acc0);
        acc1 = fmaf(sp[1][k], c, acc1);
        acc2 = fmaf(sp[2][k], c, acc2);
        acc3 = fmaf(sp[3][k], c, acc3);
    }
    float accs[4] = {acc0, acc1, acc2, acc3};
    float cs = g_csq[tid];

    for (int r = 0; r < 4; r++) {
        float logit = -(spsq[r] + cs - 2.f * accs[r]);
        out_logits[(size_t)(row0 + r) * NCLS + tid] = logit;
        bv[tid] = logit;
        bidx[tid] = tid;
        __syncthreads();
        for (int off = 64; off > 0; off >>= 1) {
            if (tid < off) {
                float ov = bv[tid + off];
                int   oi = bidx[tid + off];
                if (ov > bv[tid] || (ov == bv[tid] && oi < bidx[tid])) {
                    bv[tid] = ov; bidx[tid] = oi;
                }
            }
            __syncthreads();
        }
        if (tid == 0) g_assign[row0 + r] = bidx[0];
        __syncthreads();
    }
}

// ---------------- cluster update: chunked partials (validated r8) -------------
__global__ void clusterA_kernel(const float* __restrict__ Psi) {
    int z = blockIdx.x;
    int j = blockIdx.y;
    int tid = threadIdx.x;
    __shared__ int   sa[512];
    __shared__ float spv[512];
    sa[tid]  = g_assign[z * 512 + tid];
    spv[tid] = g_Pinv[z * 512 + tid];
    __syncthreads();
    float acc = 0.f;
    int cnt = 0;
    for (int u = 0; u < 512; u++) {
        if (sa[u] == j) { acc += Psi[(size_t)(z * 512 + u) * DP + tid] * spv[u]; cnt++; }
    }
    g_cpart[z][j][tid] = acc;
    if (tid == 0) g_ccnt[z][j] = cnt;
}

__global__ void clusterB_kernel(const float* __restrict__ centers,
                                float* __restrict__ out_centers) {
    int j = blockIdx.x;
    int tid = threadIdx.x;
    float acc = 0.f;
    int cnt = 0;
    for (int z = 0; z < 16; z++) { acc += g_cpart[z][j][tid]; cnt += g_ccnt[z][j]; }
    float denom = fmaxf((float)cnt, 1.f);
    out_centers[j * DP + tid] = centers[j * DP + tid] * 0.9f + (acc / denom) * 0.1f;
}

// ---------------- computeD (symmetric): lower-tri 64x64 tiles, tf32 ----------
// Off-diag tile (bi,bj): rowsums -> g_pD[bj][i-rows], colsums -> g_pD[bi][j-rows].
// Diag tile: rowsums only. Every g_pD[c][i] written exactly once.
__global__ void __launch_bounds__(256) computeD_sym(const float* __restrict__ FF) {
    __shared__ uint32_t sFi[64][36];
    __shared__ uint32_t sFj[64][36];
    __shared__ float srow[64][2];
    __shared__ float scol[4][64];

    int tid = threadIdx.x, wid = tid >> 5, lane = tid & 31;
    int g = lane >> 2, t = lane & 3;
    int wm = wid & 3, wn = wid >> 2;     // 4 m-warps x 2 n-warps; warp = m16 x n32

    int bt = blockIdx.x;
    int bi = (int)floorf((sqrtf(8.f * (float)bt + 1.f) - 1.f) * 0.5f);
    while ((bi + 1) * (bi + 2) / 2 <= bt) bi++;
    while (bi * (bi + 1) / 2 > bt) bi--;
    int bj = bt - bi * (bi + 1) / 2;
    int i0 = bi * 64, j0 = bj * 64;

    int ir = tid >> 2, icf = (tid & 3) * 8;
    float fia = g_Finv[i0 + ir];
    float fja = g_Finv[j0 + ir];
    const float* pi = FF + (size_t)(i0 + ir) * DM + icf;
    const float* pj = FF + (size_t)(j0 + ir) * DM + icf;

    float sc[4][4];
#pragma unroll
    for (int n8 = 0; n8 < 4; n8++)
#pragma unroll
        for (int q = 0; q < 4; q++) sc[n8][q] = 0.f;

    float4 Ra0 = *(const float4*)(pi);
    float4 Ra1 = *(const float4*)(pi + 4);
    float4 Rb0 = *(const float4*)(pj);
    float4 Rb1 = *(const float4*)(pj + 4);

    for (int kc = 0; kc < DM; kc += 32) {
        __syncthreads();
        *(uint4*)&sFi[ir][icf]     = cvt4(Ra0, fia);
        *(uint4*)&sFi[ir][icf + 4] = cvt4(Ra1, fia);
        *(uint4*)&sFj[ir][icf]     = cvt4(Rb0, fja);
        *(uint4*)&sFj[ir][icf + 4] = cvt4(Rb1, fja);
        if (kc + 32 < DM) {
            Ra0 = *(const float4*)(pi + kc + 32);
            Ra1 = *(const float4*)(pi + kc + 36);
            Rb0 = *(const float4*)(pj + kc + 32);
            Rb1 = *(const float4*)(pj + kc + 36);
        }
        __syncthreads();
#pragma unroll
        for (int kk = 0; kk < 4; kk++) {
            uint32_t a0 = sFi[wm * 16 + g][kk * 8 + t];
            uint32_t a1 = sFi[wm * 16 + g + 8][kk * 8 + t];
            uint32_t a2 = sFi[wm * 16 + g][kk * 8 + t + 4];
            uint32_t a3 = sFi[wm * 16 + g + 8][kk * 8 + t + 4];
#pragma unroll
            for (int n8 = 0; n8 < 4; n8++) {
                uint32_t b0 = sFj[wn * 32 + n8 * 8 + g][kk * 8 + t];
                uint32_t b1 = sFj[wn * 32 + n8 * 8 + g][kk * 8 + t + 4];
                mma8(sc[n8], a0, a1, a2, a3, b0, b1);
            }
        }
    }

    // clamp + diag; accumulate row partials (over j) and col partials (over i)
    float r0 = 0.f, r1 = 0.f;
    float ca[4][2];
#pragma unroll
    for (int n8 = 0; n8 < 4; n8++) {
        int col_l = wn * 32 + n8 * 8 + 2 * t;
        int gi = i0 + wm * 16 + g;
        int gj = j0 + col_l;
        float v0 = fmaxf(sc[n8][0], 0.f); if (gi == gj)         v0 = 0.f;
        float v1 = fmaxf(sc[n8][1], 0.f); if (gi == gj + 1)     v1 = 0.f;
        float v2 = fmaxf(sc[n8][2], 0.f); if (gi + 8 == gj)     v2 = 0.f;
        float v3 = fmaxf(sc[n8][3], 0.f); if (gi + 8 == gj + 1) v3 = 0.f;
        r0 += v0 + v1;
        r1 += v2 + v3;
        ca[n8][0] = v0 + v2;   // column 2t
        ca[n8][1] = v1 + v3;   // column 2t+1
    }
    // rowsum: reduce over t (lanes differ in bits 0..1)
    r0 += __shfl_xor_sync(0xffffffffu, r0, 1);
    r0 += __shfl_xor_sync(0xffffffffu, r0, 2);
    r1 += __shfl_xor_sync(0xffffffffu, r1, 1);
    r1 += __shfl_xor_sync(0xffffffffu, r1, 2);
    if (t == 0) {
        srow[wm * 16 + g][wn]     = r0;
        srow[wm * 16 + g + 8][wn] = r1;
    }
    // colsum: reduce over g (lanes differ in bits 2..4)
#pragma unroll
    for (int n8 = 0; n8 < 4; n8++) {
#pragma unroll
        for (int h = 0; h < 2; h++) {
            float c = ca[n8][h];
            c += __shfl_xor_sync(0xffffffffu, c, 4);
            c += __shfl_xor_sync(0xffffffffu, c, 8);
            c += __shfl_xor_sync(0xffffffffu, c, 16);
            if (g == 0) scol[wm][wn * 32 + n8 * 8 + 2 * t + h] = c;
        }
    }
    __syncthreads();
    if (tid < 64) {
        g_pD[bj][i0 + tid] = srow[tid][0] + srow[tid][1];
    } else if (tid < 128 && bi != bj) {
        int c = tid - 64;
        g_pD[bi][j0 + c] = scol[0][c] + scol[1][c] + scol[2][c] + scol[3][c];
    }
}

// ---------------- reduce partials -> Drs ----------------
__global__ void reduceD_kernel() {
    int i = blockIdx.x * 256 + threadIdx.x;
    float s = 0.f;
#pragma unroll 4
    for (int c = 0; c < 128; c++) s += g_pD[c][i];
    g_Drs[i] = rsqrtf(fmaxf(s / (float)(NR - 1), 1e-30f));
}

// ---------------- gpsi: tf32, 512 threads, 512-col tile (validated r7) --------
__global__ void __launch_bounds__(512, 1) gpsi_tc(const float* __restrict__ FF,
                                                  const float* __restrict__ Psi) {
    extern __shared__ uint32_t dyn[];
    uint32_t (*sS)[68]  = (uint32_t(*)[68])dyn;                 // 64x68
    uint32_t* stage     = dyn + 64 * 68;
    uint32_t (*sFi)[36] = (uint32_t(*)[36])stage;               // 64x36
    uint32_t (*sFj)[36] = (uint32_t(*)[36])(stage + 64 * 36);   // 64x36
    uint32_t (*sW)[520] = (uint32_t(*)[520])stage;              // 16x520

    int tid = threadIdx.x, wid = tid >> 5, lane = tid & 31;
    int g = lane >> 2, t = lane & 3;
    int wm = wid & 3, wn = wid >> 2;      // 4 x 4 warps
    int i0 = blockIdx.x * 64;

    int ir = tid >> 3, ic = (tid & 7) * 4;
    int wr = tid >> 5, wc = (tid & 31) * 16;

    float fia = g_Finv[i0 + ir];
    const float* pi = FF + (size_t)(i0 + ir) * DM + ic;

    float gacc[16][4];
#pragma unroll
    for (int f = 0; f < 16; f++)
#pragma unroll
        for (int q = 0; q < 4; q++) gacc[f][q] = 0.f;

    for (int kt = 0; kt < NR; kt += 64) {
        float fja = g_Finv[kt + ir];
        const float* pj = FF + (size_t)(kt + ir) * DM + ic;

        float sc[2][4];
#pragma unroll
        for (int n8 = 0; n8 < 2; n8++)
#pragma unroll
            for (int q = 0; q < 4; q++) sc[n8][q] = 0.f;

        float4 Ri = *(const float4*)(pi);
        float4 Rj = *(const float4*)(pj);
        for (int kc = 0; kc < DM; kc += 32) {
            __syncthreads();
            *(uint4*)&sFi[ir][ic] = cvt4(Ri, fia);
            *(uint4*)&sFj[ir][ic] = cvt4(Rj, fja);
            if (kc + 32 < DM) {
                Ri = *(const float4*)(pi + kc + 32);
                Rj = *(const float4*)(pj + kc + 32);
            }
            __syncthreads();
#pragma unroll
            for (int kk = 0; kk < 4; kk++) {
                uint32_t a0 = sFi[wm * 16 + g][kk * 8 + t];
                uint32_t a1 = sFi[wm * 16 + g + 8][kk * 8 + t];
                uint32_t a2 = sFi[wm * 16 + g][kk * 8 + t + 4];
                uint32_t a3 = sFi[wm * 16 + g + 8][kk * 8 + t + 4];
#pragma unroll
                for (int n8 = 0; n8 < 2; n8++) {
                    uint32_t b0 = sFj[wn * 16 + n8 * 8 + g][kk * 8 + t];
                    uint32_t b1 = sFj[wn * 16 + n8 * 8 + g][kk * 8 + t + 4];
                    mma8(sc[n8], a0, a1, a2, a3, b0, b1);
                }
            }
        }
        __syncthreads();
#pragma unroll
        for (int n8 = 0; n8 < 2; n8++) {
            int row_l0 = wm * 16 + g;
            int col_l  = wn * 16 + n8 * 8 + 2 * t;
            float v0 = fmaxf(sc[n8][0], 0.f); if (i0 + row_l0 == kt + col_l)         v0 = 0.f;
            float v1 = fmaxf(sc[n8][1], 0.f); if (i0 + row_l0 == kt + col_l + 1)     v1 = 0.f;
            float v2 = fmaxf(sc[n8][2], 0.f); if (i0 + row_l0 + 8 == kt + col_l)     v2 = 0.f;
            float v3 = fmaxf(sc[n8][3], 0.f); if (i0 + row_l0 + 8 == kt + col_l + 1) v3 = 0.f;
            sS[row_l0][col_l]         = f2tf32(v0);
            sS[row_l0][col_l + 1]     = f2tf32(v1);
            sS[row_l0 + 8][col_l]     = f2tf32(v2);
            sS[row_l0 + 8][col_l + 1] = f2tf32(v3);
        }
        __syncthreads();

        const float* pw = Psi + (size_t)(kt + wr) * DP + wc;
        float4 W0 = *(const float4*)(pw);
        float4 W1 = *(const float4*)(pw + 4);
        float4 W2 = *(const float4*)(pw + 8);
        float4 W3 = *(const float4*)(pw + 12);
#pragma unroll
        for (int ch = 0; ch < 4; ch++) {
            float wsc = g_Drs[kt + ch * 16 + wr] * SCALE;
            __syncthreads();
            *(uint4*)&sW[wr][wc]      = cvt4(W0, wsc);
            *(uint4*)&sW[wr][wc + 4]  = cvt4(W1, wsc);
            *(uint4*)&sW[wr][wc + 8]  = cvt4(W2, wsc);
            *(uint4*)&sW[wr][wc + 12] = cvt4(W3, wsc);
            if (ch < 3) {
                const float* pn = pw + (size_t)(ch + 1) * 16 * DP;
                W0 = *(const float4*)(pn);
                W1 = *(const float4*)(pn + 4);
                W2 = *(const float4*)(pn + 8);
                W3 = *(const float4*)(pn + 12);
            }
            __syncthreads();
#pragma unroll
            for (int kk = 0; kk < 2; kk++) {
                uint32_t a0 = sS[wm * 16 + g][ch * 16 + kk * 8 + t];
                uint32_t a1 = sS[wm * 16 + g + 8][ch * 16 + kk * 8 + t];
                uint32_t a2 = sS[wm * 16 + g][ch * 16 + kk * 8 + t + 4];
                uint32_t a3 = sS[wm * 16 + g + 8][ch * 16 + kk * 8 + t + 4];
#pragma unroll
                for (int n8 = 0; n8 < 16; n8++) {
                    uint32_t b0 = sW[kk * 8 + t][wn * 128 + n8 * 8 + g];
                    uint32_t b1 = sW[kk * 8 + t + 4][wn * 128 + n8 * 8 + g];
                    mma8(gacc[n8], a0, a1, a2, a3, b0, b1);
                }
            }
        }
        __syncthreads();
    }

    int row = i0 + wm * 16 + g;
    float d0 = g_Drs[row], d1 = g_Drs[row + 8];
#pragma unroll
    for (int n8 = 0; n8 < 16; n8++) {
        int col = wn * 128 + n8 * 8 + 2 * t;
        float* p0 = g_gPsi + (size_t)row * DP + col;
        float* p1 = g_gPsi + (size_t)(row + 8) * DP + col;
        p0[0] = d0 * gacc[n8][0];
        p0[1] = d0 * gacc[n8][1];
        p1[0] = d1 * gacc[n8][2];
        p1[1] = d1 * gacc[n8][3];
    }
}

// ---------------- gemm3: R partials, tf32, pipelined (validated r7) -----------
__global__ void __launch_bounds__(256) gemm3_tc(const float* __restrict__ Psi) {
    __shared__ uint32_t Xs[64][33];
    __shared__ uint32_t Ys[32][68];

    int tid = threadIdx.x, wid = tid >> 5, lane = tid & 31;
    int g = lane >> 2, t = lane & 3;
    int wm = wid & 3, wn = wid >> 2;
    int b0 = blockIdx.x * 64, a0 = blockIdx.y * 64, z = blockIdx.z;

    int lk = tid >> 3, la8 = (tid & 7) * 8;

    float sc[4][4];
#pragma unroll
    for (int n8 = 0; n8 < 4; n8++)
#pragma unroll
        for (int q = 0; q < 4; q++) sc[n8][q] = 0.f;

    int kbeg = z * (NR / 4);
    const float* px = Psi + (size_t)(kbeg + lk) * DP + a0 + la8;
    const float* py = g_gPsi + (size_t)(kbeg + lk) * DP + b0 + la8;

    float4 X0 = *(const float4*)(px);
    float4 X1 = *(const float4*)(px + 4);
    float4 Y0 = *(const float4*)(py);
    float4 Y1 = *(const float4*)(py + 4);

    for (int k0 = 0; k0 < NR / 4; k0 += 32) {
        __syncthreads();
        Xs[la8 + 0][lk] = f2tf32(X0.x * SCALE); Xs[la8 + 1][lk] = f2tf32(X0.y * SCALE);
        Xs[la8 + 2][lk] = f2tf32(X0.z * SCALE); Xs[la8 + 3][lk] = f2tf32(X0.w * SCALE);
        Xs[la8 + 4][lk] = f2tf32(X1.x * SCALE); Xs[la8 + 5][lk] = f2tf32(X1.y * SCALE);
        Xs[la8 + 6][lk] = f2tf32(X1.z * SCALE); Xs[la8 + 7][lk] = f2tf32(X1.w * SCALE);
        *(uint4*)&Ys[lk][la8]     = cvt4(Y0, 1.f);
        *(uint4*)&Ys[lk][la8 + 4] = cvt4(Y1, 1.f);
        if (k0 + 32 < NR / 4) {
            const float* nx = px + (size_t)(k0 + 32) * DP;
            const float* ny = py + (size_t)(k0 + 32) * DP;
            X0 = *(const float4*)(nx);
            X1 = *(const float4*)(nx + 4);
            Y0 = *(const float4*)(ny);
            Y1 = *(const float4*)(ny + 4);
        }
        __syncthreads();
#pragma unroll
        for (int kk = 0; kk < 4; kk++) {
            uint32_t fa0 = Xs[wm * 16 + g][kk * 8 + t];
            uint32_t fa1 = Xs[wm * 16 + g + 8][kk * 8 + t];
            uint32_t fa2 = Xs[wm * 16 + g][kk * 8 + t + 4];
            uint32_t fa3 = Xs[wm * 16 + g + 8][kk * 8 + t + 4];
#pragma unroll
            for (int n8 = 0; n8 < 4; n8++) {
                uint32_t fb0 = Ys[kk * 8 + t][wn * 32 + n8 * 8 + g];
                uint32_t fb1 = Ys[kk * 8 + t + 4][wn * 32 + n8 * 8 + g];
                mma8(sc[n8], fa0, fa1, fa2, fa3, fb0, fb1);
            }
        }
    }
    int a = a0 + wm * 16 + g;
#pragma unroll
    for (int n8 = 0; n8 < 4; n8++) {
        int b = b0 + wn * 32 + n8 * 8 + 2 * t;
        g_R4[z][a * DP + b]           = sc[n8][0];
        g_R4[z][a * DP + b + 1]       = sc[n8][1];
        g_R4[z][(a + 8) * DP + b]     = sc[n8][2];
        g_R4[z][(a + 8) * DP + b + 1] = sc[n8][3];
    }
}

// ---------------- final: trace + triu reg ----------------
__global__ void final_kernel(float* __restrict__ out2) {
    int b = threadIdx.x;
    float tr = 0.f, rg = 0.f;
    for (int a = 0; a < DP; a++) {
        float s = g_R4[0][a * DP + b] + g_R4[1][a * DP + b]
                + g_R4[2][a * DP + b] + g_R4[3][a * DP + b];
        if (b == a) tr += s;
        else if (b > a) rg += s * s;
    }
    __shared__ float st[DP], sr[DP];
    st[b] = tr; sr[b] = rg;
    __syncthreads();
    if (b == 0) {
        double T = 0.0, R = 0.0;
        for (int i = 0; i < DP; i++) { T += (double)st[i]; R += (double)sr[i]; }
        out2[0] = (float)(-T);
        out2[1] = (float)(R * 0.02);
    }
}

// ---------------- launcher ----------------
extern "C" void kernel_launch(void* const* d_in, const int* in_sizes, int n_in,
                              void* d_out, int out_size) {
    const float* FF  = (const float*)d_in[0];
    const float* Psi = (const float*)d_in[1];
    const float* C   = (const float*)d_in[2];
    float* out = (float*)d_out;

    float* out_logits  = out;
    float* out_centers = out + (size_t)NR * NCLS;
    float* out_scal    = out + (size_t)NR * NCLS + NCLS * DP;

    static int smem_set = 0;
    if (!smem_set) {
        cudaFuncSetAttribute(gpsi_tc, cudaFuncAttributeMaxDynamicSharedMemorySize, 50688);
        smem_set = 1;
    }

    // clustering branch
    prep_centers_kernel<<<NCLS, DP>>>(C);
    logits_kernel<<<NR / 4, 128>>>(Psi, out_logits);
    clusterA_kernel<<<dim3(16, NCLS), 512>>>(Psi);
    clusterB_kernel<<<NCLS, DP>>>(C, out_centers);

    // neuralef branch
    finv_kernel<<<NR / 8, 256>>>(FF);
    computeD_sym<<<(NR / 64) * (NR / 64 + 1) / 2, 256>>>(FF);   // 8256 blocks
    reduceD_kernel<<<NR / 256, 256>>>();
    gpsi_tc<<<NR / 64, 512, 50688>>>(FF, Psi);
    gemm3_tc<<<dim3(DP / 64, DP / 64, 4), 256>>>(Psi);
    final_kernel<<<1, DP>>>(out_scal);
}

// round 10
// speedup vs baseline: 5.2220x; 1.1664x over previous
#include <cuda_runtime.h>
#include <math.h>
#include <stdint.h>

#define NR     8192
#define DM     768
#define DP     512
#define NCLS   128
#define SCALE  (10.f / 8192.f)

// ---------------- scratch ----------------
__device__ float g_Pinv[NR];
__device__ float g_Finv[NR];
__device__ float g_Drs[NR];
__device__ float g_pD[128][NR];        // partial D sums: [colblock][row]
__device__ float g_gPsi[NR * DP];
__device__ float g_Ct[DP * NCLS];
__device__ float g_csq[NCLS];
__device__ int   g_assign[NR];
__device__ float g_R4[4][DP * DP];
__device__ float g_cpart[16][NCLS][DP];
__device__ int   g_ccnt[16][NCLS];

__device__ __forceinline__ float warpSum(float v) {
#pragma unroll
    for (int o = 16; o > 0; o >>= 1) v += __shfl_down_sync(0xffffffffu, v, o);
    return v;
}

__device__ __forceinline__ uint32_t f2tf32(float x) {
    uint32_t y;
    asm("cvt.rna.tf32.f32 %0, %1;" : "=r"(y) : "f"(x));
    return y;
}
__device__ __forceinline__ uint4 cvt4(float4 v, float s) {
    uint4 u;
    u.x = f2tf32(v.x * s); u.y = f2tf32(v.y * s);
    u.z = f2tf32(v.z * s); u.w = f2tf32(v.w * s);
    return u;
}

__device__ __forceinline__ void mma8(float* c,
                                     uint32_t a0, uint32_t a1, uint32_t a2, uint32_t a3,
                                     uint32_t b0, uint32_t b1) {
    asm volatile(
        "mma.sync.aligned.m16n8k8.row.col.f32.tf32.tf32.f32 "
        "{%0,%1,%2,%3}, {%4,%5,%6,%7}, {%8,%9}, {%0,%1,%2,%3};\n"
        : "+f"(c[0]), "+f"(c[1]), "+f"(c[2]), "+f"(c[3])
        : "r"(a0), "r"(a1), "r"(a2), "r"(a3), "r"(b0), "r"(b1));
}

// ---------------- FF row inverse norms ----------------
__global__ void finv_kernel(const float* __restrict__ FF) {
    int row  = blockIdx.x * 8 + (threadIdx.x >> 5);
    int lane = threadIdx.x & 31;
    const float* x = FF + (size_t)row * DM;
    float s = 0.f;
    for (int k = lane; k < DM; k += 32) { float v = x[k]; s += v * v; }
    s = warpSum(s);
    if (lane == 0) g_Finv[row] = 1.f / fmaxf(sqrtf(s), 1e-12f);
}

// ---------------- centers prep (validated) ----------------
__global__ void prep_centers_kernel(const float* __restrict__ C) {
    int j = blockIdx.x;
    int k = threadIdx.x;
    float v = C[j * DP + k];
    g_Ct[k * NCLS + j] = v;
    float s = v * v;
    __shared__ float sh[16];
    int lane = k & 31, wid = k >> 5;
    s = warpSum(s);
    if (lane == 0) sh[wid] = s;
    __syncthreads();
    if (k == 0) {
        float t = 0.f;
        for (int w = 0; w < 16; w++) t += sh[w];
        g_csq[j] = t;
    }
}

// ---------------- logits + argmax (validated; stores g_Pinv) ------------------
__global__ void logits_kernel(const float* __restrict__ Psi,
                              float* __restrict__ out_logits) {
    __shared__ float sp[4][DP];
    __shared__ float srawsq[4];
    __shared__ float spsq[4];
    __shared__ float bv[128];
    __shared__ int   bidx[128];

    int tid  = threadIdx.x;
    int w    = tid >> 5;
    int lane = tid & 31;
    int row0 = blockIdx.x * 4;

    const float* src = Psi + (size_t)(row0 + w) * DP;
    float ss = 0.f;
    for (int k = lane; k < DP; k += 32) {
        float v = src[k];
        sp[w][k] = v;
        ss += v * v;
    }
    ss = warpSum(ss);
    if (lane == 0) srawsq[w] = ss;
    __syncthreads();
    {
        float tot = srawsq[w];
        float scl = 1.f / fmaxf(sqrtf(tot), 1e-12f);
        for (int k = lane; k < DP; k += 32) sp[w][k] *= scl;
        if (lane == 0) { spsq[w] = tot * scl * scl; g_Pinv[row0 + w] = scl; }
    }
    __syncthreads();

    float acc0 = 0.f, acc1 = 0.f, acc2 = 0.f, acc3 = 0.f;
    for (int k = 0; k < DP; k++) {
        float c = g_Ct[k * NCLS + tid];
        acc0 = fmaf(sp[0][k], c, acc0);
        acc1 = fmaf(sp[1][k], c, acc1);
        acc2 = fmaf(sp[2][k], c, acc2);
        acc3 = fmaf(sp[3][k], c, acc3);
    }
    float accs[4] = {acc0, acc1, acc2, acc3};
    float cs = g_csq[tid];

    for (int r = 0; r < 4; r++) {
        float logit = -(spsq[r] + cs - 2.f * accs[r]);
        out_logits[(size_t)(row0 + r) * NCLS + tid] = logit;
        bv[tid] = logit;
        bidx[tid] = tid;
        __syncthreads();
        for (int off = 64; off > 0; off >>= 1) {
            if (tid < off) {
                float ov = bv[tid + off];
                int   oi = bidx[tid + off];
                if (ov > bv[tid] || (ov == bv[tid] && oi < bidx[tid])) {
                    bv[tid] = ov; bidx[tid] = oi;
                }
            }
            __syncthreads();
        }
        if (tid == 0) g_assign[row0 + r] = bidx[0];
        __syncthreads();
    }
}

// ---------------- cluster update: chunked partials (validated r8) -------------
__global__ void clusterA_kernel(const float* __restrict__ Psi) {
    int z = blockIdx.x;
    int j = blockIdx.y;
    int tid = threadIdx.x;
    __shared__ int   sa[512];
    __shared__ float spv[512];
    sa[tid]  = g_assign[z * 512 + tid];
    spv[tid] = g_Pinv[z * 512 + tid];
    __syncthreads();
    float acc = 0.f;
    int cnt = 0;
    for (int u = 0; u < 512; u++) {
        if (sa[u] == j) { acc += Psi[(size_t)(z * 512 + u) * DP + tid] * spv[u]; cnt++; }
    }
    g_cpart[z][j][tid] = acc;
    if (tid == 0) g_ccnt[z][j] = cnt;
}

__global__ void clusterB_kernel(const float* __restrict__ centers,
                                float* __restrict__ out_centers) {
    int j = blockIdx.x;
    int tid = threadIdx.x;
    float acc = 0.f;
    int cnt = 0;
    for (int z = 0; z < 16; z++) { acc += g_cpart[z][j][tid]; cnt += g_ccnt[z][j]; }
    float denom = fmaxf((float)cnt, 1.f);
    out_centers[j * DP + tid] = centers[j * DP + tid] * 0.9f + (acc / denom) * 0.1f;
}

// ---------------- computeD (symmetric): lower-tri 64x64 tiles, tf32 ----------
__global__ void __launch_bounds__(256) computeD_sym(const float* __restrict__ FF) {
    __shared__ uint32_t sFi[64][36];
    __shared__ uint32_t sFj[64][36];
    __shared__ float srow[64][2];
    __shared__ float scol[4][64];

    int tid = threadIdx.x, wid = tid >> 5, lane = tid & 31;
    int g = lane >> 2, t = lane & 3;
    int wm = wid & 3, wn = wid >> 2;

    int bt = blockIdx.x;
    int bi = (int)floorf((sqrtf(8.f * (float)bt + 1.f) - 1.f) * 0.5f);
    while ((bi + 1) * (bi + 2) / 2 <= bt) bi++;
    while (bi * (bi + 1) / 2 > bt) bi--;
    int bj = bt - bi * (bi + 1) / 2;
    int i0 = bi * 64, j0 = bj * 64;

    int ir = tid >> 2, icf = (tid & 3) * 8;
    float fia = g_Finv[i0 + ir];
    float fja = g_Finv[j0 + ir];
    const float* pi = FF + (size_t)(i0 + ir) * DM + icf;
    const float* pj = FF + (size_t)(j0 + ir) * DM + icf;

    float sc[4][4];
#pragma unroll
    for (int n8 = 0; n8 < 4; n8++)
#pragma unroll
        for (int q = 0; q < 4; q++) sc[n8][q] = 0.f;

    float4 Ra0 = *(const float4*)(pi);
    float4 Ra1 = *(const float4*)(pi + 4);
    float4 Rb0 = *(const float4*)(pj);
    float4 Rb1 = *(const float4*)(pj + 4);

    for (int kc = 0; kc < DM; kc += 32) {
        __syncthreads();
        *(uint4*)&sFi[ir][icf]     = cvt4(Ra0, fia);
        *(uint4*)&sFi[ir][icf + 4] = cvt4(Ra1, fia);
        *(uint4*)&sFj[ir][icf]     = cvt4(Rb0, fja);
        *(uint4*)&sFj[ir][icf + 4] = cvt4(Rb1, fja);
        if (kc + 32 < DM) {
            Ra0 = *(const float4*)(pi + kc + 32);
            Ra1 = *(const float4*)(pi + kc + 36);
            Rb0 = *(const float4*)(pj + kc + 32);
            Rb1 = *(const float4*)(pj + kc + 36);
        }
        __syncthreads();
#pragma unroll
        for (int kk = 0; kk < 4; kk++) {
            uint32_t a0 = sFi[wm * 16 + g][kk * 8 + t];
            uint32_t a1 = sFi[wm * 16 + g + 8][kk * 8 + t];
            uint32_t a2 = sFi[wm * 16 + g][kk * 8 + t + 4];
            uint32_t a3 = sFi[wm * 16 + g + 8][kk * 8 + t + 4];
#pragma unroll
            for (int n8 = 0; n8 < 4; n8++) {
                uint32_t b0 = sFj[wn * 32 + n8 * 8 + g][kk * 8 + t];
                uint32_t b1 = sFj[wn * 32 + n8 * 8 + g][kk * 8 + t + 4];
                mma8(sc[n8], a0, a1, a2, a3, b0, b1);
            }
        }
    }

    float r0 = 0.f, r1 = 0.f;
    float ca[4][2];
#pragma unroll
    for (int n8 = 0; n8 < 4; n8++) {
        int col_l = wn * 32 + n8 * 8 + 2 * t;
        int gi = i0 + wm * 16 + g;
        int gj = j0 + col_l;
        float v0 = fmaxf(sc[n8][0], 0.f); if (gi == gj)         v0 = 0.f;
        float v1 = fmaxf(sc[n8][1], 0.f); if (gi == gj + 1)     v1 = 0.f;
        float v2 = fmaxf(sc[n8][2], 0.f); if (gi + 8 == gj)     v2 = 0.f;
        float v3 = fmaxf(sc[n8][3], 0.f); if (gi + 8 == gj + 1) v3 = 0.f;
        r0 += v0 + v1;
        r1 += v2 + v3;
        ca[n8][0] = v0 + v2;
        ca[n8][1] = v1 + v3;
    }
    r0 += __shfl_xor_sync(0xffffffffu, r0, 1);
    r0 += __shfl_xor_sync(0xffffffffu, r0, 2);
    r1 += __shfl_xor_sync(0xffffffffu, r1, 1);
    r1 += __shfl_xor_sync(0xffffffffu, r1, 2);
    if (t == 0) {
        srow[wm * 16 + g][wn]     = r0;
        srow[wm * 16 + g + 8][wn] = r1;
    }
#pragma unroll
    for (int n8 = 0; n8 < 4; n8++) {
#pragma unroll
        for (int h = 0; h < 2; h++) {
            float c = ca[n8][h];
            c += __shfl_xor_sync(0xffffffffu, c, 4);
            c += __shfl_xor_sync(0xffffffffu, c, 8);
            c += __shfl_xor_sync(0xffffffffu, c, 16);
            if (g == 0) scol[wm][wn * 32 + n8 * 8 + 2 * t + h] = c;
        }
    }
    __syncthreads();
    if (tid < 64) {
        g_pD[bj][i0 + tid] = srow[tid][0] + srow[tid][1];
    } else if (tid < 128 && bi != bj) {
        int c = tid - 64;
        g_pD[bi][j0 + c] = scol[0][c] + scol[1][c] + scol[2][c] + scol[3][c];
    }
}

// ---------------- reduce partials -> Drs ----------------
__global__ void reduceD_kernel() {
    int i = blockIdx.x * 256 + threadIdx.x;
    float s = 0.f;
#pragma unroll 4
    for (int c = 0; c < 128; c++) s += g_pD[c][i];
    g_Drs[i] = rsqrtf(fmaxf(s / (float)(NR - 1), 1e-30f));
}

// ---------------- gpsi: tf32, KT=128 k-tiles, 512 threads ---------------------
// S = clamp(Fn_i . Fn_k^T) is 64x128 per tile; warp tile m16 x n32 for S-build.
__global__ void __launch_bounds__(512, 1) gpsi_tc(const float* __restrict__ FF,
                                                  const float* __restrict__ Psi) {
    extern __shared__ uint32_t dyn[];
    uint32_t (*sS)[132] = (uint32_t(*)[132])dyn;                // 64 x 132 (128 + pad)
    uint32_t* stage     = dyn + 64 * 132;
    uint32_t (*sFi)[36] = (uint32_t(*)[36])stage;               // 64 x 36
    uint32_t (*sFj)[36] = (uint32_t(*)[36])(stage + 64 * 36);   // 128 x 36
    uint32_t (*sW)[520] = (uint32_t(*)[520])stage;              // 16 x 520

    int tid = threadIdx.x, wid = tid >> 5, lane = tid & 31;
    int g = lane >> 2, t = lane & 3;
    int wm = wid & 3, wn = wid >> 2;      // 4 x 4 warps
    int i0 = blockIdx.x * 64;

    int ir = tid >> 3, ic = (tid & 7) * 4;     // Fi staging: 1 float4/thread
    int jr = tid >> 2, jc = (tid & 3) * 8;     // Fj staging: 2 float4/thread
    int wr = tid >> 5, wc = (tid & 31) * 16;   // W staging: 4 float4/thread

    float fia = g_Finv[i0 + ir];
    const float* pi = FF + (size_t)(i0 + ir) * DM + ic;

    float gacc[16][4];
#pragma unroll
    for (int f = 0; f < 16; f++)
#pragma unroll
        for (int q = 0; q < 4; q++) gacc[f][q] = 0.f;

    for (int kt = 0; kt < NR; kt += 128) {
        float fja = g_Finv[kt + jr];
        const float* pj = FF + (size_t)(kt + jr) * DM + jc;

        float sc[4][4];
#pragma unroll
        for (int n8 = 0; n8 < 4; n8++)
#pragma unroll
            for (int q = 0; q < 4; q++) sc[n8][q] = 0.f;

        // ---- S-build: 64x128 tile, pipelined over DM ----
        float4 Ri  = *(const float4*)(pi);
        float4 Rj0 = *(const float4*)(pj);
        float4 Rj1 = *(const float4*)(pj + 4);
        for (int kc = 0; kc < DM; kc += 32) {
            __syncthreads();
            *(uint4*)&sFi[ir][ic]     = cvt4(Ri, fia);
            *(uint4*)&sFj[jr][jc]     = cvt4(Rj0, fja);
            *(uint4*)&sFj[jr][jc + 4] = cvt4(Rj1, fja);
            if (kc + 32 < DM) {
                Ri  = *(const float4*)(pi + kc + 32);
                Rj0 = *(const float4*)(pj + kc + 32);
                Rj1 = *(const float4*)(pj + kc + 36);
            }
            __syncthreads();
#pragma unroll
            for (int kk = 0; kk < 4; kk++) {
                uint32_t a0 = sFi[wm * 16 + g][kk * 8 + t];
                uint32_t a1 = sFi[wm * 16 + g + 8][kk * 8 + t];
                uint32_t a2 = sFi[wm * 16 + g][kk * 8 + t + 4];
                uint32_t a3 = sFi[wm * 16 + g + 8][kk * 8 + t + 4];
#pragma unroll
                for (int n8 = 0; n8 < 4; n8++) {
                    uint32_t b0 = sFj[wn * 32 + n8 * 8 + g][kk * 8 + t];
                    uint32_t b1 = sFj[wn * 32 + n8 * 8 + g][kk * 8 + t + 4];
                    mma8(sc[n8], a0, a1, a2, a3, b0, b1);
                }
            }
        }
        __syncthreads();
        // ---- clamp + diag -> sS (tf32 bits) ----
#pragma unroll
        for (int n8 = 0; n8 < 4; n8++) {
            int row0 = wm * 16 + g;
            int col  = wn * 32 + n8 * 8 + 2 * t;
            float v0 = fmaxf(sc[n8][0], 0.f); if (i0 + row0 == kt + col)         v0 = 0.f;
            float v1 = fmaxf(sc[n8][1], 0.f); if (i0 + row0 == kt + col + 1)     v1 = 0.f;
            float v2 = fmaxf(sc[n8][2], 0.f); if (i0 + row0 + 8 == kt + col)     v2 = 0.f;
            float v3 = fmaxf(sc[n8][3], 0.f); if (i0 + row0 + 8 == kt + col + 1) v3 = 0.f;
            sS[row0][col]         = f2tf32(v0);
            sS[row0][col + 1]     = f2tf32(v1);
            sS[row0 + 8][col]     = f2tf32(v2);
            sS[row0 + 8][col + 1] = f2tf32(v3);
        }
        __syncthreads();

        // ---- S @ W: 8 chunks of k=16 ----
        const float* pw = Psi + (size_t)(kt + wr) * DP + wc;
        float4 W0 = *(const float4*)(pw);
        float4 W1 = *(const float4*)(pw + 4);
        float4 W2 = *(const float4*)(pw + 8);
        float4 W3 = *(const float4*)(pw + 12);
#pragma unroll
        for (int ch = 0; ch < 8; ch++) {
            float wsc = g_Drs[kt + ch * 16 + wr] * SCALE;
            __syncthreads();
            *(uint4*)&sW[wr][wc]      = cvt4(W0, wsc);
            *(uint4*)&sW[wr][wc + 4]  = cvt4(W1, wsc);
            *(uint4*)&sW[wr][wc + 8]  = cvt4(W2, wsc);
            *(uint4*)&sW[wr][wc + 12] = cvt4(W3, wsc);
            if (ch < 7) {
                const float* pn = pw + (size_t)(ch + 1) * 16 * DP;
                W0 = *(const float4*)(pn);
                W1 = *(const float4*)(pn + 4);
                W2 = *(const float4*)(pn + 8);
                W3 = *(const float4*)(pn + 12);
            }
            __syncthreads();
#pragma unroll
            for (int kk = 0; kk < 2; kk++) {
                uint32_t a0 = sS[wm * 16 + g][ch * 16 + kk * 8 + t];
                uint32_t a1 = sS[wm * 16 + g + 8][ch * 16 + kk * 8 + t];
                uint32_t a2 = sS[wm * 16 + g][ch * 16 + kk * 8 + t + 4];
                uint32_t a3 = sS[wm * 16 + g + 8][ch * 16 + kk * 8 + t + 4];
#pragma unroll
                for (int n8 = 0; n8 < 16; n8++) {
                    uint32_t b0 = sW[kk * 8 + t][wn * 128 + n8 * 8 + g];
                    uint32_t b1 = sW[kk * 8 + t + 4][wn * 128 + n8 * 8 + g];
                    mma8(gacc[n8], a0, a1, a2, a3, b0, b1);
                }
            }
        }
        __syncthreads();
    }

    int row = i0 + wm * 16 + g;
    float d0 = g_Drs[row], d1 = g_Drs[row + 8];
#pragma unroll
    for (int n8 = 0; n8 < 16; n8++) {
        int col = wn * 128 + n8 * 8 + 2 * t;
        float* p0 = g_gPsi + (size_t)row * DP + col;
        float* p1 = g_gPsi + (size_t)(row + 8) * DP + col;
        p0[0] = d0 * gacc[n8][0];
        p0[1] = d0 * gacc[n8][1];
        p1[0] = d1 * gacc[n8][2];
        p1[1] = d1 * gacc[n8][3];
    }
}

// ---------------- gemm3: R partials, tf32, pipelined (validated) --------------
__global__ void __launch_bounds__(256) gemm3_tc(const float* __restrict__ Psi) {
    __shared__ uint32_t Xs[64][33];
    __shared__ uint32_t Ys[32][68];

    int tid = threadIdx.x, wid = tid >> 5, lane = tid & 31;
    int g = lane >> 2, t = lane & 3;
    int wm = wid & 3, wn = wid >> 2;
    int b0 = blockIdx.x * 64, a0 = blockIdx.y * 64, z = blockIdx.z;

    int lk = tid >> 3, la8 = (tid & 7) * 8;

    float sc[4][4];
#pragma unroll
    for (int n8 = 0; n8 < 4; n8++)
#pragma unroll
        for (int q = 0; q < 4; q++) sc[n8][q] = 0.f;

    int kbeg = z * (NR / 4);
    const float* px = Psi + (size_t)(kbeg + lk) * DP + a0 + la8;
    const float* py = g_gPsi + (size_t)(kbeg + lk) * DP + b0 + la8;

    float4 X0 = *(const float4*)(px);
    float4 X1 = *(const float4*)(px + 4);
    float4 Y0 = *(const float4*)(py);
    float4 Y1 = *(const float4*)(py + 4);

    for (int k0 = 0; k0 < NR / 4; k0 += 32) {
        __syncthreads();
        Xs[la8 + 0][lk] = f2tf32(X0.x * SCALE); Xs[la8 + 1][lk] = f2tf32(X0.y * SCALE);
        Xs[la8 + 2][lk] = f2tf32(X0.z * SCALE); Xs[la8 + 3][lk] = f2tf32(X0.w * SCALE);
        Xs[la8 + 4][lk] = f2tf32(X1.x * SCALE); Xs[la8 + 5][lk] = f2tf32(X1.y * SCALE);
        Xs[la8 + 6][lk] = f2tf32(X1.z * SCALE); Xs[la8 + 7][lk] = f2tf32(X1.w * SCALE);
        *(uint4*)&Ys[lk][la8]     = cvt4(Y0, 1.f);
        *(uint4*)&Ys[lk][la8 + 4] = cvt4(Y1, 1.f);
        if (k0 + 32 < NR / 4) {
            const float* nx = px + (size_t)(k0 + 32) * DP;
            const float* ny = py + (size_t)(k0 + 32) * DP;
            X0 = *(const float4*)(nx);
            X1 = *(const float4*)(nx + 4);
            Y0 = *(const float4*)(ny);
            Y1 = *(const float4*)(ny + 4);
        }
        __syncthreads();
#pragma unroll
        for (int kk = 0; kk < 4; kk++) {
            uint32_t fa0 = Xs[wm * 16 + g][kk * 8 + t];
            uint32_t fa1 = Xs[wm * 16 + g + 8][kk * 8 + t];
            uint32_t fa2 = Xs[wm * 16 + g][kk * 8 + t + 4];
            uint32_t fa3 = Xs[wm * 16 + g + 8][kk * 8 + t + 4];
#pragma unroll
            for (int n8 = 0; n8 < 4; n8++) {
                uint32_t fb0 = Ys[kk * 8 + t][wn * 32 + n8 * 8 + g];
                uint32_t fb1 = Ys[kk * 8 + t + 4][wn * 32 + n8 * 8 + g];
                mma8(sc[n8], fa0, fa1, fa2, fa3, fb0, fb1);
            }
        }
    }
    int a = a0 + wm * 16 + g;
#pragma unroll
    for (int n8 = 0; n8 < 4; n8++) {
        int b = b0 + wn * 32 + n8 * 8 + 2 * t;
        g_R4[z][a * DP + b]           = sc[n8][0];
        g_R4[z][a * DP + b + 1]       = sc[n8][1];
        g_R4[z][(a + 8) * DP + b]     = sc[n8][2];
        g_R4[z][(a + 8) * DP + b + 1] = sc[n8][3];
    }
}

// ---------------- final: trace + triu reg ----------------
__global__ void final_kernel(float* __restrict__ out2) {
    int b = threadIdx.x;
    float tr = 0.f, rg = 0.f;
    for (int a = 0; a < DP; a++) {
        float s = g_R4[0][a * DP + b] + g_R4[1][a * DP + b]
                + g_R4[2][a * DP + b] + g_R4[3][a * DP + b];
        if (b == a) tr += s;
        else if (b > a) rg += s * s;
    }
    __shared__ float st[DP], sr[DP];
    st[b] = tr; sr[b] = rg;
    __syncthreads();
    if (b == 0) {
        double T = 0.0, R = 0.0;
        for (int i = 0; i < DP; i++) { T += (double)st[i]; R += (double)sr[i]; }
        out2[0] = (float)(-T);
        out2[1] = (float)(R * 0.02);
    }
}

// ---------------- launcher ----------------
extern "C" void kernel_launch(void* const* d_in, const int* in_sizes, int n_in,
                              void* d_out, int out_size) {
    const float* FF  = (const float*)d_in[0];
    const float* Psi = (const float*)d_in[1];
    const float* C   = (const float*)d_in[2];
    float* out = (float*)d_out;

    float* out_logits  = out;
    float* out_centers = out + (size_t)NR * NCLS;
    float* out_scal    = out + (size_t)NR * NCLS + NCLS * DP;

    static int smem_set = 0;
    if (!smem_set) {
        cudaFuncSetAttribute(gpsi_tc, cudaFuncAttributeMaxDynamicSharedMemorySize, 67072);
        smem_set = 1;
    }

    // clustering branch
    prep_centers_kernel<<<NCLS, DP>>>(C);
    logits_kernel<<<NR / 4, 128>>>(Psi, out_logits);
    clusterA_kernel<<<dim3(16, NCLS), 512>>>(Psi);
    clusterB_kernel<<<NCLS, DP>>>(C, out_centers);

    // neuralef branch
    finv_kernel<<<NR / 8, 256>>>(FF);
    computeD_sym<<<(NR / 64) * (NR / 64 + 1) / 2, 256>>>(FF);
    reduceD_kernel<<<NR / 256, 256>>>();
    gpsi_tc<<<NR / 64, 512, 67072>>>(FF, Psi);
    gemm3_tc<<<dim3(DP / 64, DP / 64, 4), 256>>>(Psi);
    final_kernel<<<1, DP>>>(out_scal);
}

// round 11
// speedup vs baseline: 5.4760x; 1.0486x over previous
#include <cuda_runtime.h>
#include <math.h>
#include <stdint.h>

#define NR     8192
#define DM     768
#define DP     512
#define NCLS   128
#define SCALE  (10.f / 8192.f)

// ---------------- scratch ----------------
__device__ float g_Pinv[NR];
__device__ float g_Finv[NR];
__device__ float g_Drs[NR];
__device__ float g_pD[128][NR];        // partial D sums: [colblock][row]
__device__ float g_gPsi[NR * DP];
__device__ float g_Ct[DP * NCLS];
__device__ float g_csq[NCLS];
__device__ int   g_assign[NR];
__device__ float g_R4[4][DP * DP];
__device__ float g_cpart[16][NCLS][DP];
__device__ int   g_ccnt[16][NCLS];

__device__ __forceinline__ float warpSum(float v) {
#pragma unroll
    for (int o = 16; o > 0; o >>= 1) v += __shfl_down_sync(0xffffffffu, v, o);
    return v;
}

__device__ __forceinline__ uint32_t f2tf32(float x) {
    uint32_t y;
    asm("cvt.rna.tf32.f32 %0, %1;" : "=r"(y) : "f"(x));
    return y;
}
__device__ __forceinline__ uint4 cvt4(float4 v, float s) {
    uint4 u;
    u.x = f2tf32(v.x * s); u.y = f2tf32(v.y * s);
    u.z = f2tf32(v.z * s); u.w = f2tf32(v.w * s);
    return u;
}
// pack two floats into bf16x2 (lo = k even, hi = k odd)
__device__ __forceinline__ uint32_t pbf2(float lo, float hi) {
    uint32_t d;
    asm("cvt.rn.bf16x2.f32 %0, %1, %2;" : "=r"(d) : "f"(hi), "f"(lo));
    return d;
}

__device__ __forceinline__ void mma8(float* c,
                                     uint32_t a0, uint32_t a1, uint32_t a2, uint32_t a3,
                                     uint32_t b0, uint32_t b1) {
    asm volatile(
        "mma.sync.aligned.m16n8k8.row.col.f32.tf32.tf32.f32 "
        "{%0,%1,%2,%3}, {%4,%5,%6,%7}, {%8,%9}, {%0,%1,%2,%3};\n"
        : "+f"(c[0]), "+f"(c[1]), "+f"(c[2]), "+f"(c[3])
        : "r"(a0), "r"(a1), "r"(a2), "r"(a3), "r"(b0), "r"(b1));
}
__device__ __forceinline__ void mma16(float* c,
                                      uint32_t a0, uint32_t a1, uint32_t a2, uint32_t a3,
                                      uint32_t b0, uint32_t b1) {
    asm volatile(
        "mma.sync.aligned.m16n8k16.row.col.f32.bf16.bf16.f32 "
        "{%0,%1,%2,%3}, {%4,%5,%6,%7}, {%8,%9}, {%0,%1,%2,%3};\n"
        : "+f"(c[0]), "+f"(c[1]), "+f"(c[2]), "+f"(c[3])
        : "r"(a0), "r"(a1), "r"(a2), "r"(a3), "r"(b0), "r"(b1));
}

// ---------------- FF row inverse norms ----------------
__global__ void finv_kernel(const float* __restrict__ FF) {
    int row  = blockIdx.x * 8 + (threadIdx.x >> 5);
    int lane = threadIdx.x & 31;
    const float* x = FF + (size_t)row * DM;
    float s = 0.f;
    for (int k = lane; k < DM; k += 32) { float v = x[k]; s += v * v; }
    s = warpSum(s);
    if (lane == 0) g_Finv[row] = 1.f / fmaxf(sqrtf(s), 1e-12f);
}

// ---------------- centers prep (validated) ----------------
__global__ void prep_centers_kernel(const float* __restrict__ C) {
    int j = blockIdx.x;
    int k = threadIdx.x;
    float v = C[j * DP + k];
    g_Ct[k * NCLS + j] = v;
    float s = v * v;
    __shared__ float sh[16];
    int lane = k & 31, wid = k >> 5;
    s = warpSum(s);
    if (lane == 0) sh[wid] = s;
    __syncthreads();
    if (k == 0) {
        float t = 0.f;
        for (int w = 0; w < 16; w++) t += sh[w];
        g_csq[j] = t;
    }
}

// ---------------- logits + argmax (validated; stores g_Pinv) ------------------
__global__ void logits_kernel(const float* __restrict__ Psi,
                              float* __restrict__ out_logits) {
    __shared__ float sp[4][DP];
    __shared__ float srawsq[4];
    __shared__ float spsq[4];
    __shared__ float bv[128];
    __shared__ int   bidx[128];

    int tid  = threadIdx.x;
    int w    = tid >> 5;
    int lane = tid & 31;
    int row0 = blockIdx.x * 4;

    const float* src = Psi + (size_t)(row0 + w) * DP;
    float ss = 0.f;
    for (int k = lane; k < DP; k += 32) {
        float v = src[k];
        sp[w][k] = v;
        ss += v * v;
    }
    ss = warpSum(ss);
    if (lane == 0) srawsq[w] = ss;
    __syncthreads();
    {
        float tot = srawsq[w];
        float scl = 1.f / fmaxf(sqrtf(tot), 1e-12f);
        for (int k = lane; k < DP; k += 32) sp[w][k] *= scl;
        if (lane == 0) { spsq[w] = tot * scl * scl; g_Pinv[row0 + w] = scl; }
    }
    __syncthreads();

    float acc0 = 0.f, acc1 = 0.f, acc2 = 0.f, acc3 = 0.f;
    for (int k = 0; k < DP; k++) {
        float c = g_Ct[k * NCLS + tid];
        acc0 = fmaf(sp[0][k], c, acc0);
        acc1 = fmaf(sp[1][k], c, acc1);
        acc2 = fmaf(sp[2][k], c, acc2);
        acc3 = fmaf(sp[3][k], c, acc3);
    }
    float accs[4] = {acc0, acc1, acc2, acc3};
    float cs = g_csq[tid];

    for (int r = 0; r < 4; r++) {
        float logit = -(spsq[r] + cs - 2.f * accs[r]);
        out_logits[(size_t)(row0 + r) * NCLS + tid] = logit;
        bv[tid] = logit;
        bidx[tid] = tid;
        __syncthreads();
        for (int off = 64; off > 0; off >>= 1) {
            if (tid < off) {
                float ov = bv[tid + off];
                int   oi = bidx[tid + off];
                if (ov > bv[tid] || (ov == bv[tid] && oi < bidx[tid])) {
                    bv[tid] = ov; bidx[tid] = oi;
                }
            }
            __syncthreads();
        }
        if (tid == 0) g_assign[row0 + r] = bidx[0];
        __syncthreads();
    }
}

// ---------------- cluster update: chunked partials (validated r8) -------------
__global__ void clusterA_kernel(const float* __restrict__ Psi) {
    int z = blockIdx.x;
    int j = blockIdx.y;
    int tid = threadIdx.x;
    __shared__ int   sa[512];
    __shared__ float spv[512];
    sa[tid]  = g_assign[z * 512 + tid];
    spv[tid] = g_Pinv[z * 512 + tid];
    __syncthreads();
    float acc = 0.f;
    int cnt = 0;
    for (int u = 0; u < 512; u++) {
        if (sa[u] == j) { acc += Psi[(size_t)(z * 512 + u) * DP + tid] * spv[u]; cnt++; }
    }
    g_cpart[z][j][tid] = acc;
    if (tid == 0) g_ccnt[z][j] = cnt;
}

__global__ void clusterB_kernel(const float* __restrict__ centers,
                                float* __restrict__ out_centers) {
    int j = blockIdx.x;
    int tid = threadIdx.x;
    float acc = 0.f;
    int cnt = 0;
    for (int z = 0; z < 16; z++) { acc += g_cpart[z][j][tid]; cnt += g_ccnt[z][j]; }
    float denom = fmaxf((float)cnt, 1.f);
    out_centers[j * DP + tid] = centers[j * DP + tid] * 0.9f + (acc / denom) * 0.1f;
}

// ---------------- computeD (symmetric, bf16 mma16): lower-tri 64x64 tiles -----
// D only needs rowsums of A; bf16 per-entry noise averages out over 8192 terms.
__global__ void __launch_bounds__(256) computeD_sym(const float* __restrict__ FF) {
    __shared__ uint32_t sFi[64][20];   // 16 bf16x2 kpairs + pad
    __shared__ uint32_t sFj[64][20];
    __shared__ float srow[64][2];
    __shared__ float scol[4][64];

    int tid = threadIdx.x, wid = tid >> 5, lane = tid & 31;
    int g = lane >> 2, t = lane & 3;
    int wm = wid & 3, wn = wid >> 2;   // 4 m-warps x 2 n-warps; warp = m16 x n32

    int bt = blockIdx.x;
    int bi = (int)floorf((sqrtf(8.f * (float)bt + 1.f) - 1.f) * 0.5f);
    while ((bi + 1) * (bi + 2) / 2 <= bt) bi++;
    while (bi * (bi + 1) / 2 > bt) bi--;
    int bj = bt - bi * (bi + 1) / 2;
    int i0 = bi * 64, j0 = bj * 64;

    int ir = tid >> 2, icf = (tid & 3) * 8;   // 8 floats = 4 kpairs per thread
    int icp = (tid & 3) * 4;                  // pair index
    float fia = g_Finv[i0 + ir];
    float fja = g_Finv[j0 + ir];
    const float* pi = FF + (size_t)(i0 + ir) * DM + icf;
    const float* pj = FF + (size_t)(j0 + ir) * DM + icf;

    float sc[4][4];
#pragma unroll
    for (int n8 = 0; n8 < 4; n8++)
#pragma unroll
        for (int q = 0; q < 4; q++) sc[n8][q] = 0.f;

    float4 Ra0 = *(const float4*)(pi);
    float4 Ra1 = *(const float4*)(pi + 4);
    float4 Rb0 = *(const float4*)(pj);
    float4 Rb1 = *(const float4*)(pj + 4);

    for (int kc = 0; kc < DM; kc += 32) {
        __syncthreads();
        {
            uint4 wa, wb;
            wa.x = pbf2(Ra0.x * fia, Ra0.y * fia);
            wa.y = pbf2(Ra0.z * fia, Ra0.w * fia);
            wa.z = pbf2(Ra1.x * fia, Ra1.y * fia);
            wa.w = pbf2(Ra1.z * fia, Ra1.w * fia);
            wb.x = pbf2(Rb0.x * fja, Rb0.y * fja);
            wb.y = pbf2(Rb0.z * fja, Rb0.w * fja);
            wb.z = pbf2(Rb1.x * fja, Rb1.y * fja);
            wb.w = pbf2(Rb1.z * fja, Rb1.w * fja);
            *(uint4*)&sFi[ir][icp] = wa;
            *(uint4*)&sFj[ir][icp] = wb;
        }
        if (kc + 32 < DM) {
            Ra0 = *(const float4*)(pi + kc + 32);
            Ra1 = *(const float4*)(pi + kc + 36);
            Rb0 = *(const float4*)(pj + kc + 32);
            Rb1 = *(const float4*)(pj + kc + 36);
        }
        __syncthreads();
#pragma unroll
        for (int kk = 0; kk < 2; kk++) {
            uint32_t a0 = sFi[wm * 16 + g][kk * 8 + t];
            uint32_t a1 = sFi[wm * 16 + g + 8][kk * 8 + t];
            uint32_t a2 = sFi[wm * 16 + g][kk * 8 + t + 4];
            uint32_t a3 = sFi[wm * 16 + g + 8][kk * 8 + t + 4];
#pragma unroll
            for (int n8 = 0; n8 < 4; n8++) {
                uint32_t b0 = sFj[wn * 32 + n8 * 8 + g][kk * 8 + t];
                uint32_t b1 = sFj[wn * 32 + n8 * 8 + g][kk * 8 + t + 4];
                mma16(sc[n8], a0, a1, a2, a3, b0, b1);
            }
        }
    }

    float r0 = 0.f, r1 = 0.f;
    float ca[4][2];
#pragma unroll
    for (int n8 = 0; n8 < 4; n8++) {
        int col_l = wn * 32 + n8 * 8 + 2 * t;
        int gi = i0 + wm * 16 + g;
        int gj = j0 + col_l;
        float v0 = fmaxf(sc[n8][0], 0.f); if (gi == gj)         v0 = 0.f;
        float v1 = fmaxf(sc[n8][1], 0.f); if (gi == gj + 1)     v1 = 0.f;
        float v2 = fmaxf(sc[n8][2], 0.f); if (gi + 8 == gj)     v2 = 0.f;
        float v3 = fmaxf(sc[n8][3], 0.f); if (gi + 8 == gj + 1) v3 = 0.f;
        r0 += v0 + v1;
        r1 += v2 + v3;
        ca[n8][0] = v0 + v2;
        ca[n8][1] = v1 + v3;
    }
    r0 += __shfl_xor_sync(0xffffffffu, r0, 1);
    r0 += __shfl_xor_sync(0xffffffffu, r0, 2);
    r1 += __shfl_xor_sync(0xffffffffu, r1, 1);
    r1 += __shfl_xor_sync(0xffffffffu, r1, 2);
    if (t == 0) {
        srow[wm * 16 + g][wn]     = r0;
        srow[wm * 16 + g + 8][wn] = r1;
    }
#pragma unroll
    for (int n8 = 0; n8 < 4; n8++) {
#pragma unroll
        for (int h = 0; h < 2; h++) {
            float c = ca[n8][h];
            c += __shfl_xor_sync(0xffffffffu, c, 4);
            c += __shfl_xor_sync(0xffffffffu, c, 8);
            c += __shfl_xor_sync(0xffffffffu, c, 16);
            if (g == 0) scol[wm][wn * 32 + n8 * 8 + 2 * t + h] = c;
        }
    }
    __syncthreads();
    if (tid < 64) {
        g_pD[bj][i0 + tid] = srow[tid][0] + srow[tid][1];
    } else if (tid < 128 && bi != bj) {
        int c = tid - 64;
        g_pD[bi][j0 + c] = scol[0][c] + scol[1][c] + scol[2][c] + scol[3][c];
    }
}

// ---------------- reduce partials -> Drs ----------------
__global__ void reduceD_kernel() {
    int i = blockIdx.x * 256 + threadIdx.x;
    float s = 0.f;
#pragma unroll 4
    for (int c = 0; c < 128; c++) s += g_pD[c][i];
    g_Drs[i] = rsqrtf(fmaxf(s / (float)(NR - 1), 1e-30f));
}

// ---------------- gpsi: tf32, KT=128 k-tiles, 512 threads (validated r10) -----
__global__ void __launch_bounds__(512, 1) gpsi_tc(const float* __restrict__ FF,
                                                  const float* __restrict__ Psi) {
    extern __shared__ uint32_t dyn[];
    uint32_t (*sS)[132] = (uint32_t(*)[132])dyn;                // 64 x 132
    uint32_t* stage     = dyn + 64 * 132;
    uint32_t (*sFi)[36] = (uint32_t(*)[36])stage;               // 64 x 36
    uint32_t (*sFj)[36] = (uint32_t(*)[36])(stage + 64 * 36);   // 128 x 36
    uint32_t (*sW)[520] = (uint32_t(*)[520])stage;              // 16 x 520

    int tid = threadIdx.x, wid = tid >> 5, lane = tid & 31;
    int g = lane >> 2, t = lane & 3;
    int wm = wid & 3, wn = wid >> 2;      // 4 x 4 warps
    int i0 = blockIdx.x * 64;

    int ir = tid >> 3, ic = (tid & 7) * 4;
    int jr = tid >> 2, jc = (tid & 3) * 8;
    int wr = tid >> 5, wc = (tid & 31) * 16;

    float fia = g_Finv[i0 + ir];
    const float* pi = FF + (size_t)(i0 + ir) * DM + ic;

    float gacc[16][4];
#pragma unroll
    for (int f = 0; f < 16; f++)
#pragma unroll
        for (int q = 0; q < 4; q++) gacc[f][q] = 0.f;

    for (int kt = 0; kt < NR; kt += 128) {
        float fja = g_Finv[kt + jr];
        const float* pj = FF + (size_t)(kt + jr) * DM + jc;

        float sc[4][4];
#pragma unroll
        for (int n8 = 0; n8 < 4; n8++)
#pragma unroll
            for (int q = 0; q < 4; q++) sc[n8][q] = 0.f;

        // ---- S-build: 64x128 tile ----
        float4 Ri  = *(const float4*)(pi);
        float4 Rj0 = *(const float4*)(pj);
        float4 Rj1 = *(const float4*)(pj + 4);
        for (int kc = 0; kc < DM; kc += 32) {
            __syncthreads();
            *(uint4*)&sFi[ir][ic]     = cvt4(Ri, fia);
            *(uint4*)&sFj[jr][jc]     = cvt4(Rj0, fja);
            *(uint4*)&sFj[jr][jc + 4] = cvt4(Rj1, fja);
            if (kc + 32 < DM) {
                Ri  = *(const float4*)(pi + kc + 32);
                Rj0 = *(const float4*)(pj + kc + 32);
                Rj1 = *(const float4*)(pj + kc + 36);
            }
            __syncthreads();
#pragma unroll
            for (int kk = 0; kk < 4; kk++) {
                uint32_t a0 = sFi[wm * 16 + g][kk * 8 + t];
                uint32_t a1 = sFi[wm * 16 + g + 8][kk * 8 + t];
                uint32_t a2 = sFi[wm * 16 + g][kk * 8 + t + 4];
                uint32_t a3 = sFi[wm * 16 + g + 8][kk * 8 + t + 4];
#pragma unroll
                for (int n8 = 0; n8 < 4; n8++) {
                    uint32_t b0 = sFj[wn * 32 + n8 * 8 + g][kk * 8 + t];
                    uint32_t b1 = sFj[wn * 32 + n8 * 8 + g][kk * 8 + t + 4];
                    mma8(sc[n8], a0, a1, a2, a3, b0, b1);
                }
            }
        }
        __syncthreads();
#pragma unroll
        for (int n8 = 0; n8 < 4; n8++) {
            int row0 = wm * 16 + g;
            int col  = wn * 32 + n8 * 8 + 2 * t;
            float v0 = fmaxf(sc[n8][0], 0.f); if (i0 + row0 == kt + col)         v0 = 0.f;
            float v1 = fmaxf(sc[n8][1], 0.f); if (i0 + row0 == kt + col + 1)     v1 = 0.f;
            float v2 = fmaxf(sc[n8][2], 0.f); if (i0 + row0 + 8 == kt + col)     v2 = 0.f;
            float v3 = fmaxf(sc[n8][3], 0.f); if (i0 + row0 + 8 == kt + col + 1) v3 = 0.f;
            sS[row0][col]         = f2tf32(v0);
            sS[row0][col + 1]     = f2tf32(v1);
            sS[row0 + 8][col]     = f2tf32(v2);
            sS[row0 + 8][col + 1] = f2tf32(v3);
        }
        __syncthreads();

        // ---- S @ W: 8 chunks of k=16 ----
        const float* pw = Psi + (size_t)(kt + wr) * DP + wc;
        float4 W0 = *(const float4*)(pw);
        float4 W1 = *(const float4*)(pw + 4);
        float4 W2 = *(const float4*)(pw + 8);
        float4 W3 = *(const float4*)(pw + 12);
#pragma unroll
        for (int ch = 0; ch < 8; ch++) {
            float wsc = g_Drs[kt + ch * 16 + wr] * SCALE;
            __syncthreads();
            *(uint4*)&sW[wr][wc]      = cvt4(W0, wsc);
            *(uint4*)&sW[wr][wc + 4]  = cvt4(W1, wsc);
            *(uint4*)&sW[wr][wc + 8]  = cvt4(W2, wsc);
            *(uint4*)&sW[wr][wc + 12] = cvt4(W3, wsc);
            if (ch < 7) {
                const float* pn = pw + (size_t)(ch + 1) * 16 * DP;
                W0 = *(const float4*)(pn);
                W1 = *(const float4*)(pn + 4);
                W2 = *(const float4*)(pn + 8);
                W3 = *(const float4*)(pn + 12);
            }
            __syncthreads();
#pragma unroll
            for (int kk = 0; kk < 2; kk++) {
                uint32_t a0 = sS[wm * 16 + g][ch * 16 + kk * 8 + t];
                uint32_t a1 = sS[wm * 16 + g + 8][ch * 16 + kk * 8 + t];
                uint32_t a2 = sS[wm * 16 + g][ch * 16 + kk * 8 + t + 4];
                uint32_t a3 = sS[wm * 16 + g + 8][ch * 16 + kk * 8 + t + 4];
#pragma unroll
                for (int n8 = 0; n8 < 16; n8++) {
                    uint32_t b0 = sW[kk * 8 + t][wn * 128 + n8 * 8 + g];
                    uint32_t b1 = sW[kk * 8 + t + 4][wn * 128 + n8 * 8 + g];
                    mma8(gacc[n8], a0, a1, a2, a3, b0, b1);
                }
            }
        }
        __syncthreads();
    }

    int row = i0 + wm * 16 + g;
    float d0 = g_Drs[row], d1 = g_Drs[row + 8];
#pragma unroll
    for (int n8 = 0; n8 < 16; n8++) {
        int col = wn * 128 + n8 * 8 + 2 * t;
        float* p0 = g_gPsi + (size_t)row * DP + col;
        float* p1 = g_gPsi + (size_t)(row + 8) * DP + col;
        p0[0] = d0 * gacc[n8][0];
        p0[1] = d0 * gacc[n8][1];
        p1[0] = d1 * gacc[n8][2];
        p1[1] = d1 * gacc[n8][3];
    }
}

// ---------------- gemm3: R partials, tf32, pipelined (validated) --------------
__global__ void __launch_bounds__(256) gemm3_tc(const float* __restrict__ Psi) {
    __shared__ uint32_t Xs[64][33];
    __shared__ uint32_t Ys[32][68];

    int tid = threadIdx.x, wid = tid >> 5, lane = tid & 31;
    int g = lane >> 2, t = lane & 3;
    int wm = wid & 3, wn = wid >> 2;
    int b0 = blockIdx.x * 64, a0 = blockIdx.y * 64, z = blockIdx.z;

    int lk = tid >> 3, la8 = (tid & 7) * 8;

    float sc[4][4];
#pragma unroll
    for (int n8 = 0; n8 < 4; n8++)
#pragma unroll
        for (int q = 0; q < 4; q++) sc[n8][q] = 0.f;

    int kbeg = z * (NR / 4);
    const float* px = Psi + (size_t)(kbeg + lk) * DP + a0 + la8;
    const float* py = g_gPsi + (size_t)(kbeg + lk) * DP + b0 + la8;

    float4 X0 = *(const float4*)(px);
    float4 X1 = *(const float4*)(px + 4);
    float4 Y0 = *(const float4*)(py);
    float4 Y1 = *(const float4*)(py + 4);

    for (int k0 = 0; k0 < NR / 4; k0 += 32) {
        __syncthreads();
        Xs[la8 + 0][lk] = f2tf32(X0.x * SCALE); Xs[la8 + 1][lk] = f2tf32(X0.y * SCALE);
        Xs[la8 + 2][lk] = f2tf32(X0.z * SCALE); Xs[la8 + 3][lk] = f2tf32(X0.w * SCALE);
        Xs[la8 + 4][lk] = f2tf32(X1.x * SCALE); Xs[la8 + 5][lk] = f2tf32(X1.y * SCALE);
        Xs[la8 + 6][lk] = f2tf32(X1.z * SCALE); Xs[la8 + 7][lk] = f2tf32(X1.w * SCALE);
        *(uint4*)&Ys[lk][la8]     = cvt4(Y0, 1.f);
        *(uint4*)&Ys[lk][la8 + 4] = cvt4(Y1, 1.f);
        if (k0 + 32 < NR / 4) {
            const float* nx = px + (size_t)(k0 + 32) * DP;
            const float* ny = py + (size_t)(k0 + 32) * DP;
            X0 = *(const float4*)(nx);
            X1 = *(const float4*)(nx + 4);
            Y0 = *(const float4*)(ny);
            Y1 = *(const float4*)(ny + 4);
        }
        __syncthreads();
#pragma unroll
        for (int kk = 0; kk < 4; kk++) {
            uint32_t fa0 = Xs[wm * 16 + g][kk * 8 + t];
            uint32_t fa1 = Xs[wm * 16 + g + 8][kk * 8 + t];
            uint32_t fa2 = Xs[wm * 16 + g][kk * 8 + t + 4];
            uint32_t fa3 = Xs[wm * 16 + g + 8][kk * 8 + t + 4];
#pragma unroll
            for (int n8 = 0; n8 < 4; n8++) {
                uint32_t fb0 = Ys[kk * 8 + t][wn * 32 + n8 * 8 + g];
                uint32_t fb1 = Ys[kk * 8 + t + 4][wn * 32 + n8 * 8 + g];
                mma8(sc[n8], fa0, fa1, fa2, fa3, fb0, fb1);
            }
        }
    }
    int a = a0 + wm * 16 + g;
#pragma unroll
    for (int n8 = 0; n8 < 4; n8++) {
        int b = b0 + wn * 32 + n8 * 8 + 2 * t;
        g_R4[z][a * DP + b]           = sc[n8][0];
        g_R4[z][a * DP + b + 1]       = sc[n8][1];
        g_R4[z][(a + 8) * DP + b]     = sc[n8][2];
        g_R4[z][(a + 8) * DP + b + 1] = sc[n8][3];
    }
}

// ---------------- final: trace + triu reg ----------------
__global__ void final_kernel(float* __restrict__ out2) {
    int b = threadIdx.x;
    float tr = 0.f, rg = 0.f;
    for (int a = 0; a < DP; a++) {
        float s = g_R4[0][a * DP + b] + g_R4[1][a * DP + b]
                + g_R4[2][a * DP + b] + g_R4[3][a * DP + b];
        if (b == a) tr += s;
        else if (b > a) rg += s * s;
    }
    __shared__ float st[DP], sr[DP];
    st[b] = tr; sr[b] = rg;
    __syncthreads();
    if (b == 0) {
        double T = 0.0, R = 0.0;
        for (int i = 0; i < DP; i++) { T += (double)st[i]; R += (double)sr[i]; }
        out2[0] = (float)(-T);
        out2[1] = (float)(R * 0.02);
    }
}

// ---------------- launcher (fork clustering branch onto side stream) ----------
extern "C" void kernel_launch(void* const* d_in, const int* in_sizes, int n_in,
                              void* d_out, int out_size) {
    const float* FF  = (const float*)d_in[0];
    const float* Psi = (const float*)d_in[1];
    const float* C   = (const float*)d_in[2];
    float* out = (float*)d_out;

    float* out_logits  = out;
    float* out_centers = out + (size_t)NR * NCLS;
    float* out_scal    = out + (size_t)NR * NCLS + NCLS * DP;

    static cudaStream_t s2 = nullptr;
    static cudaEvent_t evFork = nullptr, evJoin = nullptr;
    if (!s2) {
        cudaStreamCreateWithFlags(&s2, cudaStreamNonBlocking);
        cudaEventCreateWithFlags(&evFork, cudaEventDisableTiming);
        cudaEventCreateWithFlags(&evJoin, cudaEventDisableTiming);
        cudaFuncSetAttribute(gpsi_tc, cudaFuncAttributeMaxDynamicSharedMemorySize, 67072);
    }

    // fork: clustering branch on s2, neuralef branch on launch stream
    cudaEventRecord(evFork, 0);
    cudaStreamWaitEvent(s2, evFork, 0);

    prep_centers_kernel<<<NCLS, DP, 0, s2>>>(C);
    logits_kernel<<<NR / 4, 128, 0, s2>>>(Psi, out_logits);
    clusterA_kernel<<<dim3(16, NCLS), 512, 0, s2>>>(Psi);
    clusterB_kernel<<<NCLS, DP, 0, s2>>>(C, out_centers);
    cudaEventRecord(evJoin, s2);

    finv_kernel<<<NR / 8, 256>>>(FF);
    computeD_sym<<<(NR / 64) * (NR / 64 + 1) / 2, 256>>>(FF);
    reduceD_kernel<<<NR / 256, 256>>>();
    gpsi_tc<<<NR / 64, 512, 67072>>>(FF, Psi);
    gemm3_tc<<<dim3(DP / 64, DP / 64, 4), 256>>>(Psi);
    final_kernel<<<1, DP>>>(out_scal);

    // join
    cudaStreamWaitEvent(0, evJoin, 0);
}

// round 14
// speedup vs baseline: 11.3325x; 2.0695x over previous
#include <cuda_runtime.h>
#include <cuda_fp16.h>
#include <math.h>
#include <stdint.h>

#define NR     8192
#define DM     768
#define DP     512
#define NCLS   128
#define SCALE  (10.f / 8192.f)

// ---------------- scratch ----------------
__device__ float g_Pinv[NR];
__device__ float g_Finv[NR];
__device__ float g_Drs[NR];
__device__ float g_pD[128][NR];
__device__ float g_gPsi[NR * DP];
__device__ float g_Ct[DP * NCLS];
__device__ float g_csq[NCLS];
__device__ int   g_assign[NR];
__device__ float g_R4[4][DP * DP];
__device__ float g_cpart[16][NCLS][DP];
__device__ int   g_ccnt[16][NCLS];
// A in fp16 (packed half2 words, row-major), split into 8 x 16MB objects
__device__ uint32_t g_A16[8][1024 * (NR / 2)];
// W = Drs*SCALE*Psi in fp16, kpair-packed: [kpair(4096)][n(512)] half2{k_even,k_odd}
__device__ uint32_t g_W16[(NR / 2) * DP];

__device__ __forceinline__ float warpSum(float v) {
#pragma unroll
    for (int o = 16; o > 0; o >>= 1) v += __shfl_down_sync(0xffffffffu, v, o);
    return v;
}
__device__ __forceinline__ uint32_t f2tf32(float x) {
    uint32_t y;
    asm("cvt.rna.tf32.f32 %0, %1;" : "=r"(y) : "f"(x));
    return y;
}
__device__ __forceinline__ uint4 cvt4(float4 v, float s) {
    uint4 u;
    u.x = f2tf32(v.x * s); u.y = f2tf32(v.y * s);
    u.z = f2tf32(v.z * s); u.w = f2tf32(v.w * s);
    return u;
}
// pack two floats to f16x2: lo -> bits[0:16), hi -> bits[16:32)
__device__ __forceinline__ uint32_t ph2(float lo, float hi) {
    uint32_t d;
    asm("cvt.rn.f16x2.f32 %0, %1, %2;" : "=r"(d) : "f"(hi), "f"(lo));
    return d;
}
__device__ __forceinline__ void mma8(float* c,
                                     uint32_t a0, uint32_t a1, uint32_t a2, uint32_t a3,
                                     uint32_t b0, uint32_t b1) {
    asm volatile(
        "mma.sync.aligned.m16n8k8.row.col.f32.tf32.tf32.f32 "
        "{%0,%1,%2,%3}, {%4,%5,%6,%7}, {%8,%9}, {%0,%1,%2,%3};\n"
        : "+f"(c[0]), "+f"(c[1]), "+f"(c[2]), "+f"(c[3])
        : "r"(a0), "r"(a1), "r"(a2), "r"(a3), "r"(b0), "r"(b1));
}
__device__ __forceinline__ void mma16h(float* c,
                                       uint32_t a0, uint32_t a1, uint32_t a2, uint32_t a3,
                                       uint32_t b0, uint32_t b1) {
    asm volatile(
        "mma.sync.aligned.m16n8k16.row.col.f32.f16.f16.f32 "
        "{%0,%1,%2,%3}, {%4,%5,%6,%7}, {%8,%9}, {%0,%1,%2,%3};\n"
        : "+f"(c[0]), "+f"(c[1]), "+f"(c[2]), "+f"(c[3])
        : "r"(a0), "r"(a1), "r"(a2), "r"(a3), "r"(b0), "r"(b1));
}
#define CPA16(dst, src)  asm volatile("cp.async.cg.shared.global [%0], [%1], 16;" :: "r"(dst), "l"(src) : "memory")
#define CPA_COMMIT()     asm volatile("cp.async.commit_group;" ::: "memory")
#define CPA_WAIT(n)      asm volatile("cp.async.wait_group %0;" :: "n"(n) : "memory")
__device__ __forceinline__ uint32_t smem_u32(const void* p) {
    uint32_t a;
    asm("{ .reg .u64 t; cvta.to.shared.u64 t, %1; cvt.u32.u64 %0, t; }" : "=r"(a) : "l"(p));
    return a;
}

// ---------------- FF row inverse norms ----------------
__global__ void finv_kernel(const float* __restrict__ FF) {
    int row  = blockIdx.x * 8 + (threadIdx.x >> 5);
    int lane = threadIdx.x & 31;
    const float* x = FF + (size_t)row * DM;
    float s = 0.f;
    for (int k = lane; k < DM; k += 32) { float v = x[k]; s += v * v; }
    s = warpSum(s);
    if (lane == 0) g_Finv[row] = 1.f / fmaxf(sqrtf(s), 1e-12f);
}

// ---------------- centers prep (validated) ----------------
__global__ void prep_centers_kernel(const float* __restrict__ C) {
    int j = blockIdx.x;
    int k = threadIdx.x;
    float v = C[j * DP + k];
    g_Ct[k * NCLS + j] = v;
    float s = v * v;
    __shared__ float sh[16];
    int lane = k & 31, wid = k >> 5;
    s = warpSum(s);
    if (lane == 0) sh[wid] = s;
    __syncthreads();
    if (k == 0) {
        float t = 0.f;
        for (int w = 0; w < 16; w++) t += sh[w];
        g_csq[j] = t;
    }
}

// ---------------- logits + argmax (validated) ----------------
__global__ void logits_kernel(const float* __restrict__ Psi,
                              float* __restrict__ out_logits) {
    __shared__ float sp[4][DP];
    __shared__ float srawsq[4];
    __shared__ float spsq[4];
    __shared__ float bv[128];
    __shared__ int   bidx[128];

    int tid  = threadIdx.x;
    int w    = tid >> 5;
    int lane = tid & 31;
    int row0 = blockIdx.x * 4;

    const float* src = Psi + (size_t)(row0 + w) * DP;
    float ss = 0.f;
    for (int k = lane; k < DP; k += 32) {
        float v = src[k];
        sp[w][k] = v;
        ss += v * v;
    }
    ss = warpSum(ss);
    if (lane == 0) srawsq[w] = ss;
    __syncthreads();
    {
        float tot = srawsq[w];
        float scl = 1.f / fmaxf(sqrtf(tot), 1e-12f);
        for (int k = lane; k < DP; k += 32) sp[w][k] *= scl;
        if (lane == 0) { spsq[w] = tot * scl * scl; g_Pinv[row0 + w] = scl; }
    }
    __syncthreads();

    float acc0 = 0.f, acc1 = 0.f, acc2 = 0.f, acc3 = 0.f;
    for (int k = 0; k < DP; k++) {
        float c = g_Ct[k * NCLS + tid];
        acc0 = fmaf(sp[0][k], c, acc0);
        acc1 = fmaf(sp[1][k], c, acc1);
        acc2 = fmaf(sp[2][k], c, acc2);
        acc3 = fmaf(sp[3][k], c, acc3);
    }
    float accs[4] = {acc0, acc1, acc2, acc3};
    float cs = g_csq[tid];

    for (int r = 0; r < 4; r++) {
        float logit = -(spsq[r] + cs - 2.f * accs[r]);
        out_logits[(size_t)(row0 + r) * NCLS + tid] = logit;
        bv[tid] = logit;
        bidx[tid] = tid;
        __syncthreads();
        for (int off = 64; off > 0; off >>= 1) {
            if (tid < off) {
                float ov = bv[tid + off];
                int   oi = bidx[tid + off];
                if (ov > bv[tid] || (ov == bv[tid] && oi < bidx[tid])) {
                    bv[tid] = ov; bidx[tid] = oi;
                }
            }
            __syncthreads();
        }
        if (tid == 0) g_assign[row0 + r] = bidx[0];
        __syncthreads();
    }
}

// ---------------- cluster update (validated) ----------------
__global__ void clusterA_kernel(const float* __restrict__ Psi) {
    int z = blockIdx.x;
    int j = blockIdx.y;
    int tid = threadIdx.x;
    __shared__ int   sa[512];
    __shared__ float spv[512];
    sa[tid]  = g_assign[z * 512 + tid];
    spv[tid] = g_Pinv[z * 512 + tid];
    __syncthreads();
    float acc = 0.f;
    int cnt = 0;
    for (int u = 0; u < 512; u++) {
        if (sa[u] == j) { acc += Psi[(size_t)(z * 512 + u) * DP + tid] * spv[u]; cnt++; }
    }
    g_cpart[z][j][tid] = acc;
    if (tid == 0) g_ccnt[z][j] = cnt;
}

__global__ void clusterB_kernel(const float* __restrict__ centers,
                                float* __restrict__ out_centers) {
    int j = blockIdx.x;
    int tid = threadIdx.x;
    float acc = 0.f;
    int cnt = 0;
    for (int z = 0; z < 16; z++) { acc += g_cpart[z][j][tid]; cnt += g_ccnt[z][j]; }
    float denom = fmaxf((float)cnt, 1.f);
    out_centers[j * DP + tid] = centers[j * DP + tid] * 0.9f + (acc / denom) * 0.1f;
}

// ---------------- computeD (tf32, symmetric) + materialize A in fp16 ----------
__global__ void __launch_bounds__(256) computeD_sym(const float* __restrict__ FF) {
    __shared__ uint32_t sFi[64][36];
    __shared__ uint32_t sFj[64][36];
    __shared__ float srow[64][2];
    __shared__ float scol[4][64];
    __shared__ __half sT[64][72];   // transposed tile for coalesced mirror store

    int tid = threadIdx.x, wid = tid >> 5, lane = tid & 31;
    int g = lane >> 2, t = lane & 3;
    int wm = wid & 3, wn = wid >> 2;

    int bt = blockIdx.x;
    int bi = (int)floorf((sqrtf(8.f * (float)bt + 1.f) - 1.f) * 0.5f);
    while ((bi + 1) * (bi + 2) / 2 <= bt) bi++;
    while (bi * (bi + 1) / 2 > bt) bi--;
    int bj = bt - bi * (bi + 1) / 2;
    int i0 = bi * 64, j0 = bj * 64;

    int ir = tid >> 2, icf = (tid & 3) * 8;
    float fia = g_Finv[i0 + ir];
    float fja = g_Finv[j0 + ir];
    const float* pi = FF + (size_t)(i0 + ir) * DM + icf;
    const float* pj = FF + (size_t)(j0 + ir) * DM + icf;

    float sc[4][4];
#pragma unroll
    for (int n8 = 0; n8 < 4; n8++)
#pragma unroll
        for (int q = 0; q < 4; q++) sc[n8][q] = 0.f;

    float4 Ra0 = *(const float4*)(pi);
    float4 Ra1 = *(const float4*)(pi + 4);
    float4 Rb0 = *(const float4*)(pj);
    float4 Rb1 = *(const float4*)(pj + 4);

    for (int kc = 0; kc < DM; kc += 32) {
        __syncthreads();
        *(uint4*)&sFi[ir][icf]     = cvt4(Ra0, fia);
        *(uint4*)&sFi[ir][icf + 4] = cvt4(Ra1, fia);
        *(uint4*)&sFj[ir][icf]     = cvt4(Rb0, fja);
        *(uint4*)&sFj[ir][icf + 4] = cvt4(Rb1, fja);
        if (kc + 32 < DM) {
            Ra0 = *(const float4*)(pi + kc + 32);
            Ra1 = *(const float4*)(pi + kc + 36);
            Rb0 = *(const float4*)(pj + kc + 32);
            Rb1 = *(const float4*)(pj + kc + 36);
        }
        __syncthreads();
#pragma unroll
        for (int kk = 0; kk < 4; kk++) {
            uint32_t a0 = sFi[wm * 16 + g][kk * 8 + t];
            uint32_t a1 = sFi[wm * 16 + g + 8][kk * 8 + t];
            uint32_t a2 = sFi[wm * 16 + g][kk * 8 + t + 4];
            uint32_t a3 = sFi[wm * 16 + g + 8][kk * 8 + t + 4];
#pragma unroll
            for (int n8 = 0; n8 < 4; n8++) {
                uint32_t b0 = sFj[wn * 32 + n8 * 8 + g][kk * 8 + t];
                uint32_t b1 = sFj[wn * 32 + n8 * 8 + g][kk * 8 + t + 4];
                mma8(sc[n8], a0, a1, a2, a3, b0, b1);
            }
        }
    }

    // clamp + diag; D partials; A stores (direct fp16 + transposed staging)
    uint32_t* Ai = g_A16[i0 >> 10];
    int gi = i0 + wm * 16 + g;
    float r0 = 0.f, r1 = 0.f;
    float ca[4][2];
#pragma unroll
    for (int n8 = 0; n8 < 4; n8++) {
        int col_l = wn * 32 + n8 * 8 + 2 * t;
        int gj = j0 + col_l;
        float v0 = fmaxf(sc[n8][0], 0.f); if (gi == gj)         v0 = 0.f;
        float v1 = fmaxf(sc[n8][1], 0.f); if (gi == gj + 1)     v1 = 0.f;
        float v2 = fmaxf(sc[n8][2], 0.f); if (gi + 8 == gj)     v2 = 0.f;
        float v3 = fmaxf(sc[n8][3], 0.f); if (gi + 8 == gj + 1) v3 = 0.f;
        r0 += v0 + v1;
        r1 += v2 + v3;
        ca[n8][0] = v0 + v2;
        ca[n8][1] = v1 + v3;
        // direct tile store (fp16 pairs)
        Ai[(size_t)(gi & 1023) * (NR / 2) + (gj >> 1)]       = ph2(v0, v1);
        Ai[(size_t)((gi + 8) & 1023) * (NR / 2) + (gj >> 1)] = ph2(v2, v3);
        // transposed staging for mirror tile
        int row_l = wm * 16 + g;
        sT[col_l][row_l]         = __float2half(v0);
        sT[col_l + 1][row_l]     = __float2half(v1);
        sT[col_l][row_l + 8]     = __float2half(v2);
        sT[col_l + 1][row_l + 8] = __float2half(v3);
    }
    r0 += __shfl_xor_sync(0xffffffffu, r0, 1);
    r0 += __shfl_xor_sync(0xffffffffu, r0, 2);
    r1 += __shfl_xor_sync(0xffffffffu, r1, 1);
    r1 += __shfl_xor_sync(0xffffffffu, r1, 2);
    if (t == 0) {
        srow[wm * 16 + g][wn]     = r0;
        srow[wm * 16 + g + 8][wn] = r1;
    }
#pragma unroll
    for (int n8 = 0; n8 < 4; n8++) {
#pragma unroll
        for (int h = 0; h < 2; h++) {
            float c = ca[n8][h];
            c += __shfl_xor_sync(0xffffffffu, c, 4);
            c += __shfl_xor_sync(0xffffffffu, c, 8);
            c += __shfl_xor_sync(0xffffffffu, c, 16);
            if (g == 0) scol[wm][wn * 32 + n8 * 8 + 2 * t + h] = c;
        }
    }
    __syncthreads();
    if (tid < 64) {
        g_pD[bj][i0 + tid] = srow[tid][0] + srow[tid][1];
    } else if (tid < 128 && bi != bj) {
        int c = tid - 64;
        g_pD[bi][j0 + c] = scol[0][c] + scol[1][c] + scol[2][c] + scol[3][c];
    }
    // mirror tile coalesced store: A[j0+row][i0 .. i0+63]
    if (bi != bj) {
        uint32_t* Aj = g_A16[j0 >> 10];
        int row = tid >> 2, seg = tid & 3;
        const uint4* srcp = (const uint4*)&sT[row][seg * 16];
        size_t wbase = (size_t)((j0 + row) & 1023) * (NR / 2) + (i0 >> 1) + seg * 8;
        *(uint4*)&Aj[wbase]     = srcp[0];
        *(uint4*)&Aj[wbase + 4] = srcp[1];
    }
}

// ---------------- reduce partials -> Drs ----------------
__global__ void reduceD_kernel() {
    int i = blockIdx.x * 256 + threadIdx.x;
    float s = 0.f;
#pragma unroll 4
    for (int c = 0; c < 128; c++) s += g_pD[c][i];
    g_Drs[i] = rsqrtf(fmaxf(s / (float)(NR - 1), 1e-30f));
}

// ---------------- W16 prep: pack Drs*SCALE*Psi as fp16 kpairs ----------------
__global__ void w16prep_kernel(const float* __restrict__ Psi) {
    int idx = blockIdx.x * 512 + threadIdx.x;     // 4096 kpairs * 32 segs
    int p = idx >> 5, seg = idx & 31;
    float w0 = g_Drs[2 * p] * SCALE;
    float w1 = g_Drs[2 * p + 1] * SCALE;
    const float* r0p = Psi + (size_t)(2 * p) * DP + seg * 16;
    const float* r1p = Psi + (size_t)(2 * p + 1) * DP + seg * 16;
    uint32_t* dst = g_W16 + (size_t)p * DP + seg * 16;
#pragma unroll
    for (int q = 0; q < 4; q++) {
        float4 x = *(const float4*)(r0p + q * 4);
        float4 y = *(const float4*)(r1p + q * 4);
        uint4 o;
        o.x = ph2(x.x * w0, y.x * w1);
        o.y = ph2(x.y * w0, y.y * w1);
        o.z = ph2(x.z * w0, y.z * w1);
        o.w = ph2(x.w * w0, y.w * w1);
        *(uint4*)(dst + q * 4) = o;
    }
}

// ---------------- gpsi: fp16 mma, A streamed via cp.async (4-deep) -----------
// block: 64 rows x 512 cols; k chunks of 32. smem/stage: W 16x520 w, A 64x20 w.
#define WST   (16 * 520)            // words per W stage
#define AST   (64 * 20)             // words per A stage
#define NCH   (NR / 32)             // 256 chunks
__global__ void __launch_bounds__(512, 1) gpsi_f16(void) {
    extern __shared__ uint32_t dyn[];
    uint32_t smb = smem_u32(dyn);
    int tid = threadIdx.x, wid = tid >> 5, lane = tid & 31;
    int g = lane >> 2, t = lane & 3;
    int wm = wid & 3, wn = wid >> 2;     // 4 m x 4 n warps; warp = m16 x n128
    int i0 = blockIdx.x * 64;
    const uint32_t* Abase = g_A16[i0 >> 10] + (size_t)(i0 & 1023) * (NR / 2);

    float gacc[16][4];
#pragma unroll
    for (int f = 0; f < 16; f++)
#pragma unroll
        for (int q = 0; q < 4; q++) gacc[f][q] = 0.f;

    // stage copy lambda (all threads): W then A
    auto issue = [&](int c) {
        int st = c & 3;
        int kt = c * 32;
        {   // W: 16 kpairs x 512 words
            int p = tid >> 5, seg = tid & 31;
            uint32_t dst = smb + (st * WST + p * 520 + seg * 16) * 4;
            const uint32_t* src = g_W16 + (size_t)((kt >> 1) + p) * DP + seg * 16;
#pragma unroll
            for (int q = 0; q < 4; q++) CPA16(dst + q * 16, src + q * 4);
        }
        if (tid < 256) {   // A: 64 rows x 16 words
            int r = tid >> 2, q = tid & 3;
            uint32_t dst = smb + (4 * WST + st * AST + r * 20 + q * 4) * 4;
            const uint32_t* src = Abase + (size_t)r * (NR / 2) + (kt >> 1) + q * 4;
            CPA16(dst, src);
        }
        CPA_COMMIT();
    };

    issue(0); issue(1); issue(2);

    for (int c = 0; c < NCH; c++) {
        if (c + 3 < NCH) issue(c + 3);
        if (c + 3 < NCH)      CPA_WAIT(3);
        else if (c + 2 < NCH) CPA_WAIT(2);
        else if (c + 1 < NCH) CPA_WAIT(1);
        else                  CPA_WAIT(0);
        __syncthreads();

        int st = c & 3;
        const uint32_t* pW = dyn + st * WST;
        const uint32_t* pA = dyn + 4 * WST + st * AST;
#pragma unroll
        for (int s = 0; s < 2; s++) {
            uint32_t a0 = pA[(wm * 16 + g) * 20 + 8 * s + t];
            uint32_t a1 = pA[(wm * 16 + g + 8) * 20 + 8 * s + t];
            uint32_t a2 = pA[(wm * 16 + g) * 20 + 8 * s + t + 4];
            uint32_t a3 = pA[(wm * 16 + g + 8) * 20 + 8 * s + t + 4];
            const uint32_t* rb0 = pW + (8 * s + t) * 520;
            const uint32_t* rb1 = pW + (8 * s + 4 + t) * 520;
#pragma unroll
            for (int n8 = 0; n8 < 16; n8++) {
                int n = wn * 128 + n8 * 8 + g;
                mma16h(gacc[n8], a0, a1, a2, a3, rb0[n], rb1[n]);
            }
        }
        __syncthreads();
    }

    // epilogue: scale by Drs_i, write fp32 gPsi
    int row = i0 + wm * 16 + g;
    float d0 = g_Drs[row], d1 = g_Drs[row + 8];
#pragma unroll
    for (int n8 = 0; n8 < 16; n8++) {
        int col = wn * 128 + n8 * 8 + 2 * t;
        *(float2*)(g_gPsi + (size_t)row * DP + col) =
            make_float2(d0 * gacc[n8][0], d0 * gacc[n8][1]);
        *(float2*)(g_gPsi + (size_t)(row + 8) * DP + col) =
            make_float2(d1 * gacc[n8][2], d1 * gacc[n8][3]);
    }
}

// ---------------- gemm3: R partials, tf32 (validated) ----------------
__global__ void __launch_bounds__(256) gemm3_tc(const float* __restrict__ Psi) {
    __shared__ uint32_t Xs[64][33];
    __shared__ uint32_t Ys[32][68];

    int tid = threadIdx.x, wid = tid >> 5, lane = tid & 31;
    int g = lane >> 2, t = lane & 3;
    int wm = wid & 3, wn = wid >> 2;
    int b0 = blockIdx.x * 64, a0 = blockIdx.y * 64, z = blockIdx.z;

    int lk = tid >> 3, la8 = (tid & 7) * 8;

    float sc[4][4];
#pragma unroll
    for (int n8 = 0; n8 < 4; n8++)
#pragma unroll
        for (int q = 0; q < 4; q++) sc[n8][q] = 0.f;

    int kbeg = z * (NR / 4);
    const float* px = Psi + (size_t)(kbeg + lk) * DP + a0 + la8;
    const float* py = g_gPsi + (size_t)(kbeg + lk) * DP + b0 + la8;

    float4 X0 = *(const float4*)(px);
    float4 X1 = *(const float4*)(px + 4);
    float4 Y0 = *(const float4*)(py);
    float4 Y1 = *(const float4*)(py + 4);

    for (int k0 = 0; k0 < NR / 4; k0 += 32) {
        __syncthreads();
        Xs[la8 + 0][lk] = f2tf32(X0.x * SCALE); Xs[la8 + 1][lk] = f2tf32(X0.y * SCALE);
        Xs[la8 + 2][lk] = f2tf32(X0.z * SCALE); Xs[la8 + 3][lk] = f2tf32(X0.w * SCALE);
        Xs[la8 + 4][lk] = f2tf32(X1.x * SCALE); Xs[la8 + 5][lk] = f2tf32(X1.y * SCALE);
        Xs[la8 + 6][lk] = f2tf32(X1.z * SCALE); Xs[la8 + 7][lk] = f2tf32(X1.w * SCALE);
        *(uint4*)&Ys[lk][la8]     = cvt4(Y0, 1.f);
        *(uint4*)&Ys[lk][la8 + 4] = cvt4(Y1, 1.f);
        if (k0 + 32 < NR / 4) {
            const float* nx = px + (size_t)(k0 + 32) * DP;
            const float* ny = py + (size_t)(k0 + 32) * DP;
            X0 = *(const float4*)(nx);
            X1 = *(const float4*)(nx + 4);
            Y0 = *(const float4*)(ny);
            Y1 = *(const float4*)(ny + 4);
        }
        __syncthreads();
#pragma unroll
        for (int kk = 0; kk < 4; kk++) {
            uint32_t fa0 = Xs[wm * 16 + g][kk * 8 + t];
            uint32_t fa1 = Xs[wm * 16 + g + 8][kk * 8 + t];
            uint32_t fa2 = Xs[wm * 16 + g][kk * 8 + t + 4];
            uint32_t fa3 = Xs[wm * 16 + g + 8][kk * 8 + t + 4];
#pragma unroll
            for (int n8 = 0; n8 < 4; n8++) {
                uint32_t fb0 = Ys[kk * 8 + t][wn * 32 + n8 * 8 + g];
                uint32_t fb1 = Ys[kk * 8 + t + 4][wn * 32 + n8 * 8 + g];
                mma8(sc[n8], fa0, fa1, fa2, fa3, fb0, fb1);
            }
        }
    }
    int a = a0 + wm * 16 + g;
#pragma unroll
    for (int n8 = 0; n8 < 4; n8++) {
        int b = b0 + wn * 32 + n8 * 8 + 2 * t;
        g_R4[z][a * DP + b]           = sc[n8][0];
        g_R4[z][a * DP + b + 1]       = sc[n8][1];
        g_R4[z][(a + 8) * DP + b]     = sc[n8][2];
        g_R4[z][(a + 8) * DP + b + 1] = sc[n8][3];
    }
}

// ---------------- final: trace + triu reg ----------------
__global__ void final_kernel(float* __restrict__ out2) {
    int b = threadIdx.x;
    float tr = 0.f, rg = 0.f;
    for (int a = 0; a < DP; a++) {
        float s = g_R4[0][a * DP + b] + g_R4[1][a * DP + b]
                + g_R4[2][a * DP + b] + g_R4[3][a * DP + b];
        if (b == a) tr += s;
        else if (b > a) rg += s * s;
    }
    __shared__ float st[DP], sr[DP];
    st[b] = tr; sr[b] = rg;
    __syncthreads();
    if (b == 0) {
        double T = 0.0, R = 0.0;
        for (int i = 0; i < DP; i++) { T += (double)st[i]; R += (double)sr[i]; }
        out2[0] = (float)(-T);
        out2[1] = (float)(R * 0.02);
    }
}

// ---------------- launcher ----------------
extern "C" void kernel_launch(void* const* d_in, const int* in_sizes, int n_in,
                              void* d_out, int out_size) {
    const float* FF  = (const float*)d_in[0];
    const float* Psi = (const float*)d_in[1];
    const float* C   = (const float*)d_in[2];
    float* out = (float*)d_out;

    float* out_logits  = out;
    float* out_centers = out + (size_t)NR * NCLS;
    float* out_scal    = out + (size_t)NR * NCLS + NCLS * DP;

    static cudaStream_t s2 = nullptr;
    static cudaEvent_t evFork = nullptr, evJoin = nullptr;
    if (!s2) {
        cudaStreamCreateWithFlags(&s2, cudaStreamNonBlocking);
        cudaEventCreateWithFlags(&evFork, cudaEventDisableTiming);
        cudaEventCreateWithFlags(&evJoin, cudaEventDisableTiming);
        cudaFuncSetAttribute(gpsi_f16, cudaFuncAttributeMaxDynamicSharedMemorySize,
                             (4 * WST + 4 * AST) * 4);
    }

    cudaEventRecord(evFork, 0);
    cudaStreamWaitEvent(s2, evFork, 0);

    prep_centers_kernel<<<NCLS, DP, 0, s2>>>(C);
    logits_kernel<<<NR / 4, 128, 0, s2>>>(Psi, out_logits);
    clusterA_kernel<<<dim3(16, NCLS), 512, 0, s2>>>(Psi);
    clusterB_kernel<<<NCLS, DP, 0, s2>>>(C, out_centers);
    cudaEventRecord(evJoin, s2);

    finv_kernel<<<NR / 8, 256>>>(FF);
    computeD_sym<<<(NR / 64) * (NR / 64 + 1) / 2, 256>>>(FF);
    reduceD_kernel<<<NR / 256, 256>>>();
    w16prep_kernel<<<(NR / 2) * (DP / 16) / 512, 512>>>(Psi);
    gpsi_f16<<<NR / 64, 512, (4 * WST + 4 * AST) * 4>>>();
    gemm3_tc<<<dim3(DP / 64, DP / 64, 4), 256>>>(Psi);
    final_kernel<<<1, DP>>>(out_scal);

    cudaStreamWaitEvent(0, evJoin, 0);
}

// round 15
// speedup vs baseline: 12.7158x; 1.1221x over previous
#include <cuda_runtime.h>
#include <cuda_fp16.h>
#include <math.h>
#include <stdint.h>

#define NR     8192
#define DM     768
#define DP     512
#define NCLS   128
#define SCALE  (10.f / 8192.f)

// ---------------- scratch ----------------
__device__ float g_Pinv[NR];
__device__ float g_Finv[NR];
__device__ float g_Drs[NR];
__device__ float g_pD[128][NR];
__device__ float g_gPsi[NR * DP];
__device__ float g_Ct[DP * NCLS];
__device__ float g_csq[NCLS];
__device__ int   g_assign[NR];
__device__ float g_R4[4][DP * DP];
__device__ float g_cpart[16][NCLS][DP];
__device__ int   g_ccnt[16][NCLS];
// A in fp16 (packed half2 words, row-major), split into 8 x 16MB objects
__device__ uint32_t g_A16[8][1024 * (NR / 2)];
// W = Drs*SCALE*Psi in fp16, kpair-packed: [kpair(4096)][n(512)] half2{k_even,k_odd}
__device__ uint32_t g_W16[(NR / 2) * DP];

__device__ __forceinline__ float warpSum(float v) {
#pragma unroll
    for (int o = 16; o > 0; o >>= 1) v += __shfl_down_sync(0xffffffffu, v, o);
    return v;
}
__device__ __forceinline__ uint32_t f2tf32(float x) {
    uint32_t y;
    asm("cvt.rna.tf32.f32 %0, %1;" : "=r"(y) : "f"(x));
    return y;
}
__device__ __forceinline__ uint4 cvt4(float4 v, float s) {
    uint4 u;
    u.x = f2tf32(v.x * s); u.y = f2tf32(v.y * s);
    u.z = f2tf32(v.z * s); u.w = f2tf32(v.w * s);
    return u;
}
// pack two floats to f16x2: lo -> bits[0:16), hi -> bits[16:32)
__device__ __forceinline__ uint32_t ph2(float lo, float hi) {
    uint32_t d;
    asm("cvt.rn.f16x2.f32 %0, %1, %2;" : "=r"(d) : "f"(hi), "f"(lo));
    return d;
}
__device__ __forceinline__ void mma8(float* c,
                                     uint32_t a0, uint32_t a1, uint32_t a2, uint32_t a3,
                                     uint32_t b0, uint32_t b1) {
    asm volatile(
        "mma.sync.aligned.m16n8k8.row.col.f32.tf32.tf32.f32 "
        "{%0,%1,%2,%3}, {%4,%5,%6,%7}, {%8,%9}, {%0,%1,%2,%3};\n"
        : "+f"(c[0]), "+f"(c[1]), "+f"(c[2]), "+f"(c[3])
        : "r"(a0), "r"(a1), "r"(a2), "r"(a3), "r"(b0), "r"(b1));
}
__device__ __forceinline__ void mma16h(float* c,
                                       uint32_t a0, uint32_t a1, uint32_t a2, uint32_t a3,
                                       uint32_t b0, uint32_t b1) {
    asm volatile(
        "mma.sync.aligned.m16n8k16.row.col.f32.f16.f16.f32 "
        "{%0,%1,%2,%3}, {%4,%5,%6,%7}, {%8,%9}, {%0,%1,%2,%3};\n"
        : "+f"(c[0]), "+f"(c[1]), "+f"(c[2]), "+f"(c[3])
        : "r"(a0), "r"(a1), "r"(a2), "r"(a3), "r"(b0), "r"(b1));
}
#define CPA16(dst, src)  asm volatile("cp.async.cg.shared.global [%0], [%1], 16;" :: "r"(dst), "l"(src) : "memory")
#define CPA_COMMIT()     asm volatile("cp.async.commit_group;" ::: "memory")
#define CPA_WAIT(n)      asm volatile("cp.async.wait_group %0;" :: "n"(n) : "memory")
__device__ __forceinline__ uint32_t smem_u32(const void* p) {
    uint32_t a;
    asm("{ .reg .u64 t; cvta.to.shared.u64 t, %1; cvt.u32.u64 %0, t; }" : "=r"(a) : "l"(p));
    return a;
}

// ---------------- FF row inverse norms ----------------
__global__ void finv_kernel(const float* __restrict__ FF) {
    int row  = blockIdx.x * 8 + (threadIdx.x >> 5);
    int lane = threadIdx.x & 31;
    const float* x = FF + (size_t)row * DM;
    float s = 0.f;
    for (int k = lane; k < DM; k += 32) { float v = x[k]; s += v * v; }
    s = warpSum(s);
    if (lane == 0) g_Finv[row] = 1.f / fmaxf(sqrtf(s), 1e-12f);
}

// ---------------- centers prep (validated) ----------------
__global__ void prep_centers_kernel(const float* __restrict__ C) {
    int j = blockIdx.x;
    int k = threadIdx.x;
    float v = C[j * DP + k];
    g_Ct[k * NCLS + j] = v;
    float s = v * v;
    __shared__ float sh[16];
    int lane = k & 31, wid = k >> 5;
    s = warpSum(s);
    if (lane == 0) sh[wid] = s;
    __syncthreads();
    if (k == 0) {
        float t = 0.f;
        for (int w = 0; w < 16; w++) t += sh[w];
        g_csq[j] = t;
    }
}

// ---------------- logits + argmax (validated) ----------------
__global__ void logits_kernel(const float* __restrict__ Psi,
                              float* __restrict__ out_logits) {
    __shared__ float sp[4][DP];
    __shared__ float srawsq[4];
    __shared__ float spsq[4];
    __shared__ float bv[128];
    __shared__ int   bidx[128];

    int tid  = threadIdx.x;
    int w    = tid >> 5;
    int lane = tid & 31;
    int row0 = blockIdx.x * 4;

    const float* src = Psi + (size_t)(row0 + w) * DP;
    float ss = 0.f;
    for (int k = lane; k < DP; k += 32) {
        float v = src[k];
        sp[w][k] = v;
        ss += v * v;
    }
    ss = warpSum(ss);
    if (lane == 0) srawsq[w] = ss;
    __syncthreads();
    {
        float tot = srawsq[w];
        float scl = 1.f / fmaxf(sqrtf(tot), 1e-12f);
        for (int k = lane; k < DP; k += 32) sp[w][k] *= scl;
        if (lane == 0) { spsq[w] = tot * scl * scl; g_Pinv[row0 + w] = scl; }
    }
    __syncthreads();

    float acc0 = 0.f, acc1 = 0.f, acc2 = 0.f, acc3 = 0.f;
    for (int k = 0; k < DP; k++) {
        float c = g_Ct[k * NCLS + tid];
        acc0 = fmaf(sp[0][k], c, acc0);
        acc1 = fmaf(sp[1][k], c, acc1);
        acc2 = fmaf(sp[2][k], c, acc2);
        acc3 = fmaf(sp[3][k], c, acc3);
    }
    float accs[4] = {acc0, acc1, acc2, acc3};
    float cs = g_csq[tid];

    for (int r = 0; r < 4; r++) {
        float logit = -(spsq[r] + cs - 2.f * accs[r]);
        out_logits[(size_t)(row0 + r) * NCLS + tid] = logit;
        bv[tid] = logit;
        bidx[tid] = tid;
        __syncthreads();
        for (int off = 64; off > 0; off >>= 1) {
            if (tid < off) {
                float ov = bv[tid + off];
                int   oi = bidx[tid + off];
                if (ov > bv[tid] || (ov == bv[tid] && oi < bidx[tid])) {
                    bv[tid] = ov; bidx[tid] = oi;
                }
            }
            __syncthreads();
        }
        if (tid == 0) g_assign[row0 + r] = bidx[0];
        __syncthreads();
    }
}

// ---------------- cluster update (validated) ----------------
__global__ void clusterA_kernel(const float* __restrict__ Psi) {
    int z = blockIdx.x;
    int j = blockIdx.y;
    int tid = threadIdx.x;
    __shared__ int   sa[512];
    __shared__ float spv[512];
    sa[tid]  = g_assign[z * 512 + tid];
    spv[tid] = g_Pinv[z * 512 + tid];
    __syncthreads();
    float acc = 0.f;
    int cnt = 0;
    for (int u = 0; u < 512; u++) {
        if (sa[u] == j) { acc += Psi[(size_t)(z * 512 + u) * DP + tid] * spv[u]; cnt++; }
    }
    g_cpart[z][j][tid] = acc;
    if (tid == 0) g_ccnt[z][j] = cnt;
}

__global__ void clusterB_kernel(const float* __restrict__ centers,
                                float* __restrict__ out_centers) {
    int j = blockIdx.x;
    int tid = threadIdx.x;
    float acc = 0.f;
    int cnt = 0;
    for (int z = 0; z < 16; z++) { acc += g_cpart[z][j][tid]; cnt += g_ccnt[z][j]; }
    float denom = fmaxf((float)cnt, 1.f);
    out_centers[j * DP + tid] = centers[j * DP + tid] * 0.9f + (acc / denom) * 0.1f;
}

// ---------------- computeD (fp16 mma16, symmetric) + materialize A fp16 -------
__global__ void __launch_bounds__(256) computeD_sym(const float* __restrict__ FF) {
    __shared__ uint32_t sFi[64][20];   // 16 f16x2 kpairs + pad
    __shared__ uint32_t sFj[64][20];
    __shared__ float srow[64][2];
    __shared__ float scol[4][64];
    __shared__ __half sT[64][72];      // transposed tile for coalesced mirror store

    int tid = threadIdx.x, wid = tid >> 5, lane = tid & 31;
    int g = lane >> 2, t = lane & 3;
    int wm = wid & 3, wn = wid >> 2;   // 4 m-warps x 2 n-warps; warp = m16 x n32

    int bt = blockIdx.x;
    int bi = (int)floorf((sqrtf(8.f * (float)bt + 1.f) - 1.f) * 0.5f);
    while ((bi + 1) * (bi + 2) / 2 <= bt) bi++;
    while (bi * (bi + 1) / 2 > bt) bi--;
    int bj = bt - bi * (bi + 1) / 2;
    int i0 = bi * 64, j0 = bj * 64;

    int ir = tid >> 2, icf = (tid & 3) * 8;   // 8 floats = 4 kpairs per thread
    int icp = (tid & 3) * 4;                  // pair word index
    float fia = g_Finv[i0 + ir];
    float fja = g_Finv[j0 + ir];
    const float* pi = FF + (size_t)(i0 + ir) * DM + icf;
    const float* pj = FF + (size_t)(j0 + ir) * DM + icf;

    float sc[4][4];
#pragma unroll
    for (int n8 = 0; n8 < 4; n8++)
#pragma unroll
        for (int q = 0; q < 4; q++) sc[n8][q] = 0.f;

    float4 Ra0 = *(const float4*)(pi);
    float4 Ra1 = *(const float4*)(pi + 4);
    float4 Rb0 = *(const float4*)(pj);
    float4 Rb1 = *(const float4*)(pj + 4);

    for (int kc = 0; kc < DM; kc += 32) {
        __syncthreads();
        {
            uint4 wa, wb;
            wa.x = ph2(Ra0.x * fia, Ra0.y * fia);
            wa.y = ph2(Ra0.z * fia, Ra0.w * fia);
            wa.z = ph2(Ra1.x * fia, Ra1.y * fia);
            wa.w = ph2(Ra1.z * fia, Ra1.w * fia);
            wb.x = ph2(Rb0.x * fja, Rb0.y * fja);
            wb.y = ph2(Rb0.z * fja, Rb0.w * fja);
            wb.z = ph2(Rb1.x * fja, Rb1.y * fja);
            wb.w = ph2(Rb1.z * fja, Rb1.w * fja);
            *(uint4*)&sFi[ir][icp] = wa;
            *(uint4*)&sFj[ir][icp] = wb;
        }
        if (kc + 32 < DM) {
            Ra0 = *(const float4*)(pi + kc + 32);
            Ra1 = *(const float4*)(pi + kc + 36);
            Rb0 = *(const float4*)(pj + kc + 32);
            Rb1 = *(const float4*)(pj + kc + 36);
        }
        __syncthreads();
#pragma unroll
        for (int kk = 0; kk < 2; kk++) {
            uint32_t a0 = sFi[wm * 16 + g][kk * 8 + t];
            uint32_t a1 = sFi[wm * 16 + g + 8][kk * 8 + t];
            uint32_t a2 = sFi[wm * 16 + g][kk * 8 + t + 4];
            uint32_t a3 = sFi[wm * 16 + g + 8][kk * 8 + t + 4];
#pragma unroll
            for (int n8 = 0; n8 < 4; n8++) {
                uint32_t b0 = sFj[wn * 32 + n8 * 8 + g][kk * 8 + t];
                uint32_t b1 = sFj[wn * 32 + n8 * 8 + g][kk * 8 + t + 4];
                mma16h(sc[n8], a0, a1, a2, a3, b0, b1);
            }
        }
    }

    // clamp + diag; D partials; A stores (direct fp16 + transposed staging)
    uint32_t* Ai = g_A16[i0 >> 10];
    int gi = i0 + wm * 16 + g;
    float r0 = 0.f, r1 = 0.f;
    float ca[4][2];
#pragma unroll
    for (int n8 = 0; n8 < 4; n8++) {
        int col_l = wn * 32 + n8 * 8 + 2 * t;
        int gj = j0 + col_l;
        float v0 = fmaxf(sc[n8][0], 0.f); if (gi == gj)         v0 = 0.f;
        float v1 = fmaxf(sc[n8][1], 0.f); if (gi == gj + 1)     v1 = 0.f;
        float v2 = fmaxf(sc[n8][2], 0.f); if (gi + 8 == gj)     v2 = 0.f;
        float v3 = fmaxf(sc[n8][3], 0.f); if (gi + 8 == gj + 1) v3 = 0.f;
        r0 += v0 + v1;
        r1 += v2 + v3;
        ca[n8][0] = v0 + v2;
        ca[n8][1] = v1 + v3;
        Ai[(size_t)(gi & 1023) * (NR / 2) + (gj >> 1)]       = ph2(v0, v1);
        Ai[(size_t)((gi + 8) & 1023) * (NR / 2) + (gj >> 1)] = ph2(v2, v3);
        int row_l = wm * 16 + g;
        sT[col_l][row_l]         = __float2half(v0);
        sT[col_l + 1][row_l]     = __float2half(v1);
        sT[col_l][row_l + 8]     = __float2half(v2);
        sT[col_l + 1][row_l + 8] = __float2half(v3);
    }
    r0 += __shfl_xor_sync(0xffffffffu, r0, 1);
    r0 += __shfl_xor_sync(0xffffffffu, r0, 2);
    r1 += __shfl_xor_sync(0xffffffffu, r1, 1);
    r1 += __shfl_xor_sync(0xffffffffu, r1, 2);
    if (t == 0) {
        srow[wm * 16 + g][wn]     = r0;
        srow[wm * 16 + g + 8][wn] = r1;
    }
#pragma unroll
    for (int n8 = 0; n8 < 4; n8++) {
#pragma unroll
        for (int h = 0; h < 2; h++) {
            float c = ca[n8][h];
            c += __shfl_xor_sync(0xffffffffu, c, 4);
            c += __shfl_xor_sync(0xffffffffu, c, 8);
            c += __shfl_xor_sync(0xffffffffu, c, 16);
            if (g == 0) scol[wm][wn * 32 + n8 * 8 + 2 * t + h] = c;
        }
    }
    __syncthreads();
    if (tid < 64) {
        g_pD[bj][i0 + tid] = srow[tid][0] + srow[tid][1];
    } else if (tid < 128 && bi != bj) {
        int c = tid - 64;
        g_pD[bi][j0 + c] = scol[0][c] + scol[1][c] + scol[2][c] + scol[3][c];
    }
    // mirror tile coalesced store: A[j0+row][i0 .. i0+63]
    if (bi != bj) {
        uint32_t* Aj = g_A16[j0 >> 10];
        int row = tid >> 2, seg = tid & 3;
        const uint4* srcp = (const uint4*)&sT[row][seg * 16];
        size_t wbase = (size_t)((j0 + row) & 1023) * (NR / 2) + (i0 >> 1) + seg * 8;
        *(uint4*)&Aj[wbase]     = srcp[0];
        *(uint4*)&Aj[wbase + 4] = srcp[1];
    }
}

// ---------------- reduce partials -> Drs ----------------
__global__ void reduceD_kernel() {
    int i = blockIdx.x * 256 + threadIdx.x;
    float s = 0.f;
#pragma unroll 4
    for (int c = 0; c < 128; c++) s += g_pD[c][i];
    g_Drs[i] = rsqrtf(fmaxf(s / (float)(NR - 1), 1e-30f));
}

// ---------------- W16 prep: pack Drs*SCALE*Psi as fp16 kpairs ----------------
__global__ void w16prep_kernel(const float* __restrict__ Psi) {
    int idx = blockIdx.x * 512 + threadIdx.x;
    int p = idx >> 5, seg = idx & 31;
    float w0 = g_Drs[2 * p] * SCALE;
    float w1 = g_Drs[2 * p + 1] * SCALE;
    const float* r0p = Psi + (size_t)(2 * p) * DP + seg * 16;
    const float* r1p = Psi + (size_t)(2 * p + 1) * DP + seg * 16;
    uint32_t* dst = g_W16 + (size_t)p * DP + seg * 16;
#pragma unroll
    for (int q = 0; q < 4; q++) {
        float4 x = *(const float4*)(r0p + q * 4);
        float4 y = *(const float4*)(r1p + q * 4);
        uint4 o;
        o.x = ph2(x.x * w0, y.x * w1);
        o.y = ph2(x.y * w0, y.y * w1);
        o.z = ph2(x.z * w0, y.z * w1);
        o.w = ph2(x.w * w0, y.w * w1);
        *(uint4*)(dst + q * 4) = o;
    }
}

// ---------------- gpsi: fp16 mma, A streamed via cp.async (validated r14) -----
#define WST   (16 * 520)
#define AST   (64 * 20)
#define NCH   (NR / 32)
__global__ void __launch_bounds__(512, 1) gpsi_f16(void) {
    extern __shared__ uint32_t dyn[];
    uint32_t smb = smem_u32(dyn);
    int tid = threadIdx.x, wid = tid >> 5, lane = tid & 31;
    int g = lane >> 2, t = lane & 3;
    int wm = wid & 3, wn = wid >> 2;
    int i0 = blockIdx.x * 64;
    const uint32_t* Abase = g_A16[i0 >> 10] + (size_t)(i0 & 1023) * (NR / 2);

    float gacc[16][4];
#pragma unroll
    for (int f = 0; f < 16; f++)
#pragma unroll
        for (int q = 0; q < 4; q++) gacc[f][q] = 0.f;

    auto issue = [&](int c) {
        int st = c & 3;
        int kt = c * 32;
        {
            int p = tid >> 5, seg = tid & 31;
            uint32_t dst = smb + (st * WST + p * 520 + seg * 16) * 4;
            const uint32_t* src = g_W16 + (size_t)((kt >> 1) + p) * DP + seg * 16;
#pragma unroll
            for (int q = 0; q < 4; q++) CPA16(dst + q * 16, src + q * 4);
        }
        if (tid < 256) {
            int r = tid >> 2, q = tid & 3;
            uint32_t dst = smb + (4 * WST + st * AST + r * 20 + q * 4) * 4;
            const uint32_t* src = Abase + (size_t)r * (NR / 2) + (kt >> 1) + q * 4;
            CPA16(dst, src);
        }
        CPA_COMMIT();
    };

    issue(0); issue(1); issue(2);

    for (int c = 0; c < NCH; c++) {
        if (c + 3 < NCH) issue(c + 3);
        if (c + 3 < NCH)      CPA_WAIT(3);
        else if (c + 2 < NCH) CPA_WAIT(2);
        else if (c + 1 < NCH) CPA_WAIT(1);
        else                  CPA_WAIT(0);
        __syncthreads();

        int st = c & 3;
        const uint32_t* pW = dyn + st * WST;
        const uint32_t* pA = dyn + 4 * WST + st * AST;
#pragma unroll
        for (int s = 0; s < 2; s++) {
            uint32_t a0 = pA[(wm * 16 + g) * 20 + 8 * s + t];
            uint32_t a1 = pA[(wm * 16 + g + 8) * 20 + 8 * s + t];
            uint32_t a2 = pA[(wm * 16 + g) * 20 + 8 * s + t + 4];
            uint32_t a3 = pA[(wm * 16 + g + 8) * 20 + 8 * s + t + 4];
            const uint32_t* rb0 = pW + (8 * s + t) * 520;
            const uint32_t* rb1 = pW + (8 * s + 4 + t) * 520;
#pragma unroll
            for (int n8 = 0; n8 < 16; n8++) {
                int n = wn * 128 + n8 * 8 + g;
                mma16h(gacc[n8], a0, a1, a2, a3, rb0[n], rb1[n]);
            }
        }
        __syncthreads();
    }

    int row = i0 + wm * 16 + g;
    float d0 = g_Drs[row], d1 = g_Drs[row + 8];
#pragma unroll
    for (int n8 = 0; n8 < 16; n8++) {
        int col = wn * 128 + n8 * 8 + 2 * t;
        *(float2*)(g_gPsi + (size_t)row * DP + col) =
            make_float2(d0 * gacc[n8][0], d0 * gacc[n8][1]);
        *(float2*)(g_gPsi + (size_t)(row + 8) * DP + col) =
            make_float2(d1 * gacc[n8][2], d1 * gacc[n8][3]);
    }
}

// ---------------- gemm3: R partials, tf32 (validated) ----------------
__global__ void __launch_bounds__(256) gemm3_tc(const float* __restrict__ Psi) {
    __shared__ uint32_t Xs[64][33];
    __shared__ uint32_t Ys[32][68];

    int tid = threadIdx.x, wid = tid >> 5, lane = tid & 31;
    int g = lane >> 2, t = lane & 3;
    int wm = wid & 3, wn = wid >> 2;
    int b0 = blockIdx.x * 64, a0 = blockIdx.y * 64, z = blockIdx.z;

    int lk = tid >> 3, la8 = (tid & 7) * 8;

    float sc[4][4];
#pragma unroll
    for (int n8 = 0; n8 < 4; n8++)
#pragma unroll
        for (int q = 0; q < 4; q++) sc[n8][q] = 0.f;

    int kbeg = z * (NR / 4);
    const float* px = Psi + (size_t)(kbeg + lk) * DP + a0 + la8;
    const float* py = g_gPsi + (size_t)(kbeg + lk) * DP + b0 + la8;

    float4 X0 = *(const float4*)(px);
    float4 X1 = *(const float4*)(px + 4);
    float4 Y0 = *(const float4*)(py);
    float4 Y1 = *(const float4*)(py + 4);

    for (int k0 = 0; k0 < NR / 4; k0 += 32) {
        __syncthreads();
        Xs[la8 + 0][lk] = f2tf32(X0.x * SCALE); Xs[la8 + 1][lk] = f2tf32(X0.y * SCALE);
        Xs[la8 + 2][lk] = f2tf32(X0.z * SCALE); Xs[la8 + 3][lk] = f2tf32(X0.w * SCALE);
        Xs[la8 + 4][lk] = f2tf32(X1.x * SCALE); Xs[la8 + 5][lk] = f2tf32(X1.y * SCALE);
        Xs[la8 + 6][lk] = f2tf32(X1.z * SCALE); Xs[la8 + 7][lk] = f2tf32(X1.w * SCALE);
        *(uint4*)&Ys[lk][la8]     = cvt4(Y0, 1.f);
        *(uint4*)&Ys[lk][la8 + 4] = cvt4(Y1, 1.f);
        if (k0 + 32 < NR / 4) {
            const float* nx = px + (size_t)(k0 + 32) * DP;
            const float* ny = py + (size_t)(k0 + 32) * DP;
            X0 = *(const float4*)(nx);
            X1 = *(const float4*)(nx + 4);
            Y0 = *(const float4*)(ny);
            Y1 = *(const float4*)(ny + 4);
        }
        __syncthreads();
#pragma unroll
        for (int kk = 0; kk < 4; kk++) {
            uint32_t fa0 = Xs[wm * 16 + g][kk * 8 + t];
            uint32_t fa1 = Xs[wm * 16 + g + 8][kk * 8 + t];
            uint32_t fa2 = Xs[wm * 16 + g][kk * 8 + t + 4];
            uint32_t fa3 = Xs[wm * 16 + g + 8][kk * 8 + t + 4];
#pragma unroll
            for (int n8 = 0; n8 < 4; n8++) {
                uint32_t fb0 = Ys[kk * 8 + t][wn * 32 + n8 * 8 + g];
                uint32_t fb1 = Ys[kk * 8 + t + 4][wn * 32 + n8 * 8 + g];
                mma8(sc[n8], fa0, fa1, fa2, fa3, fb0, fb1);
            }
        }
    }
    int a = a0 + wm * 16 + g;
#pragma unroll
    for (int n8 = 0; n8 < 4; n8++) {
        int b = b0 + wn * 32 + n8 * 8 + 2 * t;
        g_R4[z][a * DP + b]           = sc[n8][0];
        g_R4[z][a * DP + b + 1]       = sc[n8][1];
        g_R4[z][(a + 8) * DP + b]     = sc[n8][2];
        g_R4[z][(a + 8) * DP + b + 1] = sc[n8][3];
    }
}

// ---------------- final: trace + triu reg ----------------
__global__ void final_kernel(float* __restrict__ out2) {
    int b = threadIdx.x;
    float tr = 0.f, rg = 0.f;
    for (int a = 0; a < DP; a++) {
        float s = g_R4[0][a * DP + b] + g_R4[1][a * DP + b]
                + g_R4[2][a * DP + b] + g_R4[3][a * DP + b];
        if (b == a) tr += s;
        else if (b > a) rg += s * s;
    }
    __shared__ float st[DP], sr[DP];
    st[b] = tr; sr[b] = rg;
    __syncthreads();
    if (b == 0) {
        double T = 0.0, R = 0.0;
        for (int i = 0; i < DP; i++) { T += (double)st[i]; R += (double)sr[i]; }
        out2[0] = (float)(-T);
        out2[1] = (float)(R * 0.02);
    }
}

// ---------------- launcher ----------------
extern "C" void kernel_launch(void* const* d_in, const int* in_sizes, int n_in,
                              void* d_out, int out_size) {
    const float* FF  = (const float*)d_in[0];
    const float* Psi = (const float*)d_in[1];
    const float* C   = (const float*)d_in[2];
    float* out = (float*)d_out;

    float* out_logits  = out;
    float* out_centers = out + (size_t)NR * NCLS;
    float* out_scal    = out + (size_t)NR * NCLS + NCLS * DP;

    static cudaStream_t s2 = nullptr;
    static cudaEvent_t evFork = nullptr, evJoin = nullptr;
    if (!s2) {
        cudaStreamCreateWithFlags(&s2, cudaStreamNonBlocking);
        cudaEventCreateWithFlags(&evFork, cudaEventDisableTiming);
        cudaEventCreateWithFlags(&evJoin, cudaEventDisableTiming);
        cudaFuncSetAttribute(gpsi_f16, cudaFuncAttributeMaxDynamicSharedMemorySize,
                             (4 * WST + 4 * AST) * 4);
    }

    cudaEventRecord(evFork, 0);
    cudaStreamWaitEvent(s2, evFork, 0);

    prep_centers_kernel<<<NCLS, DP, 0, s2>>>(C);
    logits_kernel<<<NR / 4, 128, 0, s2>>>(Psi, out_logits);
    clusterA_kernel<<<dim3(16, NCLS), 512, 0, s2>>>(Psi);
    clusterB_kernel<<<NCLS, DP, 0, s2>>>(C, out_centers);
    cudaEventRecord(evJoin, s2);

    finv_kernel<<<NR / 8, 256>>>(FF);
    computeD_sym<<<(NR / 64) * (NR / 64 + 1) / 2, 256>>>(FF);
    reduceD_kernel<<<NR / 256, 256>>>();
    w16prep_kernel<<<(NR / 2) * (DP / 16) / 512, 512>>>(Psi);
    gpsi_f16<<<NR / 64, 512, (4 * WST + 4 * AST) * 4>>>();
    gemm3_tc<<<dim3(DP / 64, DP / 64, 4), 256>>>(Psi);
    final_kernel<<<1, DP>>>(out_scal);

    cudaStreamWaitEvent(0, evJoin, 0);
}

// round 16
// speedup vs baseline: 14.8199x; 1.1655x over previous
#include <cuda_runtime.h>
#include <cuda_fp16.h>
#include <math.h>
#include <stdint.h>

#define NR     8192
#define DM     768
#define DP     512
#define NCLS   128
#define SCALE  (10.f / 8192.f)

// ---------------- scratch ----------------
__device__ float g_Pinv[NR];
__device__ float g_Finv[NR];
__device__ float g_Drs[NR];
__device__ float g_pD[128][NR];
__device__ float g_gPsi[NR * DP];
__device__ float g_Ct[DP * NCLS];
__device__ float g_csq[NCLS];
__device__ int   g_assign[NR];
__device__ float g_R4[4][DP * DP];
__device__ float g_fin[16][DP][2];
__device__ float g_cpart[16][NCLS][DP];
__device__ int   g_ccnt[16][NCLS];
// FFn in fp16 kpair-packed (row-major halves): [row][DM/2 words]
__device__ uint32_t g_F16[NR * (DM / 2)];
// A in fp16 (packed half2 words, row-major), split into 8 x 16MB objects
__device__ uint32_t g_A16[8][1024 * (NR / 2)];
// W = Drs*SCALE*Psi in fp16 kpair-packed: [kpair(4096)][n(512)]
__device__ uint32_t g_W16[(NR / 2) * DP];

__device__ __forceinline__ float warpSum(float v) {
#pragma unroll
    for (int o = 16; o > 0; o >>= 1) v += __shfl_down_sync(0xffffffffu, v, o);
    return v;
}
__device__ __forceinline__ uint32_t f2tf32(float x) {
    uint32_t y;
    asm("cvt.rna.tf32.f32 %0, %1;" : "=r"(y) : "f"(x));
    return y;
}
__device__ __forceinline__ uint4 cvt4(float4 v, float s) {
    uint4 u;
    u.x = f2tf32(v.x * s); u.y = f2tf32(v.y * s);
    u.z = f2tf32(v.z * s); u.w = f2tf32(v.w * s);
    return u;
}
__device__ __forceinline__ uint32_t ph2(float lo, float hi) {
    uint32_t d;
    asm("cvt.rn.f16x2.f32 %0, %1, %2;" : "=r"(d) : "f"(hi), "f"(lo));
    return d;
}
__device__ __forceinline__ void mma8(float* c,
                                     uint32_t a0, uint32_t a1, uint32_t a2, uint32_t a3,
                                     uint32_t b0, uint32_t b1) {
    asm volatile(
        "mma.sync.aligned.m16n8k8.row.col.f32.tf32.tf32.f32 "
        "{%0,%1,%2,%3}, {%4,%5,%6,%7}, {%8,%9}, {%0,%1,%2,%3};\n"
        : "+f"(c[0]), "+f"(c[1]), "+f"(c[2]), "+f"(c[3])
        : "r"(a0), "r"(a1), "r"(a2), "r"(a3), "r"(b0), "r"(b1));
}
__device__ __forceinline__ void mma16h(float* c,
                                       uint32_t a0, uint32_t a1, uint32_t a2, uint32_t a3,
                                       uint32_t b0, uint32_t b1) {
    asm volatile(
        "mma.sync.aligned.m16n8k16.row.col.f32.f16.f16.f32 "
        "{%0,%1,%2,%3}, {%4,%5,%6,%7}, {%8,%9}, {%0,%1,%2,%3};\n"
        : "+f"(c[0]), "+f"(c[1]), "+f"(c[2]), "+f"(c[3])
        : "r"(a0), "r"(a1), "r"(a2), "r"(a3), "r"(b0), "r"(b1));
}
#define CPA16(dst, src)  asm volatile("cp.async.cg.shared.global [%0], [%1], 16;" :: "r"(dst), "l"(src) : "memory")
#define CPA_COMMIT()     asm volatile("cp.async.commit_group;" ::: "memory")
#define CPA_WAIT(n)      asm volatile("cp.async.wait_group %0;" :: "n"(n) : "memory")
__device__ __forceinline__ uint32_t smem_u32(const void* p) {
    uint32_t a;
    asm("{ .reg .u64 t; cvta.to.shared.u64 t, %1; cvt.u32.u64 %0, t; }" : "=r"(a) : "l"(p));
    return a;
}

// ---------------- FF row inverse norms ----------------
__global__ void finv_kernel(const float* __restrict__ FF) {
    int row  = blockIdx.x * 8 + (threadIdx.x >> 5);
    int lane = threadIdx.x & 31;
    const float* x = FF + (size_t)row * DM;
    float s = 0.f;
    for (int k = lane; k < DM; k += 32) { float v = x[k]; s += v * v; }
    s = warpSum(s);
    if (lane == 0) g_Finv[row] = 1.f / fmaxf(sqrtf(s), 1e-12f);
}

// ---------------- FFn -> fp16 kpair pack (normalized) ----------------
__global__ void f16prep_kernel(const float* __restrict__ FF) {
    int idx = blockIdx.x * 256 + threadIdx.x;   // word groups of 4
    int w0 = idx * 4;
    int row = w0 / (DM / 2);
    float fia = g_Finv[row];
    const float* src = FF + (size_t)w0 * 2;
    float4 x0 = *(const float4*)(src);
    float4 x1 = *(const float4*)(src + 4);
    uint4 o;
    o.x = ph2(x0.x * fia, x0.y * fia);
    o.y = ph2(x0.z * fia, x0.w * fia);
    o.z = ph2(x1.x * fia, x1.y * fia);
    o.w = ph2(x1.z * fia, x1.w * fia);
    *(uint4*)(g_F16 + w0) = o;
}

// ---------------- centers prep (validated) ----------------
__global__ void prep_centers_kernel(const float* __restrict__ C) {
    int j = blockIdx.x;
    int k = threadIdx.x;
    float v = C[j * DP + k];
    g_Ct[k * NCLS + j] = v;
    float s = v * v;
    __shared__ float sh[16];
    int lane = k & 31, wid = k >> 5;
    s = warpSum(s);
    if (lane == 0) sh[wid] = s;
    __syncthreads();
    if (k == 0) {
        float t = 0.f;
        for (int w = 0; w < 16; w++) t += sh[w];
        g_csq[j] = t;
    }
}

// ---------------- logits + argmax (validated) ----------------
__global__ void logits_kernel(const float* __restrict__ Psi,
                              float* __restrict__ out_logits) {
    __shared__ float sp[4][DP];
    __shared__ float srawsq[4];
    __shared__ float spsq[4];
    __shared__ float bv[128];
    __shared__ int   bidx[128];

    int tid  = threadIdx.x;
    int w    = tid >> 5;
    int lane = tid & 31;
    int row0 = blockIdx.x * 4;

    const float* src = Psi + (size_t)(row0 + w) * DP;
    float ss = 0.f;
    for (int k = lane; k < DP; k += 32) {
        float v = src[k];
        sp[w][k] = v;
        ss += v * v;
    }
    ss = warpSum(ss);
    if (lane == 0) srawsq[w] = ss;
    __syncthreads();
    {
        float tot = srawsq[w];
        float scl = 1.f / fmaxf(sqrtf(tot), 1e-12f);
        for (int k = lane; k < DP; k += 32) sp[w][k] *= scl;
        if (lane == 0) { spsq[w] = tot * scl * scl; g_Pinv[row0 + w] = scl; }
    }
    __syncthreads();

    float acc0 = 0.f, acc1 = 0.f, acc2 = 0.f, acc3 = 0.f;
    for (int k = 0; k < DP; k++) {
        float c = g_Ct[k * NCLS + tid];
        acc0 = fmaf(sp[0][k], c, acc0);
        acc1 = fmaf(sp[1][k], c, acc1);
        acc2 = fmaf(sp[2][k], c, acc2);
        acc3 = fmaf(sp[3][k], c, acc3);
    }
    float accs[4] = {acc0, acc1, acc2, acc3};
    float cs = g_csq[tid];

    for (int r = 0; r < 4; r++) {
        float logit = -(spsq[r] + cs - 2.f * accs[r]);
        out_logits[(size_t)(row0 + r) * NCLS + tid] = logit;
        bv[tid] = logit;
        bidx[tid] = tid;
        __syncthreads();
        for (int off = 64; off > 0; off >>= 1) {
            if (tid < off) {
                float ov = bv[tid + off];
                int   oi = bidx[tid + off];
                if (ov > bv[tid] || (ov == bv[tid] && oi < bidx[tid])) {
                    bv[tid] = ov; bidx[tid] = oi;
                }
            }
            __syncthreads();
        }
        if (tid == 0) g_assign[row0 + r] = bidx[0];
        __syncthreads();
    }
}

// ---------------- cluster update (validated) ----------------
__global__ void clusterA_kernel(const float* __restrict__ Psi) {
    int z = blockIdx.x;
    int j = blockIdx.y;
    int tid = threadIdx.x;
    __shared__ int   sa[512];
    __shared__ float spv[512];
    sa[tid]  = g_assign[z * 512 + tid];
    spv[tid] = g_Pinv[z * 512 + tid];
    __syncthreads();
    float acc = 0.f;
    int cnt = 0;
    for (int u = 0; u < 512; u++) {
        if (sa[u] == j) { acc += Psi[(size_t)(z * 512 + u) * DP + tid] * spv[u]; cnt++; }
    }
    g_cpart[z][j][tid] = acc;
    if (tid == 0) g_ccnt[z][j] = cnt;
}

__global__ void clusterB_kernel(const float* __restrict__ centers,
                                float* __restrict__ out_centers) {
    int j = blockIdx.x;
    int tid = threadIdx.x;
    float acc = 0.f;
    int cnt = 0;
    for (int z = 0; z < 16; z++) { acc += g_cpart[z][j][tid]; cnt += g_ccnt[z][j]; }
    float denom = fmaxf((float)cnt, 1.f);
    out_centers[j * DP + tid] = centers[j * DP + tid] * 0.9f + (acc / denom) * 0.1f;
}

// ---------------- computeD: fp16 streamed (cp.async) + A materialization ------
#define FST (64 * 20)
#define DCH (DM / 32)          // 24 chunks
__global__ void __launch_bounds__(256) computeD_f16(void) {
    extern __shared__ uint32_t dynD[];
    __shared__ float srow[64][2];
    __shared__ float scol[4][64];
    __shared__ __half sT[64][72];

    uint32_t smb = smem_u32(dynD);
    int tid = threadIdx.x, wid = tid >> 5, lane = tid & 31;
    int g = lane >> 2, t = lane & 3;
    int wm = wid & 3, wn = wid >> 2;

    int bt = blockIdx.x;
    int bi = (int)floorf((sqrtf(8.f * (float)bt + 1.f) - 1.f) * 0.5f);
    while ((bi + 1) * (bi + 2) / 2 <= bt) bi++;
    while (bi * (bi + 1) / 2 > bt) bi--;
    int bj = bt - bi * (bi + 1) / 2;
    int i0 = bi * 64, j0 = bj * 64;

    const uint32_t* Fi = g_F16 + (size_t)i0 * (DM / 2);
    const uint32_t* Fj = g_F16 + (size_t)j0 * (DM / 2);

    float sc[4][4];
#pragma unroll
    for (int n8 = 0; n8 < 4; n8++)
#pragma unroll
        for (int q = 0; q < 4; q++) sc[n8][q] = 0.f;

    int r = tid >> 2, q = tid & 3;
    auto issueD = [&](int c) {
        int st = c & 3;
        CPA16(smb + (st * 2 * FST + r * 20 + q * 4) * 4,
              Fi + (size_t)r * (DM / 2) + c * 16 + q * 4);
        CPA16(smb + (st * 2 * FST + FST + r * 20 + q * 4) * 4,
              Fj + (size_t)r * (DM / 2) + c * 16 + q * 4);
        CPA_COMMIT();
    };

    issueD(0); issueD(1); issueD(2);

    for (int c = 0; c < DCH; c++) {
        if (c + 3 < DCH) issueD(c + 3);
        if (c + 3 < DCH)      CPA_WAIT(3);
        else if (c + 2 < DCH) CPA_WAIT(2);
        else if (c + 1 < DCH) CPA_WAIT(1);
        else                  CPA_WAIT(0);
        __syncthreads();

        const uint32_t* pFi = dynD + (c & 3) * 2 * FST;
        const uint32_t* pFj = pFi + FST;
#pragma unroll
        for (int kk = 0; kk < 2; kk++) {
            uint32_t a0 = pFi[(wm * 16 + g) * 20 + kk * 8 + t];
            uint32_t a1 = pFi[(wm * 16 + g + 8) * 20 + kk * 8 + t];
            uint32_t a2 = pFi[(wm * 16 + g) * 20 + kk * 8 + t + 4];
            uint32_t a3 = pFi[(wm * 16 + g + 8) * 20 + kk * 8 + t + 4];
#pragma unroll
            for (int n8 = 0; n8 < 4; n8++) {
                uint32_t b0 = pFj[(wn * 32 + n8 * 8 + g) * 20 + kk * 8 + t];
                uint32_t b1 = pFj[(wn * 32 + n8 * 8 + g) * 20 + kk * 8 + t + 4];
                mma16h(sc[n8], a0, a1, a2, a3, b0, b1);
            }
        }
        __syncthreads();
    }

    // epilogue: clamp + diag; D partials; A stores (validated r15)
    uint32_t* Ai = g_A16[i0 >> 10];
    int gi = i0 + wm * 16 + g;
    float r0 = 0.f, r1 = 0.f;
    float ca[4][2];
#pragma unroll
    for (int n8 = 0; n8 < 4; n8++) {
        int col_l = wn * 32 + n8 * 8 + 2 * t;
        int gj = j0 + col_l;
        float v0 = fmaxf(sc[n8][0], 0.f); if (gi == gj)         v0 = 0.f;
        float v1 = fmaxf(sc[n8][1], 0.f); if (gi == gj + 1)     v1 = 0.f;
        float v2 = fmaxf(sc[n8][2], 0.f); if (gi + 8 == gj)     v2 = 0.f;
        float v3 = fmaxf(sc[n8][3], 0.f); if (gi + 8 == gj + 1) v3 = 0.f;
        r0 += v0 + v1;
        r1 += v2 + v3;
        ca[n8][0] = v0 + v2;
        ca[n8][1] = v1 + v3;
        Ai[(size_t)(gi & 1023) * (NR / 2) + (gj >> 1)]       = ph2(v0, v1);
        Ai[(size_t)((gi + 8) & 1023) * (NR / 2) + (gj >> 1)] = ph2(v2, v3);
        int row_l = wm * 16 + g;
        sT[col_l][row_l]         = __float2half(v0);
        sT[col_l + 1][row_l]     = __float2half(v1);
        sT[col_l][row_l + 8]     = __float2half(v2);
        sT[col_l + 1][row_l + 8] = __float2half(v3);
    }
    r0 += __shfl_xor_sync(0xffffffffu, r0, 1);
    r0 += __shfl_xor_sync(0xffffffffu, r0, 2);
    r1 += __shfl_xor_sync(0xffffffffu, r1, 1);
    r1 += __shfl_xor_sync(0xffffffffu, r1, 2);
    if (t == 0) {
        srow[wm * 16 + g][wn]     = r0;
        srow[wm * 16 + g + 8][wn] = r1;
    }
#pragma unroll
    for (int n8 = 0; n8 < 4; n8++) {
#pragma unroll
        for (int h = 0; h < 2; h++) {
            float c = ca[n8][h];
            c += __shfl_xor_sync(0xffffffffu, c, 4);
            c += __shfl_xor_sync(0xffffffffu, c, 8);
            c += __shfl_xor_sync(0xffffffffu, c, 16);
            if (g == 0) scol[wm][wn * 32 + n8 * 8 + 2 * t + h] = c;
        }
    }
    __syncthreads();
    if (tid < 64) {
        g_pD[bj][i0 + tid] = srow[tid][0] + srow[tid][1];
    } else if (tid < 128 && bi != bj) {
        int c = tid - 64;
        g_pD[bi][j0 + c] = scol[0][c] + scol[1][c] + scol[2][c] + scol[3][c];
    }
    if (bi != bj) {
        uint32_t* Aj = g_A16[j0 >> 10];
        int row = tid >> 2, seg = tid & 3;
        const uint4* srcp = (const uint4*)&sT[row][seg * 16];
        size_t wbase = (size_t)((j0 + row) & 1023) * (NR / 2) + (i0 >> 1) + seg * 8;
        *(uint4*)&Aj[wbase]     = srcp[0];
        *(uint4*)&Aj[wbase + 4] = srcp[1];
    }
}

// ---------------- reduce partials -> Drs ----------------
__global__ void reduceD_kernel() {
    int i = blockIdx.x * 256 + threadIdx.x;
    float s = 0.f;
#pragma unroll 4
    for (int c = 0; c < 128; c++) s += g_pD[c][i];
    g_Drs[i] = rsqrtf(fmaxf(s / (float)(NR - 1), 1e-30f));
}

// ---------------- W16 prep ----------------
__global__ void w16prep_kernel(const float* __restrict__ Psi) {
    int idx = blockIdx.x * 512 + threadIdx.x;
    int p = idx >> 5, seg = idx & 31;
    float w0 = g_Drs[2 * p] * SCALE;
    float w1 = g_Drs[2 * p + 1] * SCALE;
    const float* r0p = Psi + (size_t)(2 * p) * DP + seg * 16;
    const float* r1p = Psi + (size_t)(2 * p + 1) * DP + seg * 16;
    uint32_t* dst = g_W16 + (size_t)p * DP + seg * 16;
#pragma unroll
    for (int q = 0; q < 4; q++) {
        float4 x = *(const float4*)(r0p + q * 4);
        float4 y = *(const float4*)(r1p + q * 4);
        uint4 o;
        o.x = ph2(x.x * w0, y.x * w1);
        o.y = ph2(x.y * w0, y.y * w1);
        o.z = ph2(x.z * w0, y.z * w1);
        o.w = ph2(x.w * w0, y.w * w1);
        *(uint4*)(dst + q * 4) = o;
    }
}

// ---------------- gpsi: fp16 mma, A streamed via cp.async (validated r14) -----
#define WST   (16 * 520)
#define AST   (64 * 20)
#define NCH   (NR / 32)
__global__ void __launch_bounds__(512, 1) gpsi_f16(void) {
    extern __shared__ uint32_t dyn[];
    uint32_t smb = smem_u32(dyn);
    int tid = threadIdx.x, wid = tid >> 5, lane = tid & 31;
    int g = lane >> 2, t = lane & 3;
    int wm = wid & 3, wn = wid >> 2;
    int i0 = blockIdx.x * 64;
    const uint32_t* Abase = g_A16[i0 >> 10] + (size_t)(i0 & 1023) * (NR / 2);

    float gacc[16][4];
#pragma unroll
    for (int f = 0; f < 16; f++)
#pragma unroll
        for (int q = 0; q < 4; q++) gacc[f][q] = 0.f;

    auto issue = [&](int c) {
        int st = c & 3;
        int kt = c * 32;
        {
            int p = tid >> 5, seg = tid & 31;
            uint32_t dst = smb + (st * WST + p * 520 + seg * 16) * 4;
            const uint32_t* src = g_W16 + (size_t)((kt >> 1) + p) * DP + seg * 16;
#pragma unroll
            for (int q = 0; q < 4; q++) CPA16(dst + q * 16, src + q * 4);
        }
        if (tid < 256) {
            int r = tid >> 2, q = tid & 3;
            uint32_t dst = smb + (4 * WST + st * AST + r * 20 + q * 4) * 4;
            const uint32_t* src = Abase + (size_t)r * (NR / 2) + (kt >> 1) + q * 4;
            CPA16(dst, src);
        }
        CPA_COMMIT();
    };

    issue(0); issue(1); issue(2);

    for (int c = 0; c < NCH; c++) {
        if (c + 3 < NCH) issue(c + 3);
        if (c + 3 < NCH)      CPA_WAIT(3);
        else if (c + 2 < NCH) CPA_WAIT(2);
        else if (c + 1 < NCH) CPA_WAIT(1);
        else                  CPA_WAIT(0);
        __syncthreads();

        int st = c & 3;
        const uint32_t* pW = dyn + st * WST;
        const uint32_t* pA = dyn + 4 * WST + st * AST;
#pragma unroll
        for (int s = 0; s < 2; s++) {
            uint32_t a0 = pA[(wm * 16 + g) * 20 + 8 * s + t];
            uint32_t a1 = pA[(wm * 16 + g + 8) * 20 + 8 * s + t];
            uint32_t a2 = pA[(wm * 16 + g) * 20 + 8 * s + t + 4];
            uint32_t a3 = pA[(wm * 16 + g + 8) * 20 + 8 * s + t + 4];
            const uint32_t* rb0 = pW + (8 * s + t) * 520;
            const uint32_t* rb1 = pW + (8 * s + 4 + t) * 520;
#pragma unroll
            for (int n8 = 0; n8 < 16; n8++) {
                int n = wn * 128 + n8 * 8 + g;
                mma16h(gacc[n8], a0, a1, a2, a3, rb0[n], rb1[n]);
            }
        }
        __syncthreads();
    }

    int row = i0 + wm * 16 + g;
    float d0 = g_Drs[row], d1 = g_Drs[row + 8];
#pragma unroll
    for (int n8 = 0; n8 < 16; n8++) {
        int col = wn * 128 + n8 * 8 + 2 * t;
        *(float2*)(g_gPsi + (size_t)row * DP + col) =
            make_float2(d0 * gacc[n8][0], d0 * gacc[n8][1]);
        *(float2*)(g_gPsi + (size_t)(row + 8) * DP + col) =
            make_float2(d1 * gacc[n8][2], d1 * gacc[n8][3]);
    }
}

// ---------------- gemm3: R partials, tf32 (validated) ----------------
__global__ void __launch_bounds__(256) gemm3_tc(const float* __restrict__ Psi) {
    __shared__ uint32_t Xs[64][33];
    __shared__ uint32_t Ys[32][68];

    int tid = threadIdx.x, wid = tid >> 5, lane = tid & 31;
    int g = lane >> 2, t = lane & 3;
    int wm = wid & 3, wn = wid >> 2;
    int b0 = blockIdx.x * 64, a0 = blockIdx.y * 64, z = blockIdx.z;

    int lk = tid >> 3, la8 = (tid & 7) * 8;

    float sc[4][4];
#pragma unroll
    for (int n8 = 0; n8 < 4; n8++)
#pragma unroll
        for (int q = 0; q < 4; q++) sc[n8][q] = 0.f;

    int kbeg = z * (NR / 4);
    const float* px = Psi + (size_t)(kbeg + lk) * DP + a0 + la8;
    const float* py = g_gPsi + (size_t)(kbeg + lk) * DP + b0 + la8;

    float4 X0 = *(const float4*)(px);
    float4 X1 = *(const float4*)(px + 4);
    float4 Y0 = *(const float4*)(py);
    float4 Y1 = *(const float4*)(py + 4);

    for (int k0 = 0; k0 < NR / 4; k0 += 32) {
        __syncthreads();
        Xs[la8 + 0][lk] = f2tf32(X0.x * SCALE); Xs[la8 + 1][lk] = f2tf32(X0.y * SCALE);
        Xs[la8 + 2][lk] = f2tf32(X0.z * SCALE); Xs[la8 + 3][lk] = f2tf32(X0.w * SCALE);
        Xs[la8 + 4][lk] = f2tf32(X1.x * SCALE); Xs[la8 + 5][lk] = f2tf32(X1.y * SCALE);
        Xs[la8 + 6][lk] = f2tf32(X1.z * SCALE); Xs[la8 + 7][lk] = f2tf32(X1.w * SCALE);
        *(uint4*)&Ys[lk][la8]     = cvt4(Y0, 1.f);
        *(uint4*)&Ys[lk][la8 + 4] = cvt4(Y1, 1.f);
        if (k0 + 32 < NR / 4) {
            const float* nx = px + (size_t)(k0 + 32) * DP;
            const float* ny = py + (size_t)(k0 + 32) * DP;
            X0 = *(const float4*)(nx);
            X1 = *(const float4*)(nx + 4);
            Y0 = *(const float4*)(ny);
            Y1 = *(const float4*)(ny + 4);
        }
        __syncthreads();
#pragma unroll
        for (int kk = 0; kk < 4; kk++) {
            uint32_t fa0 = Xs[wm * 16 + g][kk * 8 + t];
            uint32_t fa1 = Xs[wm * 16 + g + 8][kk * 8 + t];
            uint32_t fa2 = Xs[wm * 16 + g][kk * 8 + t + 4];
            uint32_t fa3 = Xs[wm * 16 + g + 8][kk * 8 + t + 4];
#pragma unroll
            for (int n8 = 0; n8 < 4; n8++) {
                uint32_t fb0 = Ys[kk * 8 + t][wn * 32 + n8 * 8 + g];
                uint32_t fb1 = Ys[kk * 8 + t + 4][wn * 32 + n8 * 8 + g];
                mma8(sc[n8], fa0, fa1, fa2, fa3, fb0, fb1);
            }
        }
    }
    int a = a0 + wm * 16 + g;
#pragma unroll
    for (int n8 = 0; n8 < 4; n8++) {
        int b = b0 + wn * 32 + n8 * 8 + 2 * t;
        g_R4[z][a * DP + b]           = sc[n8][0];
        g_R4[z][a * DP + b + 1]       = sc[n8][1];
        g_R4[z][(a + 8) * DP + b]     = sc[n8][2];
        g_R4[z][(a + 8) * DP + b + 1] = sc[n8][3];
    }
}

// ---------------- final: parallel trace + triu reg ----------------
__global__ void final1_kernel() {
    int b = threadIdx.x;       // 512
    int z = blockIdx.x;        // 16 row strips of 32
    float tr = 0.f, rg = 0.f;
    for (int a = z * 32; a < z * 32 + 32; a++) {
        float s = g_R4[0][a * DP + b] + g_R4[1][a * DP + b]
                + g_R4[2][a * DP + b] + g_R4[3][a * DP + b];
        if (b == a) tr += s;
        else if (b > a) rg += s * s;
    }
    g_fin[z][b][0] = tr;
    g_fin[z][b][1] = rg;
}

__global__ void final2_kernel(float* __restrict__ out2) {
    int b = threadIdx.x;       // 512
    float tr = 0.f, rg = 0.f;
#pragma unroll
    for (int z = 0; z < 16; z++) { tr += g_fin[z][b][0]; rg += g_fin[z][b][1]; }
    __shared__ float st[DP], sr[DP];
    st[b] = tr; sr[b] = rg;
    __syncthreads();
    if (b == 0) {
        double T = 0.0, R = 0.0;
        for (int i = 0; i < DP; i++) { T += (double)st[i]; R += (double)sr[i]; }
        out2[0] = (float)(-T);
        out2[1] = (float)(R * 0.02);
    }
}

// ---------------- launcher ----------------
extern "C" void kernel_launch(void* const* d_in, const int* in_sizes, int n_in,
                              void* d_out, int out_size) {
    const float* FF  = (const float*)d_in[0];
    const float* Psi = (const float*)d_in[1];
    const float* C   = (const float*)d_in[2];
    float* out = (float*)d_out;

    float* out_logits  = out;
    float* out_centers = out + (size_t)NR * NCLS;
    float* out_scal    = out + (size_t)NR * NCLS + NCLS * DP;

    static cudaStream_t s2 = nullptr;
    static cudaEvent_t evFork = nullptr, evJoin = nullptr;
    if (!s2) {
        cudaStreamCreateWithFlags(&s2, cudaStreamNonBlocking);
        cudaEventCreateWithFlags(&evFork, cudaEventDisableTiming);
        cudaEventCreateWithFlags(&evJoin, cudaEventDisableTiming);
        cudaFuncSetAttribute(gpsi_f16, cudaFuncAttributeMaxDynamicSharedMemorySize,
                             (4 * WST + 4 * AST) * 4);
        cudaFuncSetAttribute(computeD_f16, cudaFuncAttributeMaxDynamicSharedMemorySize,
                             4 * 2 * FST * 4);
    }

    cudaEventRecord(evFork, 0);
    cudaStreamWaitEvent(s2, evFork, 0);

    prep_centers_kernel<<<NCLS, DP, 0, s2>>>(C);
    logits_kernel<<<NR / 4, 128, 0, s2>>>(Psi, out_logits);
    clusterA_kernel<<<dim3(16, NCLS), 512, 0, s2>>>(Psi);
    clusterB_kernel<<<NCLS, DP, 0, s2>>>(C, out_centers);
    cudaEventRecord(evJoin, s2);

    finv_kernel<<<NR / 8, 256>>>(FF);
    f16prep_kernel<<<NR * (DM / 2) / 4 / 256, 256>>>(FF);
    computeD_f16<<<(NR / 64) * (NR / 64 + 1) / 2, 256, 4 * 2 * FST * 4>>>();
    reduceD_kernel<<<NR / 256, 256>>>();
    w16prep_kernel<<<(NR / 2) * (DP / 16) / 512, 512>>>(Psi);
    gpsi_f16<<<NR / 64, 512, (4 * WST + 4 * AST) * 4>>>();
    gemm3_tc<<<dim3(DP / 64, DP / 64, 4), 256>>>(Psi);
    final1_kernel<<<16, DP>>>();
    final2_kernel<<<1, DP>>>(out_scal);

    cudaStreamWaitEvent(0, evJoin, 0);
}

// round 17
// speedup vs baseline: 15.3951x; 1.0388x over previous
#include <cuda_runtime.h>
#include <cuda_fp16.h>
#include <math.h>
#include <stdint.h>

#define NR     8192
#define DM     768
#define DP     512
#define NCLS   128
#define SCALE  (10.f / 8192.f)

// ---------------- scratch ----------------
__device__ float g_Pinv[NR];
__device__ float g_Finv[NR];
__device__ float g_Drs[NR];
__device__ float g_pD[64][NR];
__device__ float g_gPsi[NR * DP];
__device__ float g_Ct[DP * NCLS];
__device__ float g_csq[NCLS];
__device__ int   g_assign[NR];
__device__ float g_R4[4][DP * DP];
__device__ float g_fin[16][DP][2];
__device__ float g_cpart[16][NCLS][DP];
__device__ int   g_ccnt[16][NCLS];
__device__ uint32_t g_F16[NR * (DM / 2)];
__device__ uint32_t g_A16[8][1024 * (NR / 2)];
__device__ uint32_t g_W16[(NR / 2) * DP];

__device__ __forceinline__ float warpSum(float v) {
#pragma unroll
    for (int o = 16; o > 0; o >>= 1) v += __shfl_down_sync(0xffffffffu, v, o);
    return v;
}
__device__ __forceinline__ uint32_t f2tf32(float x) {
    uint32_t y;
    asm("cvt.rna.tf32.f32 %0, %1;" : "=r"(y) : "f"(x));
    return y;
}
__device__ __forceinline__ uint4 cvt4(float4 v, float s) {
    uint4 u;
    u.x = f2tf32(v.x * s); u.y = f2tf32(v.y * s);
    u.z = f2tf32(v.z * s); u.w = f2tf32(v.w * s);
    return u;
}
__device__ __forceinline__ uint32_t ph2(float lo, float hi) {
    uint32_t d;
    asm("cvt.rn.f16x2.f32 %0, %1, %2;" : "=r"(d) : "f"(hi), "f"(lo));
    return d;
}
__device__ __forceinline__ void mma8(float* c,
                                     uint32_t a0, uint32_t a1, uint32_t a2, uint32_t a3,
                                     uint32_t b0, uint32_t b1) {
    asm volatile(
        "mma.sync.aligned.m16n8k8.row.col.f32.tf32.tf32.f32 "
        "{%0,%1,%2,%3}, {%4,%5,%6,%7}, {%8,%9}, {%0,%1,%2,%3};\n"
        : "+f"(c[0]), "+f"(c[1]), "+f"(c[2]), "+f"(c[3])
        : "r"(a0), "r"(a1), "r"(a2), "r"(a3), "r"(b0), "r"(b1));
}
__device__ __forceinline__ void mma16h(float* c,
                                       uint32_t a0, uint32_t a1, uint32_t a2, uint32_t a3,
                                       uint32_t b0, uint32_t b1) {
    asm volatile(
        "mma.sync.aligned.m16n8k16.row.col.f32.f16.f16.f32 "
        "{%0,%1,%2,%3}, {%4,%5,%6,%7}, {%8,%9}, {%0,%1,%2,%3};\n"
        : "+f"(c[0]), "+f"(c[1]), "+f"(c[2]), "+f"(c[3])
        : "r"(a0), "r"(a1), "r"(a2), "r"(a3), "r"(b0), "r"(b1));
}
#define CPA16(dst, src)  asm volatile("cp.async.cg.shared.global [%0], [%1], 16;" :: "r"(dst), "l"(src) : "memory")
#define CPA_COMMIT()     asm volatile("cp.async.commit_group;" ::: "memory")
#define CPA_WAIT(n)      asm volatile("cp.async.wait_group %0;" :: "n"(n) : "memory")
__device__ __forceinline__ uint32_t smem_u32(const void* p) {
    uint32_t a;
    asm("{ .reg .u64 t; cvta.to.shared.u64 t, %1; cvt.u32.u64 %0, t; }" : "=r"(a) : "l"(p));
    return a;
}

// ---------------- FF row inverse norms ----------------
__global__ void finv_kernel(const float* __restrict__ FF) {
    int row  = blockIdx.x * 8 + (threadIdx.x >> 5);
    int lane = threadIdx.x & 31;
    const float* x = FF + (size_t)row * DM;
    float s = 0.f;
    for (int k = lane; k < DM; k += 32) { float v = x[k]; s += v * v; }
    s = warpSum(s);
    if (lane == 0) g_Finv[row] = 1.f / fmaxf(sqrtf(s), 1e-12f);
}

// ---------------- FFn -> fp16 kpair pack ----------------
__global__ void f16prep_kernel(const float* __restrict__ FF) {
    int idx = blockIdx.x * 256 + threadIdx.x;
    int w0 = idx * 4;
    int row = w0 / (DM / 2);
    float fia = g_Finv[row];
    const float* src = FF + (size_t)w0 * 2;
    float4 x0 = *(const float4*)(src);
    float4 x1 = *(const float4*)(src + 4);
    uint4 o;
    o.x = ph2(x0.x * fia, x0.y * fia);
    o.y = ph2(x0.z * fia, x0.w * fia);
    o.z = ph2(x1.x * fia, x1.y * fia);
    o.w = ph2(x1.z * fia, x1.w * fia);
    *(uint4*)(g_F16 + w0) = o;
}

// ---------------- centers prep (validated) ----------------
__global__ void prep_centers_kernel(const float* __restrict__ C) {
    int j = blockIdx.x;
    int k = threadIdx.x;
    float v = C[j * DP + k];
    g_Ct[k * NCLS + j] = v;
    float s = v * v;
    __shared__ float sh[16];
    int lane = k & 31, wid = k >> 5;
    s = warpSum(s);
    if (lane == 0) sh[wid] = s;
    __syncthreads();
    if (k == 0) {
        float t = 0.f;
        for (int w = 0; w < 16; w++) t += sh[w];
        g_csq[j] = t;
    }
}

// ---------------- logits + argmax (validated) ----------------
__global__ void logits_kernel(const float* __restrict__ Psi,
                              float* __restrict__ out_logits) {
    __shared__ float sp[4][DP];
    __shared__ float srawsq[4];
    __shared__ float spsq[4];
    __shared__ float bv[128];
    __shared__ int   bidx[128];

    int tid  = threadIdx.x;
    int w    = tid >> 5;
    int lane = tid & 31;
    int row0 = blockIdx.x * 4;

    const float* src = Psi + (size_t)(row0 + w) * DP;
    float ss = 0.f;
    for (int k = lane; k < DP; k += 32) {
        float v = src[k];
        sp[w][k] = v;
        ss += v * v;
    }
    ss = warpSum(ss);
    if (lane == 0) srawsq[w] = ss;
    __syncthreads();
    {
        float tot = srawsq[w];
        float scl = 1.f / fmaxf(sqrtf(tot), 1e-12f);
        for (int k = lane; k < DP; k += 32) sp[w][k] *= scl;
        if (lane == 0) { spsq[w] = tot * scl * scl; g_Pinv[row0 + w] = scl; }
    }
    __syncthreads();

    float acc0 = 0.f, acc1 = 0.f, acc2 = 0.f, acc3 = 0.f;
    for (int k = 0; k < DP; k++) {
        float c = g_Ct[k * NCLS + tid];
        acc0 = fmaf(sp[0][k], c, acc0);
        acc1 = fmaf(sp[1][k], c, acc1);
        acc2 = fmaf(sp[2][k], c, acc2);
        acc3 = fmaf(sp[3][k], c, acc3);
    }
    float accs[4] = {acc0, acc1, acc2, acc3};
    float cs = g_csq[tid];

    for (int r = 0; r < 4; r++) {
        float logit = -(spsq[r] + cs - 2.f * accs[r]);
        out_logits[(size_t)(row0 + r) * NCLS + tid] = logit;
        bv[tid] = logit;
        bidx[tid] = tid;
        __syncthreads();
        for (int off = 64; off > 0; off >>= 1) {
            if (tid < off) {
                float ov = bv[tid + off];
                int   oi = bidx[tid + off];
                if (ov > bv[tid] || (ov == bv[tid] && oi < bidx[tid])) {
                    bv[tid] = ov; bidx[tid] = oi;
                }
            }
            __syncthreads();
        }
        if (tid == 0) g_assign[row0 + r] = bidx[0];
        __syncthreads();
    }
}

// ---------------- cluster update (validated) ----------------
__global__ void clusterA_kernel(const float* __restrict__ Psi) {
    int z = blockIdx.x;
    int j = blockIdx.y;
    int tid = threadIdx.x;
    __shared__ int   sa[512];
    __shared__ float spv[512];
    sa[tid]  = g_assign[z * 512 + tid];
    spv[tid] = g_Pinv[z * 512 + tid];
    __syncthreads();
    float acc = 0.f;
    int cnt = 0;
    for (int u = 0; u < 512; u++) {
        if (sa[u] == j) { acc += Psi[(size_t)(z * 512 + u) * DP + tid] * spv[u]; cnt++; }
    }
    g_cpart[z][j][tid] = acc;
    if (tid == 0) g_ccnt[z][j] = cnt;
}

__global__ void clusterB_kernel(const float* __restrict__ centers,
                                float* __restrict__ out_centers) {
    int j = blockIdx.x;
    int tid = threadIdx.x;
    float acc = 0.f;
    int cnt = 0;
    for (int z = 0; z < 16; z++) { acc += g_cpart[z][j][tid]; cnt += g_ccnt[z][j]; }
    float denom = fmaxf((float)cnt, 1.f);
    out_centers[j * DP + tid] = centers[j * DP + tid] * 0.9f + (acc / denom) * 0.1f;
}

// ---------------- computeD: fp16 streamed, 128x128 tiles ----------------
#define FST2 (128 * 20)
#define DCH  (DM / 32)
__global__ void __launch_bounds__(256) computeD_f16(void) {
    extern __shared__ uint32_t dynD[];
    __shared__ float srow[128][2];
    __shared__ float scol[4][128];
    __shared__ __half sT[128][136];

    uint32_t smb = smem_u32(dynD);
    int tid = threadIdx.x, wid = tid >> 5, lane = tid & 31;
    int g = lane >> 2, t = lane & 3;
    int wm = wid & 3, wn = wid >> 2;    // 4 m-warps (m32) x 2 n-warps (n64)

    int bt = blockIdx.x;
    int bi = (int)floorf((sqrtf(8.f * (float)bt + 1.f) - 1.f) * 0.5f);
    while ((bi + 1) * (bi + 2) / 2 <= bt) bi++;
    while (bi * (bi + 1) / 2 > bt) bi--;
    int bj = bt - bi * (bi + 1) / 2;
    int i0 = bi * 128, j0 = bj * 128;

    const uint32_t* Fi = g_F16 + (size_t)i0 * (DM / 2);
    const uint32_t* Fj = g_F16 + (size_t)j0 * (DM / 2);

    float sc[2][8][4];
#pragma unroll
    for (int f = 0; f < 2; f++)
#pragma unroll
        for (int n8 = 0; n8 < 8; n8++)
#pragma unroll
            for (int q = 0; q < 4; q++) sc[f][n8][q] = 0.f;

    int r = tid >> 1, q = (tid & 1) * 8;
    auto issueD = [&](int c) {
        int st = c & 3;
        CPA16(smb + (st * 2 * FST2 + r * 20 + q) * 4,
              Fi + (size_t)r * (DM / 2) + c * 16 + q);
        CPA16(smb + (st * 2 * FST2 + r * 20 + q + 4) * 4,
              Fi + (size_t)r * (DM / 2) + c * 16 + q + 4);
        CPA16(smb + (st * 2 * FST2 + FST2 + r * 20 + q) * 4,
              Fj + (size_t)r * (DM / 2) + c * 16 + q);
        CPA16(smb + (st * 2 * FST2 + FST2 + r * 20 + q + 4) * 4,
              Fj + (size_t)r * (DM / 2) + c * 16 + q + 4);
        CPA_COMMIT();
    };

    issueD(0); issueD(1); issueD(2);

    for (int c = 0; c < DCH; c++) {
        if (c + 3 < DCH) issueD(c + 3);
        if (c + 3 < DCH)      CPA_WAIT(3);
        else if (c + 2 < DCH) CPA_WAIT(2);
        else if (c + 1 < DCH) CPA_WAIT(1);
        else                  CPA_WAIT(0);
        __syncthreads();

        const uint32_t* pFi = dynD + (c & 3) * 2 * FST2;
        const uint32_t* pFj = pFi + FST2;
#pragma unroll
        for (int kk = 0; kk < 2; kk++) {
            uint32_t af[2][4];
#pragma unroll
            for (int f = 0; f < 2; f++) {
                int mb = wm * 32 + f * 16;
                af[f][0] = pFi[(mb + g) * 20 + kk * 8 + t];
                af[f][1] = pFi[(mb + g + 8) * 20 + kk * 8 + t];
                af[f][2] = pFi[(mb + g) * 20 + kk * 8 + t + 4];
                af[f][3] = pFi[(mb + g + 8) * 20 + kk * 8 + t + 4];
            }
#pragma unroll
            for (int n8 = 0; n8 < 8; n8++) {
                uint32_t b0 = pFj[(wn * 64 + n8 * 8 + g) * 20 + kk * 8 + t];
                uint32_t b1 = pFj[(wn * 64 + n8 * 8 + g) * 20 + kk * 8 + t + 4];
                mma16h(sc[0][n8], af[0][0], af[0][1], af[0][2], af[0][3], b0, b1);
                mma16h(sc[1][n8], af[1][0], af[1][1], af[1][2], af[1][3], b0, b1);
            }
        }
        __syncthreads();
    }

    // epilogue: clamp + diag; D partials; A stores
    uint32_t* Ai = g_A16[i0 >> 10];
    float ca[2][8][2];
#pragma unroll
    for (int f = 0; f < 2; f++) {
        int gi = i0 + wm * 32 + f * 16 + g;
        int row_l = wm * 32 + f * 16 + g;
        float rr0 = 0.f, rr1 = 0.f;
#pragma unroll
        for (int n8 = 0; n8 < 8; n8++) {
            int col_l = wn * 64 + n8 * 8 + 2 * t;
            int gj = j0 + col_l;
            float v0 = fmaxf(sc[f][n8][0], 0.f); if (gi == gj)         v0 = 0.f;
            float v1 = fmaxf(sc[f][n8][1], 0.f); if (gi == gj + 1)     v1 = 0.f;
            float v2 = fmaxf(sc[f][n8][2], 0.f); if (gi + 8 == gj)     v2 = 0.f;
            float v3 = fmaxf(sc[f][n8][3], 0.f); if (gi + 8 == gj + 1) v3 = 0.f;
            rr0 += v0 + v1;
            rr1 += v2 + v3;
            ca[f][n8][0] = v0 + v2;
            ca[f][n8][1] = v1 + v3;
            Ai[(size_t)(gi & 1023) * (NR / 2) + (gj >> 1)]       = ph2(v0, v1);
            Ai[(size_t)((gi + 8) & 1023) * (NR / 2) + (gj >> 1)] = ph2(v2, v3);
            sT[col_l][row_l]         = __float2half(v0);
            sT[col_l + 1][row_l]     = __float2half(v1);
            sT[col_l][row_l + 8]     = __float2half(v2);
            sT[col_l + 1][row_l + 8] = __float2half(v3);
        }
        rr0 += __shfl_xor_sync(0xffffffffu, rr0, 1);
        rr0 += __shfl_xor_sync(0xffffffffu, rr0, 2);
        rr1 += __shfl_xor_sync(0xffffffffu, rr1, 1);
        rr1 += __shfl_xor_sync(0xffffffffu, rr1, 2);
        if (t == 0) {
            srow[row_l][wn]     = rr0;
            srow[row_l + 8][wn] = rr1;
        }
    }
#pragma unroll
    for (int n8 = 0; n8 < 8; n8++) {
#pragma unroll
        for (int h = 0; h < 2; h++) {
            float c2 = ca[0][n8][h] + ca[1][n8][h];
            c2 += __shfl_xor_sync(0xffffffffu, c2, 4);
            c2 += __shfl_xor_sync(0xffffffffu, c2, 8);
            c2 += __shfl_xor_sync(0xffffffffu, c2, 16);
            if (g == 0) scol[wm][wn * 64 + n8 * 8 + 2 * t + h] = c2;
        }
    }
    __syncthreads();
    if (tid < 128) {
        g_pD[bj][i0 + tid] = srow[tid][0] + srow[tid][1];
    } else if (bi != bj) {
        int c2 = tid - 128;
        g_pD[bi][j0 + c2] = scol[0][c2] + scol[1][c2] + scol[2][c2] + scol[3][c2];
    }
    if (bi != bj) {
        uint32_t* Aj = g_A16[j0 >> 10];
        int row = tid >> 1, seg = tid & 1;
        const uint4* srcp = (const uint4*)&sT[row][seg * 64];
        size_t wbase = (size_t)((j0 + row) & 1023) * (NR / 2) + (i0 >> 1) + seg * 32;
#pragma unroll
        for (int u = 0; u < 8; u++)
            *(uint4*)&Aj[wbase + u * 4] = srcp[u];
    }
}

// ---------------- reduce partials -> Drs ----------------
__global__ void reduceD_kernel() {
    int i = blockIdx.x * 256 + threadIdx.x;
    float s = 0.f;
#pragma unroll 4
    for (int c = 0; c < 64; c++) s += g_pD[c][i];
    g_Drs[i] = rsqrtf(fmaxf(s / (float)(NR - 1), 1e-30f));
}

// ---------------- W16 prep ----------------
__global__ void w16prep_kernel(const float* __restrict__ Psi) {
    int idx = blockIdx.x * 512 + threadIdx.x;
    int p = idx >> 5, seg = idx & 31;
    float w0 = g_Drs[2 * p] * SCALE;
    float w1 = g_Drs[2 * p + 1] * SCALE;
    const float* r0p = Psi + (size_t)(2 * p) * DP + seg * 16;
    const float* r1p = Psi + (size_t)(2 * p + 1) * DP + seg * 16;
    uint32_t* dst = g_W16 + (size_t)p * DP + seg * 16;
#pragma unroll
    for (int q = 0; q < 4; q++) {
        float4 x = *(const float4*)(r0p + q * 4);
        float4 y = *(const float4*)(r1p + q * 4);
        uint4 o;
        o.x = ph2(x.x * w0, y.x * w1);
        o.y = ph2(x.y * w0, y.y * w1);
        o.z = ph2(x.z * w0, y.z * w1);
        o.w = ph2(x.w * w0, y.w * w1);
        *(uint4*)(dst + q * 4) = o;
    }
}

// ---------------- gpsi: fp16 mma, A streamed via cp.async (validated) ---------
#define WST   (16 * 520)
#define AST   (64 * 20)
#define NCH   (NR / 32)
__global__ void __launch_bounds__(512, 1) gpsi_f16(void) {
    extern __shared__ uint32_t dyn[];
    uint32_t smb = smem_u32(dyn);
    int tid = threadIdx.x, wid = tid >> 5, lane = tid & 31;
    int g = lane >> 2, t = lane & 3;
    int wm = wid & 3, wn = wid >> 2;
    int i0 = blockIdx.x * 64;
    const uint32_t* Abase = g_A16[i0 >> 10] + (size_t)(i0 & 1023) * (NR / 2);

    float gacc[16][4];
#pragma unroll
    for (int f = 0; f < 16; f++)
#pragma unroll
        for (int q = 0; q < 4; q++) gacc[f][q] = 0.f;

    auto issue = [&](int c) {
        int st = c & 3;
        int kt = c * 32;
        {
            int p = tid >> 5, seg = tid & 31;
            uint32_t dst = smb + (st * WST + p * 520 + seg * 16) * 4;
            const uint32_t* src = g_W16 + (size_t)((kt >> 1) + p) * DP + seg * 16;
#pragma unroll
            for (int q = 0; q < 4; q++) CPA16(dst + q * 16, src + q * 4);
        }
        if (tid < 256) {
            int r = tid >> 2, q = tid & 3;
            uint32_t dst = smb + (4 * WST + st * AST + r * 20 + q * 4) * 4;
            const uint32_t* src = Abase + (size_t)r * (NR / 2) + (kt >> 1) + q * 4;
            CPA16(dst, src);
        }
        CPA_COMMIT();
    };

    issue(0); issue(1); issue(2);

    for (int c = 0; c < NCH; c++) {
        if (c + 3 < NCH) issue(c + 3);
        if (c + 3 < NCH)      CPA_WAIT(3);
        else if (c + 2 < NCH) CPA_WAIT(2);
        else if (c + 1 < NCH) CPA_WAIT(1);
        else                  CPA_WAIT(0);
        __syncthreads();

        int st = c & 3;
        const uint32_t* pW = dyn + st * WST;
        const uint32_t* pA = dyn + 4 * WST + st * AST;
#pragma unroll
        for (int s = 0; s < 2; s++) {
            uint32_t a0 = pA[(wm * 16 + g) * 20 + 8 * s + t];
            uint32_t a1 = pA[(wm * 16 + g + 8) * 20 + 8 * s + t];
            uint32_t a2 = pA[(wm * 16 + g) * 20 + 8 * s + t + 4];
            uint32_t a3 = pA[(wm * 16 + g + 8) * 20 + 8 * s + t + 4];
            const uint32_t* rb0 = pW + (8 * s + t) * 520;
            const uint32_t* rb1 = pW + (8 * s + 4 + t) * 520;
#pragma unroll
            for (int n8 = 0; n8 < 16; n8++) {
                int n = wn * 128 + n8 * 8 + g;
                mma16h(gacc[n8], a0, a1, a2, a3, rb0[n], rb1[n]);
            }
        }
        __syncthreads();
    }

    int row = i0 + wm * 16 + g;
    float d0 = g_Drs[row], d1 = g_Drs[row + 8];
#pragma unroll
    for (int n8 = 0; n8 < 16; n8++) {
        int col = wn * 128 + n8 * 8 + 2 * t;
        *(float2*)(g_gPsi + (size_t)row * DP + col) =
            make_float2(d0 * gacc[n8][0], d0 * gacc[n8][1]);
        *(float2*)(g_gPsi + (size_t)(row + 8) * DP + col) =
            make_float2(d1 * gacc[n8][2], d1 * gacc[n8][3]);
    }
}

// ---------------- gemm3: R partials, tf32 (validated) ----------------
__global__ void __launch_bounds__(256) gemm3_tc(const float* __restrict__ Psi) {
    __shared__ uint32_t Xs[64][33];
    __shared__ uint32_t Ys[32][68];

    int tid = threadIdx.x, wid = tid >> 5, lane = tid & 31;
    int g = lane >> 2, t = lane & 3;
    int wm = wid & 3, wn = wid >> 2;
    int b0 = blockIdx.x * 64, a0 = blockIdx.y * 64, z = blockIdx.z;

    int lk = tid >> 3, la8 = (tid & 7) * 8;

    float sc[4][4];
#pragma unroll
    for (int n8 = 0; n8 < 4; n8++)
#pragma unroll
        for (int q = 0; q < 4; q++) sc[n8][q] = 0.f;

    int kbeg = z * (NR / 4);
    const float* px = Psi + (size_t)(kbeg + lk) * DP + a0 + la8;
    const float* py = g_gPsi + (size_t)(kbeg + lk) * DP + b0 + la8;

    float4 X0 = *(const float4*)(px);
    float4 X1 = *(const float4*)(px + 4);
    float4 Y0 = *(const float4*)(py);
    float4 Y1 = *(const float4*)(py + 4);

    for (int k0 = 0; k0 < NR / 4; k0 += 32) {
        __syncthreads();
        Xs[la8 + 0][lk] = f2tf32(X0.x * SCALE); Xs[la8 + 1][lk] = f2tf32(X0.y * SCALE);
        Xs[la8 + 2][lk] = f2tf32(X0.z * SCALE); Xs[la8 + 3][lk] = f2tf32(X0.w * SCALE);
        Xs[la8 + 4][lk] = f2tf32(X1.x * SCALE); Xs[la8 + 5][lk] = f2tf32(X1.y * SCALE);
        Xs[la8 + 6][lk] = f2tf32(X1.z * SCALE); Xs[la8 + 7][lk] = f2tf32(X1.w * SCALE);
        *(uint4*)&Ys[lk][la8]     = cvt4(Y0, 1.f);
        *(uint4*)&Ys[lk][la8 + 4] = cvt4(Y1, 1.f);
        if (k0 + 32 < NR / 4) {
            const float* nx = px + (size_t)(k0 + 32) * DP;
            const float* ny = py + (size_t)(k0 + 32) * DP;
            X0 = *(const float4*)(nx);
            X1 = *(const float4*)(nx + 4);
            Y0 = *(const float4*)(ny);
            Y1 = *(const float4*)(ny + 4);
        }
        __syncthreads();
#pragma unroll
        for (int kk = 0; kk < 4; kk++) {
            uint32_t fa0 = Xs[wm * 16 + g][kk * 8 + t];
            uint32_t fa1 = Xs[wm * 16 + g + 8][kk * 8 + t];
            uint32_t fa2 = Xs[wm * 16 + g][kk * 8 + t + 4];
            uint32_t fa3 = Xs[wm * 16 + g + 8][kk * 8 + t + 4];
#pragma unroll
            for (int n8 = 0; n8 < 4; n8++) {
                uint32_t fb0 = Ys[kk * 8 + t][wn * 32 + n8 * 8 + g];
                uint32_t fb1 = Ys[kk * 8 + t + 4][wn * 32 + n8 * 8 + g];
                mma8(sc[n8], fa0, fa1, fa2, fa3, fb0, fb1);
            }
        }
    }
    int a = a0 + wm * 16 + g;
#pragma unroll
    for (int n8 = 0; n8 < 4; n8++) {
        int b = b0 + wn * 32 + n8 * 8 + 2 * t;
        g_R4[z][a * DP + b]           = sc[n8][0];
        g_R4[z][a * DP + b + 1]       = sc[n8][1];
        g_R4[z][(a + 8) * DP + b]     = sc[n8][2];
        g_R4[z][(a + 8) * DP + b + 1] = sc[n8][3];
    }
}

// ---------------- final: parallel trace + triu reg ----------------
__global__ void final1_kernel() {
    int b = threadIdx.x;
    int z = blockIdx.x;
    float tr = 0.f, rg = 0.f;
    for (int a = z * 32; a < z * 32 + 32; a++) {
        float s = g_R4[0][a * DP + b] + g_R4[1][a * DP + b]
                + g_R4[2][a * DP + b] + g_R4[3][a * DP + b];
        if (b == a) tr += s;
        else if (b > a) rg += s * s;
    }
    g_fin[z][b][0] = tr;
    g_fin[z][b][1] = rg;
}

__global__ void final2_kernel(float* __restrict__ out2) {
    int b = threadIdx.x;
    float tr = 0.f, rg = 0.f;
#pragma unroll
    for (int z = 0; z < 16; z++) { tr += g_fin[z][b][0]; rg += g_fin[z][b][1]; }
    __shared__ float st[DP], sr[DP];
    st[b] = tr; sr[b] = rg;
    __syncthreads();
    if (b == 0) {
        double T = 0.0, R = 0.0;
        for (int i = 0; i < DP; i++) { T += (double)st[i]; R += (double)sr[i]; }
        out2[0] = (float)(-T);
        out2[1] = (float)(R * 0.02);
    }
}

// ---------------- launcher ----------------
extern "C" void kernel_launch(void* const* d_in, const int* in_sizes, int n_in,
                              void* d_out, int out_size) {
    const float* FF  = (const float*)d_in[0];
    const float* Psi = (const float*)d_in[1];
    const float* C   = (const float*)d_in[2];
    float* out = (float*)d_out;

    float* out_logits  = out;
    float* out_centers = out + (size_t)NR * NCLS;
    float* out_scal    = out + (size_t)NR * NCLS + NCLS * DP;

    static cudaStream_t s2 = nullptr;
    static cudaEvent_t evFork = nullptr, evJoin = nullptr;
    if (!s2) {
        cudaStreamCreateWithFlags(&s2, cudaStreamNonBlocking);
        cudaEventCreateWithFlags(&evFork, cudaEventDisableTiming);
        cudaEventCreateWithFlags(&evJoin, cudaEventDisableTiming);
        cudaFuncSetAttribute(gpsi_f16, cudaFuncAttributeMaxDynamicSharedMemorySize,
                             (4 * WST + 4 * AST) * 4);
        cudaFuncSetAttribute(computeD_f16, cudaFuncAttributeMaxDynamicSharedMemorySize,
                             4 * 2 * FST2 * 4);
    }

    cudaEventRecord(evFork, 0);
    cudaStreamWaitEvent(s2, evFork, 0);

    prep_centers_kernel<<<NCLS, DP, 0, s2>>>(C);
    logits_kernel<<<NR / 4, 128, 0, s2>>>(Psi, out_logits);
    clusterA_kernel<<<dim3(16, NCLS), 512, 0, s2>>>(Psi);
    clusterB_kernel<<<NCLS, DP, 0, s2>>>(C, out_centers);
    cudaEventRecord(evJoin, s2);

    finv_kernel<<<NR / 8, 256>>>(FF);
    f16prep_kernel<<<NR * (DM / 2) / 4 / 256, 256>>>(FF);
    computeD_f16<<<(NR / 128) * (NR / 128 + 1) / 2, 256, 4 * 2 * FST2 * 4>>>();
    reduceD_kernel<<<NR / 256, 256>>>();
    w16prep_kernel<<<(NR / 2) * (DP / 16) / 512, 512>>>(Psi);
    gpsi_f16<<<NR / 64, 512, (4 * WST + 4 * AST) * 4>>>();
    gemm3_tc<<<dim3(DP / 64, DP / 64, 4), 256>>>(Psi);
    final1_kernel<<<16, DP>>>();
    final2_kernel<<<1, DP>>>(out_scal);

    cudaStreamWaitEvent(0, evJoin, 0);
}